// round 9
// baseline (speedup 1.0000x reference)
#include <cuda_runtime.h>
#include <math.h>
#include <stdint.h>

#define SEQ    4096
#define DIM    1024
#define NH     16
#define HD     64
#define HIDDEN 4096

// ---------------- scratch -----------------------------------------------------------
__device__ float g_xn[SEQ * DIM];
__device__ float g_q [SEQ * DIM];
__device__ float g_k [SEQ * DIM];
__device__ float g_v [SEQ * DIM];
__device__ float g_at[SEQ * DIM];
__device__ float g_hn[SEQ * DIM];
__device__ float g_t1[SEQ * HIDDEN];
__device__ float g_t3[SEQ * HIDDEN];
__device__ float g_cos[SEQ * (HD / 2)];
__device__ float g_sin[SEQ * (HD / 2)];
__device__ float g_wt[16777216];          // tf32-rounded weights (64MB)

#define WQO 0
#define WKO 1048576
#define WVO 2097152
#define WOO 3145728
#define W1O 4194304
#define W3O 8388608
#define W2O 12582912

__device__ __forceinline__ uint32_t f2tf32(float f) {
    uint32_t u;
    asm("cvt.rna.tf32.f32 %0, %1;" : "=r"(u) : "f"(f));
    return u;
}
__device__ __forceinline__ float rtf32(float f) { return __uint_as_float(f2tf32(f)); }

__device__ __forceinline__ void mma_tf32(float* c, const uint32_t* a, uint32_t b0, uint32_t b1) {
    asm volatile(
        "mma.sync.aligned.m16n8k8.row.col.f32.tf32.tf32.f32 "
        "{%0,%1,%2,%3}, {%4,%5,%6,%7}, {%8,%9}, {%0,%1,%2,%3};\n"
        : "+f"(c[0]), "+f"(c[1]), "+f"(c[2]), "+f"(c[3])
        : "r"(a[0]), "r"(a[1]), "r"(a[2]), "r"(a[3]), "r"(b0), "r"(b1));
}

__device__ __forceinline__ void ldsm4(uint32_t* r, uint32_t saddr) {
    asm volatile("ldmatrix.sync.aligned.m8n8.x4.shared.b16 {%0,%1,%2,%3}, [%4];"
        : "=r"(r[0]), "=r"(r[1]), "=r"(r[2]), "=r"(r[3]) : "r"(saddr));
}

__device__ __forceinline__ void cp16(uint32_t saddr, const void* gptr) {
    asm volatile("cp.async.cg.shared.global [%0], [%1], 16;" :: "r"(saddr), "l"(gptr));
}

__device__ __forceinline__ uint32_t smem_u32(const void* p) {
    uint32_t a;
    asm("{ .reg .u64 t; cvta.to.shared.u64 t, %1; cvt.u32.u64 %0, t; }" : "=r"(a) : "l"(p));
    return a;
}

// ---------------- weight tf32 pre-round ----------------------------------------------
__global__ void cvt_w_k(const float* __restrict__ src, float* __restrict__ dst, int n4) {
    int stride = gridDim.x * blockDim.x;
    for (int i = blockIdx.x * blockDim.x + threadIdx.x; i < n4; i += stride) {
        float4 v = ((const float4*)src)[i];
        v.x = rtf32(v.x); v.y = rtf32(v.y); v.z = rtf32(v.z); v.w = rtf32(v.w);
        ((float4*)dst)[i] = v;
    }
}

// ---------------- RoPE tables in double precision ------------------------------------
__global__ void rope_tables_k(float* __restrict__ c, float* __restrict__ s) {
    int idx = blockIdx.x * blockDim.x + threadIdx.x;
    int pos = idx >> 5;
    int i   = idx & 31;
    double inv = exp(-((double)(2 * i) / (double)HD) * log(10000.0));
    double ang = (double)pos * inv;
    double cs, sn;
    sincos(ang, &sn, &cs);
    c[idx] = (float)cs;
    s[idx] = (float)sn;
}

// ---------------- RMSNorm (tf32-rounded output) ---------------------------------------
__global__ void rmsnorm_k(const float* __restrict__ x, const float* __restrict__ g,
                          float* __restrict__ o) {
    int row = blockIdx.x;
    const float4* xr = (const float4*)(x + (size_t)row * DIM);
    float4*       orow = (float4*)(o + (size_t)row * DIM);
    int t = threadIdx.x;
    float4 v = xr[t];
    float ss = v.x * v.x + v.y * v.y + v.z * v.z + v.w * v.w;
    #pragma unroll
    for (int off = 16; off; off >>= 1) ss += __shfl_xor_sync(0xffffffffu, ss, off);
    __shared__ float sp[8];
    if ((t & 31) == 0) sp[t >> 5] = ss;
    __syncthreads();
    if (t < 8) {
        float s2 = sp[t];
        #pragma unroll
        for (int off = 4; off; off >>= 1) s2 += __shfl_xor_sync(0xffu, s2, off);
        if (t == 0) sp[0] = s2;
    }
    __syncthreads();
    float rs = rsqrtf(sp[0] * (1.0f / DIM) + 1e-6f);
    float4 gg = ((const float4*)g)[t];
    float4 out;
    out.x = rtf32(v.x * rs * gg.x);
    out.y = rtf32(v.y * rs * gg.y);
    out.z = rtf32(v.z * rs * gg.z);
    out.w = rtf32(v.w * rs * gg.w);
    orow[t] = out;
}

// ---------------- tf32 GEMM: CTA 128x128, warp 64x32, BK=32, ldmatrix ----------------
#define BM 128
#define BN 128
#define BK 32
#define SST 36                      // 32 + 4 pad; row phase = 144 mod 128 = 16B: ldsm-clean
#define STAGES 3
#define AWRD (BM * SST)             // words per A stage
#define STGW (2 * AWRD)             // words per stage (A+B)
#define GSMEM (STAGES * STGW * 4)   // bytes = 110592

struct Batch3 {
    const float* B[3];
    float*       C[3];
    const float* R[3];
};

template <bool RESID>
__global__ __launch_bounds__(256, 2)
void gemm_tc(const float* __restrict__ A, Batch3 bt, int M, int N, int K) {
    extern __shared__ uint32_t sm[];
    const float* __restrict__ Bp = bt.B[blockIdx.z];
    float*       __restrict__ Cp = bt.C[blockIdx.z];
    const float* __restrict__ Rp = bt.R[blockIdx.z];

    const int bm = blockIdx.y * BM;
    const int bn = blockIdx.x * BN;
    const int tid  = threadIdx.x;
    const int warp = tid >> 5;
    const int lane = tid & 31;
    const int grp  = lane >> 2;
    const int tig  = lane & 3;
    const int wm = (warp >> 2) * 64;
    const int wn = (warp & 3) * 32;

    const int arow = lane & 15;
    const int acol = (lane >> 4) * 4;
    const int brow = ((lane >> 4) << 3) + (lane & 7);
    const int bcol = ((lane >> 3) & 1) * 4;

    const int lr = tid >> 3;            // 0..31
    const int c4 = (tid & 7) * 4;       // 0..28

    float acc[4][4][4];
    #pragma unroll
    for (int i = 0; i < 4; i++)
        #pragma unroll
        for (int j = 0; j < 4; j++)
            #pragma unroll
            for (int r = 0; r < 4; r++) acc[i][j][r] = 0.0f;

    const int NT = K / BK;
    const uint32_t smb = smem_u32(sm);

    auto issue = [&](int kt) {
        const int st = kt % STAGES;
        const uint32_t ab = smb + st * STGW * 4;
        const uint32_t bb = ab + AWRD * 4;
        const float* Ag = A  + (size_t)bm * K + kt * BK;
        const float* Bg = Bp + (size_t)bn * K + kt * BK;
        #pragma unroll
        for (int i = 0; i < 4; i++) {
            int row = lr + i * 32;
            cp16(ab + (row * SST + c4) * 4, Ag + (size_t)row * K + c4);
            cp16(bb + (row * SST + c4) * 4, Bg + (size_t)row * K + c4);
        }
        asm volatile("cp.async.commit_group;");
    };

    issue(0);
    issue(1);

    for (int kt = 0; kt < NT; kt++) {
        if (kt + 1 < NT) {
            asm volatile("cp.async.wait_group 1;");
        } else {
            asm volatile("cp.async.wait_group 0;");
        }
        __syncthreads();
        if (kt + 2 < NT) issue(kt + 2);

        const int st = kt % STAGES;
        const uint32_t ab = smb + st * STGW * 4;
        const uint32_t bb = ab + AWRD * 4;

        #pragma unroll
        for (int ks = 0; ks < 4; ks++) {
            const int kb = ks * 8;
            uint32_t af[4][4], b2[2][4];
            #pragma unroll
            for (int mt = 0; mt < 4; mt++)
                ldsm4(af[mt], ab + (((wm + mt * 16 + arow) * SST) + kb + acol) * 4);
            ldsm4(b2[0], bb + (((wn +  0 + brow) * SST) + kb + bcol) * 4);
            ldsm4(b2[1], bb + (((wn + 16 + brow) * SST) + kb + bcol) * 4);
            #pragma unroll
            for (int mt = 0; mt < 4; mt++)
                #pragma unroll
                for (int nt = 0; nt < 4; nt++)
                    mma_tf32(acc[mt][nt],
                             af[mt],
                             b2[nt >> 1][(nt & 1) * 2],
                             b2[nt >> 1][(nt & 1) * 2 + 1]);
        }
    }

    #pragma unroll
    for (int mt = 0; mt < 4; mt++) {
        const int row = bm + wm + mt * 16 + grp;
        #pragma unroll
        for (int nt = 0; nt < 4; nt++) {
            const int col = bn + wn + nt * 8 + 2 * tig;
            size_t i0 = (size_t)row * N + col;
            size_t i1 = (size_t)(row + 8) * N + col;
            float2 v0 = make_float2(acc[mt][nt][0], acc[mt][nt][1]);
            float2 v1 = make_float2(acc[mt][nt][2], acc[mt][nt][3]);
            if (RESID) {
                float2 r0v = *(const float2*)&Rp[i0];
                float2 r1v = *(const float2*)&Rp[i1];
                v0.x += r0v.x; v0.y += r0v.y;
                v1.x += r1v.x; v1.y += r1v.y;
            }
            *(float2*)&Cp[i0] = v0;
            *(float2*)&Cp[i1] = v1;
        }
    }
}

// ---------------- RoPE ---------------------------------------------------------------
__global__ void rope_k(float* __restrict__ q, float* __restrict__ k,
                       const float* __restrict__ ct, const float* __restrict__ st) {
    int pos = blockIdx.x;
    int t = threadIdx.x;
    int h = t >> 5;
    int i = t & 31;
    float c = ct[pos * 32 + i];
    float s = st[pos * 32 + i];
    size_t base = (size_t)pos * DIM + h * HD + 2 * i;
    float2 qq = *(float2*)&q[base];
    float2 qo; qo.x = qq.x * c - qq.y * s; qo.y = qq.x * s + qq.y * c;
    *(float2*)&q[base] = qo;
    float2 kk = *(float2*)&k[base];
    float2 ko; ko.x = kk.x * c - kk.y * s; ko.y = kk.x * s + kk.y * c;
    *(float2*)&k[base] = ko;
}

// ---------------- Tensor-core flash attention (tf32, ldmatrix everywhere) ------------
// K tile [kv][d] stride 68; V tile TRANSPOSED [d][kv] stride 68 (conflict-free ldsm).
#define BQ   64
#define BKV  64
#define KP   68

__global__ __launch_bounds__(128, 3)
void flash_attn_tc(const float* __restrict__ Q, const float* __restrict__ K,
                   const float* __restrict__ V, float* __restrict__ O) {
    __shared__ uint32_t Ks[BKV][KP];
    __shared__ uint32_t Vt[HD][KP];     // transposed V
    __shared__ uint32_t Ps[BQ][KP];

    const int h  = blockIdx.y;
    const int q0 = blockIdx.x * BQ;
    const int tid  = threadIdx.x;
    const int warp = tid >> 5;
    const int lane = tid & 31;
    const int grp  = lane >> 2;
    const int tig  = lane & 3;
    const int wm   = warp * 16;

    const int arow = lane & 15;
    const int acol = (lane >> 4) * 4;
    const int brow = ((lane >> 4) << 3) + (lane & 7);
    const int bcol = ((lane >> 3) & 1) * 4;

    uint32_t qf[8][4];
    {
        const float* qb = Q + (size_t)(q0 + wm) * DIM + h * HD;
        #pragma unroll
        for (int ks = 0; ks < 8; ks++) {
            qf[ks][0] = f2tf32(0.125f * qb[(size_t)grp       * DIM + ks * 8 + tig]);
            qf[ks][1] = f2tf32(0.125f * qb[(size_t)(grp + 8) * DIM + ks * 8 + tig]);
            qf[ks][2] = f2tf32(0.125f * qb[(size_t)grp       * DIM + ks * 8 + tig + 4]);
            qf[ks][3] = f2tf32(0.125f * qb[(size_t)(grp + 8) * DIM + ks * 8 + tig + 4]);
        }
    }

    float o[8][4];
    #pragma unroll
    for (int dt = 0; dt < 8; dt++)
        #pragma unroll
        for (int r = 0; r < 4; r++) o[dt][r] = 0.0f;
    float m0 = -1e30f, m1 = -1e30f, l0 = 0.0f, l1 = 0.0f;

    const uint32_t ksb = smem_u32(&Ks[0][0]);
    const uint32_t vtb = smem_u32(&Vt[0][0]);
    const uint32_t psb = smem_u32(&Ps[0][0]);

    for (int k0 = 0; k0 < SEQ; k0 += BKV) {
        __syncthreads();
        #pragma unroll
        for (int i = 0; i < 8; i++) {
            int idx = tid + i * 128;
            int row = idx >> 4;          // kv row 0..63
            int c   = (idx & 15) * 4;    // d 0..60
            float4 k4 = *(const float4*)&K[(size_t)(k0 + row) * DIM + h * HD + c];
            Ks[row][c + 0] = f2tf32(k4.x); Ks[row][c + 1] = f2tf32(k4.y);
            Ks[row][c + 2] = f2tf32(k4.z); Ks[row][c + 3] = f2tf32(k4.w);
            float4 v4 = *(const float4*)&V[(size_t)(k0 + row) * DIM + h * HD + c];
            Vt[c + 0][row] = f2tf32(v4.x); Vt[c + 1][row] = f2tf32(v4.y);
            Vt[c + 2][row] = f2tf32(v4.z); Vt[c + 3][row] = f2tf32(v4.w);
        }
        __syncthreads();

        // S = Q K^T
        float sc[8][4];
        #pragma unroll
        for (int nt = 0; nt < 8; nt++)
            #pragma unroll
            for (int r = 0; r < 4; r++) sc[nt][r] = 0.0f;
        #pragma unroll
        for (int ks = 0; ks < 8; ks++) {
            const int kb = ks * 8;
            uint32_t kf[4][4];
            #pragma unroll
            for (int g = 0; g < 4; g++)
                ldsm4(kf[g], ksb + (((g * 16 + brow) * KP) + kb + bcol) * 4);
            #pragma unroll
            for (int nt = 0; nt < 8; nt++)
                mma_tf32(sc[nt], qf[ks],
                         kf[nt >> 1][(nt & 1) * 2],
                         kf[nt >> 1][(nt & 1) * 2 + 1]);
        }

        float mx0 = -1e30f, mx1 = -1e30f;
        #pragma unroll
        for (int nt = 0; nt < 8; nt++) {
            mx0 = fmaxf(mx0, fmaxf(sc[nt][0], sc[nt][1]));
            mx1 = fmaxf(mx1, fmaxf(sc[nt][2], sc[nt][3]));
        }
        mx0 = fmaxf(mx0, __shfl_xor_sync(0xffffffffu, mx0, 1));
        mx0 = fmaxf(mx0, __shfl_xor_sync(0xffffffffu, mx0, 2));
        mx1 = fmaxf(mx1, __shfl_xor_sync(0xffffffffu, mx1, 1));
        mx1 = fmaxf(mx1, __shfl_xor_sync(0xffffffffu, mx1, 2));

        float mn0 = fmaxf(m0, mx0);
        float mn1 = fmaxf(m1, mx1);
        float cr0 = __expf(m0 - mn0);
        float cr1 = __expf(m1 - mn1);
        m0 = mn0; m1 = mn1;

        float s0 = 0.0f, s1 = 0.0f;
        #pragma unroll
        for (int nt = 0; nt < 8; nt++) {
            sc[nt][0] = __expf(sc[nt][0] - mn0);
            sc[nt][1] = __expf(sc[nt][1] - mn0);
            sc[nt][2] = __expf(sc[nt][2] - mn1);
            sc[nt][3] = __expf(sc[nt][3] - mn1);
            s0 += sc[nt][0] + sc[nt][1];
            s1 += sc[nt][2] + sc[nt][3];
        }
        s0 += __shfl_xor_sync(0xffffffffu, s0, 1);
        s0 += __shfl_xor_sync(0xffffffffu, s0, 2);
        s1 += __shfl_xor_sync(0xffffffffu, s1, 1);
        s1 += __shfl_xor_sync(0xffffffffu, s1, 2);
        l0 = l0 * cr0 + s0;
        l1 = l1 * cr1 + s1;

        #pragma unroll
        for (int dt = 0; dt < 8; dt++) {
            o[dt][0] *= cr0; o[dt][1] *= cr0;
            o[dt][2] *= cr1; o[dt][3] *= cr1;
        }

        #pragma unroll
        for (int nt = 0; nt < 8; nt++) {
            uint2 u0 = make_uint2(f2tf32(sc[nt][0]), f2tf32(sc[nt][1]));
            uint2 u1 = make_uint2(f2tf32(sc[nt][2]), f2tf32(sc[nt][3]));
            *(uint2*)&Ps[wm + grp    ][nt * 8 + 2 * tig] = u0;
            *(uint2*)&Ps[wm + grp + 8][nt * 8 + 2 * tig] = u1;
        }
        __syncwarp();

        // O += P V  (B-fragments from transposed V via ldmatrix)
        #pragma unroll
        for (int ks = 0; ks < 8; ks++) {
            const int kb = ks * 8;
            uint32_t pa[4], vf[4][4];
            ldsm4(pa, psb + (((wm + arow) * KP) + kb + acol) * 4);
            #pragma unroll
            for (int g = 0; g < 4; g++)
                ldsm4(vf[g], vtb + (((g * 16 + brow) * KP) + kb + bcol) * 4);
            #pragma unroll
            for (int dt = 0; dt < 8; dt++)
                mma_tf32(o[dt], pa,
                         vf[dt >> 1][(dt & 1) * 2],
                         vf[dt >> 1][(dt & 1) * 2 + 1]);
        }
        __syncwarp();
    }

    float il0 = 1.0f / l0;
    float il1 = 1.0f / l1;
    #pragma unroll
    for (int dt = 0; dt < 8; dt++) {
        size_t i0 = (size_t)(q0 + wm + grp    ) * DIM + h * HD + dt * 8 + 2 * tig;
        size_t i1 = (size_t)(q0 + wm + grp + 8) * DIM + h * HD + dt * 8 + 2 * tig;
        *(float2*)&O[i0] = make_float2(rtf32(o[dt][0] * il0), rtf32(o[dt][1] * il0));
        *(float2*)&O[i1] = make_float2(rtf32(o[dt][2] * il1), rtf32(o[dt][3] * il1));
    }
}

// ---------------- SwiGLU elementwise (tf32-rounded output) ---------------------------
__global__ void silu_mul_k(float* __restrict__ a, const float* __restrict__ b, int n4) {
    int i = blockIdx.x * blockDim.x + threadIdx.x;
    if (i < n4) {
        float4 x = ((float4*)a)[i];
        float4 y = ((const float4*)b)[i];
        x.x = rtf32(x.x / (1.0f + __expf(-x.x)) * y.x);
        x.y = rtf32(x.y / (1.0f + __expf(-x.y)) * y.y);
        x.z = rtf32(x.z / (1.0f + __expf(-x.z)) * y.z);
        x.w = rtf32(x.w / (1.0f + __expf(-x.w)) * y.w);
        ((float4*)a)[i] = x;
    }
}

// ---------------- launch --------------------------------------------------------------
extern "C" void kernel_launch(void* const* d_in, const int* in_sizes, int n_in,
                              void* d_out, int out_size) {
    const float* x  = (const float*)d_in[0];
    const float* wq = (const float*)d_in[1];
    const float* wk = (const float*)d_in[2];
    const float* wv = (const float*)d_in[3];
    const float* wo = (const float*)d_in[4];
    const float* w1 = (const float*)d_in[5];
    const float* w2 = (const float*)d_in[6];
    const float* w3 = (const float*)d_in[7];
    const float* ga = (const float*)d_in[8];
    const float* gf = (const float*)d_in[9];
    float* out = (float*)d_out;

    float *xn, *q, *k, *v, *at, *hn, *t1, *t3, *ct, *st, *wt;
    cudaGetSymbolAddress((void**)&xn, g_xn);
    cudaGetSymbolAddress((void**)&q,  g_q);
    cudaGetSymbolAddress((void**)&k,  g_k);
    cudaGetSymbolAddress((void**)&v,  g_v);
    cudaGetSymbolAddress((void**)&at, g_at);
    cudaGetSymbolAddress((void**)&hn, g_hn);
    cudaGetSymbolAddress((void**)&t1, g_t1);
    cudaGetSymbolAddress((void**)&t3, g_t3);
    cudaGetSymbolAddress((void**)&ct, g_cos);
    cudaGetSymbolAddress((void**)&st, g_sin);
    cudaGetSymbolAddress((void**)&wt, g_wt);

    cudaFuncSetAttribute(gemm_tc<false>, cudaFuncAttributeMaxDynamicSharedMemorySize, GSMEM);
    cudaFuncSetAttribute(gemm_tc<true>,  cudaFuncAttributeMaxDynamicSharedMemorySize, GSMEM);

    cvt_w_k<<<256, 256>>>(wq, wt + WQO, DIM * DIM / 4);
    cvt_w_k<<<256, 256>>>(wk, wt + WKO, DIM * DIM / 4);
    cvt_w_k<<<256, 256>>>(wv, wt + WVO, DIM * DIM / 4);
    cvt_w_k<<<256, 256>>>(wo, wt + WOO, DIM * DIM / 4);
    cvt_w_k<<<512, 256>>>(w1, wt + W1O, HIDDEN * DIM / 4);
    cvt_w_k<<<512, 256>>>(w3, wt + W3O, HIDDEN * DIM / 4);
    cvt_w_k<<<512, 256>>>(w2, wt + W2O, DIM * HIDDEN / 4);

    rope_tables_k<<<(SEQ * 32) / 256, 256>>>(ct, st);
    rmsnorm_k<<<SEQ, 256>>>(x, ga, xn);

    // QKV batched (z = 3)
    {
        Batch3 bt;
        bt.B[0] = wt + WQO; bt.B[1] = wt + WKO; bt.B[2] = wt + WVO;
        bt.C[0] = q; bt.C[1] = k; bt.C[2] = v;
        bt.R[0] = bt.R[1] = bt.R[2] = nullptr;
        gemm_tc<false><<<dim3(DIM / BN, SEQ / BM, 3), 256, GSMEM>>>(xn, bt, SEQ, DIM, DIM);
    }

    rope_k<<<SEQ, 512>>>(q, k, ct, st);
    flash_attn_tc<<<dim3(SEQ / BQ, NH), 128>>>(q, k, v, at);

    // Wo + residual -> out
    {
        Batch3 bt;
        bt.B[0] = wt + WOO; bt.C[0] = out; bt.R[0] = x;
        bt.B[1] = bt.B[2] = nullptr; bt.C[1] = bt.C[2] = nullptr; bt.R[1] = bt.R[2] = nullptr;
        gemm_tc<true><<<dim3(DIM / BN, SEQ / BM, 1), 256, GSMEM>>>(at, bt, SEQ, DIM, DIM);
    }

    rmsnorm_k<<<SEQ, 256>>>(out, gf, hn);

    // w1 / w3 batched (z = 2)
    {
        Batch3 bt;
        bt.B[0] = wt + W1O; bt.B[1] = wt + W3O; bt.B[2] = nullptr;
        bt.C[0] = t1; bt.C[1] = t3; bt.C[2] = nullptr;
        bt.R[0] = bt.R[1] = bt.R[2] = nullptr;
        gemm_tc<false><<<dim3(HIDDEN / BN, SEQ / BM, 2), 256, GSMEM>>>(hn, bt, SEQ, HIDDEN, DIM);
    }

    silu_mul_k<<<(SEQ * HIDDEN / 4 + 255) / 256, 256>>>(t1, t3, SEQ * HIDDEN / 4);

    // W2 + residual -> out
    {
        Batch3 bt;
        bt.B[0] = wt + W2O; bt.C[0] = out; bt.R[0] = out;
        bt.B[1] = bt.B[2] = nullptr; bt.C[1] = bt.C[2] = nullptr; bt.R[1] = bt.R[2] = nullptr;
        gemm_tc<true><<<dim3(DIM / BN, SEQ / BM, 1), 256, GSMEM>>>(t1, bt, SEQ, DIM, HIDDEN);
    }
}

// round 10
// speedup vs baseline: 1.0779x; 1.0779x over previous
#include <cuda_runtime.h>
#include <math.h>
#include <stdint.h>

#define SEQ    4096
#define DIM    1024
#define NH     16
#define HD     64
#define HIDDEN 4096

// ---------------- scratch -----------------------------------------------------------
__device__ float g_xn[SEQ * DIM];
__device__ float g_q [SEQ * DIM];
__device__ float g_k [SEQ * DIM];
__device__ float g_v [SEQ * DIM];
__device__ float g_at[SEQ * DIM];
__device__ float g_hn[SEQ * DIM];
__device__ float g_t1[SEQ * HIDDEN];
__device__ float g_t3[SEQ * HIDDEN];
__device__ float g_cos[SEQ * (HD / 2)];
__device__ float g_sin[SEQ * (HD / 2)];
__device__ float g_wt[16777216];          // tf32-rounded weights (64MB)

#define WQO 0
#define WKO 1048576
#define WVO 2097152
#define WOO 3145728
#define W1O 4194304
#define W3O 8388608
#define W2O 12582912

__device__ __forceinline__ uint32_t f2tf32(float f) {
    uint32_t u;
    asm("cvt.rna.tf32.f32 %0, %1;" : "=r"(u) : "f"(f));
    return u;
}
__device__ __forceinline__ float rtf32(float f) { return __uint_as_float(f2tf32(f)); }

__device__ __forceinline__ void mma_tf32(float* c, const uint32_t* a, uint32_t b0, uint32_t b1) {
    asm volatile(
        "mma.sync.aligned.m16n8k8.row.col.f32.tf32.tf32.f32 "
        "{%0,%1,%2,%3}, {%4,%5,%6,%7}, {%8,%9}, {%0,%1,%2,%3};\n"
        : "+f"(c[0]), "+f"(c[1]), "+f"(c[2]), "+f"(c[3])
        : "r"(a[0]), "r"(a[1]), "r"(a[2]), "r"(a[3]), "r"(b0), "r"(b1));
}

__device__ __forceinline__ void ldsm4(uint32_t* r, uint32_t saddr) {
    asm volatile("ldmatrix.sync.aligned.m8n8.x4.shared.b16 {%0,%1,%2,%3}, [%4];"
        : "=r"(r[0]), "=r"(r[1]), "=r"(r[2]), "=r"(r[3]) : "r"(saddr));
}

__device__ __forceinline__ void cp16(uint32_t saddr, const void* gptr) {
    asm volatile("cp.async.cg.shared.global [%0], [%1], 16;" :: "r"(saddr), "l"(gptr));
}

__device__ __forceinline__ uint32_t smem_u32(const void* p) {
    uint32_t a;
    asm("{ .reg .u64 t; cvta.to.shared.u64 t, %1; cvt.u32.u64 %0, t; }" : "=r"(a) : "l"(p));
    return a;
}

// ---------------- weight tf32 pre-round (single z-batched launch) --------------------
struct CvtBatch {
    const float* src[7];
    int off[7];
    int n4[7];
};

__global__ void cvt_all_k(CvtBatch cb, float* __restrict__ wt) {
    const float* src = cb.src[blockIdx.z];
    float* dst = wt + cb.off[blockIdx.z];
    int n4 = cb.n4[blockIdx.z];
    int stride = gridDim.x * blockDim.x;
    for (int i = blockIdx.x * blockDim.x + threadIdx.x; i < n4; i += stride) {
        float4 v = ((const float4*)src)[i];
        v.x = rtf32(v.x); v.y = rtf32(v.y); v.z = rtf32(v.z); v.w = rtf32(v.w);
        ((float4*)dst)[i] = v;
    }
}

// ---------------- RoPE tables in double precision ------------------------------------
__global__ void rope_tables_k(float* __restrict__ c, float* __restrict__ s) {
    int idx = blockIdx.x * blockDim.x + threadIdx.x;
    int pos = idx >> 5;
    int i   = idx & 31;
    double inv = exp(-((double)(2 * i) / (double)HD) * log(10000.0));
    double ang = (double)pos * inv;
    double cs, sn;
    sincos(ang, &sn, &cs);
    c[idx] = (float)cs;
    s[idx] = (float)sn;
}

// ---------------- RMSNorm (tf32-rounded output) ---------------------------------------
__global__ void rmsnorm_k(const float* __restrict__ x, const float* __restrict__ g,
                          float* __restrict__ o) {
    int row = blockIdx.x;
    const float4* xr = (const float4*)(x + (size_t)row * DIM);
    float4*       orow = (float4*)(o + (size_t)row * DIM);
    int t = threadIdx.x;
    float4 v = xr[t];
    float ss = v.x * v.x + v.y * v.y + v.z * v.z + v.w * v.w;
    #pragma unroll
    for (int off = 16; off; off >>= 1) ss += __shfl_xor_sync(0xffffffffu, ss, off);
    __shared__ float sp[8];
    if ((t & 31) == 0) sp[t >> 5] = ss;
    __syncthreads();
    if (t < 8) {
        float s2 = sp[t];
        #pragma unroll
        for (int off = 4; off; off >>= 1) s2 += __shfl_xor_sync(0xffu, s2, off);
        if (t == 0) sp[0] = s2;
    }
    __syncthreads();
    float rs = rsqrtf(sp[0] * (1.0f / DIM) + 1e-6f);
    float4 gg = ((const float4*)g)[t];
    float4 out;
    out.x = rtf32(v.x * rs * gg.x);
    out.y = rtf32(v.y * rs * gg.y);
    out.z = rtf32(v.z * rs * gg.z);
    out.w = rtf32(v.w * rs * gg.w);
    orow[t] = out;
}

// ---------------- tf32 GEMM: CTA 128x128, warp 64x32, ldmatrix + cp.async (R8) -------
#define BM 128
#define BN 128
#define BK 16
#define SST 20
#define STAGES 3

struct Batch3 {
    const float* B[3];
    float*       C[3];
    const float* R[3];
};

template <bool RESID>
__global__ __launch_bounds__(256, 2)
void gemm_tc(const float* __restrict__ A, Batch3 bt, int M, int N, int K) {
    const float* __restrict__ Bp = bt.B[blockIdx.z];
    float*       __restrict__ Cp = bt.C[blockIdx.z];
    const float* __restrict__ Rp = bt.R[blockIdx.z];

    __shared__ uint32_t As[STAGES][BM][SST];
    __shared__ uint32_t Bs[STAGES][BN][SST];

    const int bm = blockIdx.y * BM;
    const int bn = blockIdx.x * BN;
    const int tid  = threadIdx.x;
    const int warp = tid >> 5;
    const int lane = tid & 31;
    const int grp  = lane >> 2;
    const int tig  = lane & 3;
    const int wm = (warp >> 2) * 64;
    const int wn = (warp & 3) * 32;

    const int arow = lane & 15;
    const int acol = (lane >> 4) * 4;
    const int brow = ((lane >> 4) << 3) + (lane & 7);
    const int bcol = ((lane >> 3) & 1) * 4;

    const int r0 = tid >> 2;
    const int r1 = r0 + 64;
    const int c4 = (tid & 3) * 4;

    float acc[4][4][4];
    #pragma unroll
    for (int i = 0; i < 4; i++)
        #pragma unroll
        for (int j = 0; j < 4; j++)
            #pragma unroll
            for (int r = 0; r < 4; r++) acc[i][j][r] = 0.0f;

    const int NT = K / BK;

    auto issue = [&](int kt) {
        const int st = kt % STAGES;
        cp16(smem_u32(&As[st][r0][c4]), A  + (size_t)(bm + r0) * K + kt * BK + c4);
        cp16(smem_u32(&As[st][r1][c4]), A  + (size_t)(bm + r1) * K + kt * BK + c4);
        cp16(smem_u32(&Bs[st][r0][c4]), Bp + (size_t)(bn + r0) * K + kt * BK + c4);
        cp16(smem_u32(&Bs[st][r1][c4]), Bp + (size_t)(bn + r1) * K + kt * BK + c4);
        asm volatile("cp.async.commit_group;");
    };

    issue(0);
    issue(1);

    for (int kt = 0; kt < NT; kt++) {
        if (kt + 1 < NT) {
            asm volatile("cp.async.wait_group 1;");
        } else {
            asm volatile("cp.async.wait_group 0;");
        }
        __syncthreads();
        if (kt + 2 < NT) issue(kt + 2);

        const int cur = kt % STAGES;
        const uint32_t ab = smem_u32(&As[cur][0][0]);
        const uint32_t bb = smem_u32(&Bs[cur][0][0]);

        #pragma unroll
        for (int ks = 0; ks < 2; ks++) {
            const int kb = ks * 8;
            uint32_t af[4][4], b2[2][4];
            #pragma unroll
            for (int mt = 0; mt < 4; mt++)
                ldsm4(af[mt], ab + (((wm + mt * 16 + arow) * SST) + kb + acol) * 4);
            ldsm4(b2[0], bb + (((wn +  0 + brow) * SST) + kb + bcol) * 4);
            ldsm4(b2[1], bb + (((wn + 16 + brow) * SST) + kb + bcol) * 4);
            #pragma unroll
            for (int mt = 0; mt < 4; mt++)
                #pragma unroll
                for (int nt = 0; nt < 4; nt++)
                    mma_tf32(acc[mt][nt],
                             af[mt],
                             b2[nt >> 1][(nt & 1) * 2],
                             b2[nt >> 1][(nt & 1) * 2 + 1]);
        }
    }

    #pragma unroll
    for (int mt = 0; mt < 4; mt++) {
        const int row = bm + wm + mt * 16 + grp;
        #pragma unroll
        for (int nt = 0; nt < 4; nt++) {
            const int col = bn + wn + nt * 8 + 2 * tig;
            size_t i0 = (size_t)row * N + col;
            size_t i1 = (size_t)(row + 8) * N + col;
            float2 v0 = make_float2(acc[mt][nt][0], acc[mt][nt][1]);
            float2 v1 = make_float2(acc[mt][nt][2], acc[mt][nt][3]);
            if (RESID) {
                float2 r0v = *(const float2*)&Rp[i0];
                float2 r1v = *(const float2*)&Rp[i1];
                v0.x += r0v.x; v0.y += r0v.y;
                v1.x += r1v.x; v1.y += r1v.y;
            }
            *(float2*)&Cp[i0] = v0;
            *(float2*)&Cp[i1] = v1;
        }
    }
}

// ---------------- RoPE ---------------------------------------------------------------
__global__ void rope_k(float* __restrict__ q, float* __restrict__ k,
                       const float* __restrict__ ct, const float* __restrict__ st) {
    int pos = blockIdx.x;
    int t = threadIdx.x;
    int h = t >> 5;
    int i = t & 31;
    float c = ct[pos * 32 + i];
    float s = st[pos * 32 + i];
    size_t base = (size_t)pos * DIM + h * HD + 2 * i;
    float2 qq = *(float2*)&q[base];
    float2 qo; qo.x = qq.x * c - qq.y * s; qo.y = qq.x * s + qq.y * c;
    *(float2*)&q[base] = qo;
    float2 kk = *(float2*)&k[base];
    float2 ko; ko.x = kk.x * c - kk.y * s; ko.y = kk.x * s + kk.y * c;
    *(float2*)&k[base] = ko;
}

// ---------------- Tensor-core flash attention (tf32, BQ=128, 8 warps) ----------------
// K layout [kv][d] stride 68 (ldsm-clean); V layout [kv][d] stride 72 (scalar PV B
// loads conflict-free: bank = 8*(tig+dt+kb)+grp covers all 32); P stride 68.
#define BQ   128
#define BKV  64
#define KP   68
#define VP   72

__global__ __launch_bounds__(256, 2)
void flash_attn_tc(const float* __restrict__ Q, const float* __restrict__ K,
                   const float* __restrict__ V, float* __restrict__ O) {
    __shared__ uint32_t Ks[BKV][KP];
    __shared__ uint32_t Vs[BKV][VP];
    __shared__ uint32_t Ps[BQ][KP];

    const int h  = blockIdx.y;
    const int q0 = blockIdx.x * BQ;
    const int tid  = threadIdx.x;
    const int warp = tid >> 5;
    const int lane = tid & 31;
    const int grp  = lane >> 2;
    const int tig  = lane & 3;
    const int wm   = warp * 16;       // 8 warps x 16 rows = 128

    const int arow = lane & 15;
    const int acol = (lane >> 4) * 4;
    const int brow = ((lane >> 4) << 3) + (lane & 7);
    const int bcol = ((lane >> 3) & 1) * 4;

    uint32_t qf[8][4];
    {
        const float* qb = Q + (size_t)(q0 + wm) * DIM + h * HD;
        #pragma unroll
        for (int ks = 0; ks < 8; ks++) {
            qf[ks][0] = f2tf32(0.125f * qb[(size_t)grp       * DIM + ks * 8 + tig]);
            qf[ks][1] = f2tf32(0.125f * qb[(size_t)(grp + 8) * DIM + ks * 8 + tig]);
            qf[ks][2] = f2tf32(0.125f * qb[(size_t)grp       * DIM + ks * 8 + tig + 4]);
            qf[ks][3] = f2tf32(0.125f * qb[(size_t)(grp + 8) * DIM + ks * 8 + tig + 4]);
        }
    }

    float o[8][4];
    #pragma unroll
    for (int dt = 0; dt < 8; dt++)
        #pragma unroll
        for (int r = 0; r < 4; r++) o[dt][r] = 0.0f;
    float m0 = -1e30f, m1 = -1e30f, l0 = 0.0f, l1 = 0.0f;

    const uint32_t ksb = smem_u32(&Ks[0][0]);
    const uint32_t psb = smem_u32(&Ps[0][0]);

    for (int k0 = 0; k0 < SEQ; k0 += BKV) {
        __syncthreads();
        // 256 threads load 64x64 K and V (1024 float4 slots -> 4 iters)
        #pragma unroll
        for (int i = 0; i < 4; i++) {
            int idx = tid + i * 256;
            int row = idx >> 4;
            int c   = (idx & 15) * 4;
            float4 k4 = *(const float4*)&K[(size_t)(k0 + row) * DIM + h * HD + c];
            Ks[row][c + 0] = f2tf32(k4.x); Ks[row][c + 1] = f2tf32(k4.y);
            Ks[row][c + 2] = f2tf32(k4.z); Ks[row][c + 3] = f2tf32(k4.w);
            float4 v4 = *(const float4*)&V[(size_t)(k0 + row) * DIM + h * HD + c];
            Vs[row][c + 0] = f2tf32(v4.x); Vs[row][c + 1] = f2tf32(v4.y);
            Vs[row][c + 2] = f2tf32(v4.z); Vs[row][c + 3] = f2tf32(v4.w);
        }
        __syncthreads();

        // S = Q K^T
        float sc[8][4];
        #pragma unroll
        for (int nt = 0; nt < 8; nt++)
            #pragma unroll
            for (int r = 0; r < 4; r++) sc[nt][r] = 0.0f;
        #pragma unroll
        for (int ks = 0; ks < 8; ks++) {
            const int kb = ks * 8;
            uint32_t kf[4][4];
            #pragma unroll
            for (int g = 0; g < 4; g++)
                ldsm4(kf[g], ksb + (((g * 16 + brow) * KP) + kb + bcol) * 4);
            #pragma unroll
            for (int nt = 0; nt < 8; nt++)
                mma_tf32(sc[nt], qf[ks],
                         kf[nt >> 1][(nt & 1) * 2],
                         kf[nt >> 1][(nt & 1) * 2 + 1]);
        }

        float mx0 = -1e30f, mx1 = -1e30f;
        #pragma unroll
        for (int nt = 0; nt < 8; nt++) {
            mx0 = fmaxf(mx0, fmaxf(sc[nt][0], sc[nt][1]));
            mx1 = fmaxf(mx1, fmaxf(sc[nt][2], sc[nt][3]));
        }
        mx0 = fmaxf(mx0, __shfl_xor_sync(0xffffffffu, mx0, 1));
        mx0 = fmaxf(mx0, __shfl_xor_sync(0xffffffffu, mx0, 2));
        mx1 = fmaxf(mx1, __shfl_xor_sync(0xffffffffu, mx1, 1));
        mx1 = fmaxf(mx1, __shfl_xor_sync(0xffffffffu, mx1, 2));

        float mn0 = fmaxf(m0, mx0);
        float mn1 = fmaxf(m1, mx1);
        float cr0 = __expf(m0 - mn0);
        float cr1 = __expf(m1 - mn1);
        m0 = mn0; m1 = mn1;

        float s0 = 0.0f, s1 = 0.0f;
        #pragma unroll
        for (int nt = 0; nt < 8; nt++) {
            sc[nt][0] = __expf(sc[nt][0] - mn0);
            sc[nt][1] = __expf(sc[nt][1] - mn0);
            sc[nt][2] = __expf(sc[nt][2] - mn1);
            sc[nt][3] = __expf(sc[nt][3] - mn1);
            s0 += sc[nt][0] + sc[nt][1];
            s1 += sc[nt][2] + sc[nt][3];
        }
        s0 += __shfl_xor_sync(0xffffffffu, s0, 1);
        s0 += __shfl_xor_sync(0xffffffffu, s0, 2);
        s1 += __shfl_xor_sync(0xffffffffu, s1, 1);
        s1 += __shfl_xor_sync(0xffffffffu, s1, 2);
        l0 = l0 * cr0 + s0;
        l1 = l1 * cr1 + s1;

        #pragma unroll
        for (int dt = 0; dt < 8; dt++) {
            o[dt][0] *= cr0; o[dt][1] *= cr0;
            o[dt][2] *= cr1; o[dt][3] *= cr1;
        }

        #pragma unroll
        for (int nt = 0; nt < 8; nt++) {
            uint2 u0 = make_uint2(f2tf32(sc[nt][0]), f2tf32(sc[nt][1]));
            uint2 u1 = make_uint2(f2tf32(sc[nt][2]), f2tf32(sc[nt][3]));
            *(uint2*)&Ps[wm + grp    ][nt * 8 + 2 * tig] = u0;
            *(uint2*)&Ps[wm + grp + 8][nt * 8 + 2 * tig] = u1;
        }
        __syncwarp();

        // O += P V
        #pragma unroll
        for (int ks = 0; ks < 8; ks++) {
            const int kb = ks * 8;
            uint32_t pa[4];
            ldsm4(pa, psb + (((wm + arow) * KP) + kb + acol) * 4);
            #pragma unroll
            for (int dt = 0; dt < 8; dt++) {
                uint32_t b0 = Vs[kb + tig    ][dt * 8 + grp];
                uint32_t b1 = Vs[kb + tig + 4][dt * 8 + grp];
                mma_tf32(o[dt], pa, b0, b1);
            }
        }
        __syncwarp();
    }

    float il0 = 1.0f / l0;
    float il1 = 1.0f / l1;
    #pragma unroll
    for (int dt = 0; dt < 8; dt++) {
        size_t i0 = (size_t)(q0 + wm + grp    ) * DIM + h * HD + dt * 8 + 2 * tig;
        size_t i1 = (size_t)(q0 + wm + grp + 8) * DIM + h * HD + dt * 8 + 2 * tig;
        *(float2*)&O[i0] = make_float2(rtf32(o[dt][0] * il0), rtf32(o[dt][1] * il0));
        *(float2*)&O[i1] = make_float2(rtf32(o[dt][2] * il1), rtf32(o[dt][3] * il1));
    }
}

// ---------------- SwiGLU elementwise (tf32-rounded output) ---------------------------
__global__ void silu_mul_k(float* __restrict__ a, const float* __restrict__ b, int n4) {
    int i = blockIdx.x * blockDim.x + threadIdx.x;
    if (i < n4) {
        float4 x = ((float4*)a)[i];
        float4 y = ((const float4*)b)[i];
        x.x = rtf32(x.x / (1.0f + __expf(-x.x)) * y.x);
        x.y = rtf32(x.y / (1.0f + __expf(-x.y)) * y.y);
        x.z = rtf32(x.z / (1.0f + __expf(-x.z)) * y.z);
        x.w = rtf32(x.w / (1.0f + __expf(-x.w)) * y.w);
        ((float4*)a)[i] = x;
    }
}

// ---------------- launch --------------------------------------------------------------
extern "C" void kernel_launch(void* const* d_in, const int* in_sizes, int n_in,
                              void* d_out, int out_size) {
    const float* x  = (const float*)d_in[0];
    const float* wq = (const float*)d_in[1];
    const float* wk = (const float*)d_in[2];
    const float* wv = (const float*)d_in[3];
    const float* wo = (const float*)d_in[4];
    const float* w1 = (const float*)d_in[5];
    const float* w2 = (const float*)d_in[6];
    const float* w3 = (const float*)d_in[7];
    const float* ga = (const float*)d_in[8];
    const float* gf = (const float*)d_in[9];
    float* out = (float*)d_out;

    float *xn, *q, *k, *v, *at, *hn, *t1, *t3, *ct, *st, *wt;
    cudaGetSymbolAddress((void**)&xn, g_xn);
    cudaGetSymbolAddress((void**)&q,  g_q);
    cudaGetSymbolAddress((void**)&k,  g_k);
    cudaGetSymbolAddress((void**)&v,  g_v);
    cudaGetSymbolAddress((void**)&at, g_at);
    cudaGetSymbolAddress((void**)&hn, g_hn);
    cudaGetSymbolAddress((void**)&t1, g_t1);
    cudaGetSymbolAddress((void**)&t3, g_t3);
    cudaGetSymbolAddress((void**)&ct, g_cos);
    cudaGetSymbolAddress((void**)&st, g_sin);
    cudaGetSymbolAddress((void**)&wt, g_wt);

    // all weights -> tf32 (one z-batched launch)
    {
        CvtBatch cb;
        cb.src[0] = wq; cb.off[0] = WQO; cb.n4[0] = DIM * DIM / 4;
        cb.src[1] = wk; cb.off[1] = WKO; cb.n4[1] = DIM * DIM / 4;
        cb.src[2] = wv; cb.off[2] = WVO; cb.n4[2] = DIM * DIM / 4;
        cb.src[3] = wo; cb.off[3] = WOO; cb.n4[3] = DIM * DIM / 4;
        cb.src[4] = w1; cb.off[4] = W1O; cb.n4[4] = HIDDEN * DIM / 4;
        cb.src[5] = w3; cb.off[5] = W3O; cb.n4[5] = HIDDEN * DIM / 4;
        cb.src[6] = w2; cb.off[6] = W2O; cb.n4[6] = DIM * HIDDEN / 4;
        cvt_all_k<<<dim3(256, 1, 7), 256>>>(cb, wt);
    }

    rope_tables_k<<<(SEQ * 32) / 256, 256>>>(ct, st);
    rmsnorm_k<<<SEQ, 256>>>(x, ga, xn);

    // QKV batched (z = 3)
    {
        Batch3 bt;
        bt.B[0] = wt + WQO; bt.B[1] = wt + WKO; bt.B[2] = wt + WVO;
        bt.C[0] = q; bt.C[1] = k; bt.C[2] = v;
        bt.R[0] = bt.R[1] = bt.R[2] = nullptr;
        gemm_tc<false><<<dim3(DIM / BN, SEQ / BM, 3), 256>>>(xn, bt, SEQ, DIM, DIM);
    }

    rope_k<<<SEQ, 512>>>(q, k, ct, st);
    flash_attn_tc<<<dim3(SEQ / BQ, NH), 256>>>(q, k, v, at);

    // Wo + residual -> out
    {
        Batch3 bt;
        bt.B[0] = wt + WOO; bt.C[0] = out; bt.R[0] = x;
        bt.B[1] = bt.B[2] = nullptr; bt.C[1] = bt.C[2] = nullptr; bt.R[1] = bt.R[2] = nullptr;
        gemm_tc<true><<<dim3(DIM / BN, SEQ / BM, 1), 256>>>(at, bt, SEQ, DIM, DIM);
    }

    rmsnorm_k<<<SEQ, 256>>>(out, gf, hn);

    // w1 / w3 batched (z = 2)
    {
        Batch3 bt;
        bt.B[0] = wt + W1O; bt.B[1] = wt + W3O; bt.B[2] = nullptr;
        bt.C[0] = t1; bt.C[1] = t3; bt.C[2] = nullptr;
        bt.R[0] = bt.R[1] = bt.R[2] = nullptr;
        gemm_tc<false><<<dim3(HIDDEN / BN, SEQ / BM, 2), 256>>>(hn, bt, SEQ, HIDDEN, DIM);
    }

    silu_mul_k<<<(SEQ * HIDDEN / 4 + 255) / 256, 256>>>(t1, t3, SEQ * HIDDEN / 4);

    // W2 + residual -> out
    {
        Batch3 bt;
        bt.B[0] = wt + W2O; bt.C[0] = out; bt.R[0] = out;
        bt.B[1] = bt.B[2] = nullptr; bt.C[1] = bt.C[2] = nullptr; bt.R[1] = bt.R[2] = nullptr;
        gemm_tc<true><<<dim3(DIM / BN, SEQ / BM, 1), 256>>>(t1, bt, SEQ, DIM, HIDDEN);
    }
}

// round 11
// speedup vs baseline: 1.1049x; 1.0250x over previous
#include <cuda_runtime.h>
#include <math.h>
#include <stdint.h>

#define SEQ    4096
#define DIM    1024
#define NH     16
#define HD     64
#define HIDDEN 4096

// ---------------- scratch -----------------------------------------------------------
__device__ float g_xn[SEQ * DIM];
__device__ float g_q [SEQ * DIM];
__device__ float g_k [SEQ * DIM];
__device__ float g_v [SEQ * DIM];
__device__ float g_at[SEQ * DIM];
__device__ float g_hn[SEQ * DIM];
__device__ float g_t1[SEQ * HIDDEN];
__device__ float g_t3[SEQ * HIDDEN];
__device__ float g_cos[SEQ * (HD / 2)];
__device__ float g_sin[SEQ * (HD / 2)];
__device__ float g_wt[16777216];          // tf32-rounded weights (64MB)

#define WQO 0
#define WKO 1048576
#define WVO 2097152
#define WOO 3145728
#define W1O 4194304
#define W3O 8388608
#define W2O 12582912

__device__ __forceinline__ uint32_t f2tf32(float f) {
    uint32_t u;
    asm("cvt.rna.tf32.f32 %0, %1;" : "=r"(u) : "f"(f));
    return u;
}
__device__ __forceinline__ float rtf32(float f) { return __uint_as_float(f2tf32(f)); }

__device__ __forceinline__ void mma_tf32(float* c, const uint32_t* a, uint32_t b0, uint32_t b1) {
    asm volatile(
        "mma.sync.aligned.m16n8k8.row.col.f32.tf32.tf32.f32 "
        "{%0,%1,%2,%3}, {%4,%5,%6,%7}, {%8,%9}, {%0,%1,%2,%3};\n"
        : "+f"(c[0]), "+f"(c[1]), "+f"(c[2]), "+f"(c[3])
        : "r"(a[0]), "r"(a[1]), "r"(a[2]), "r"(a[3]), "r"(b0), "r"(b1));
}

__device__ __forceinline__ void ldsm4(uint32_t* r, uint32_t saddr) {
    asm volatile("ldmatrix.sync.aligned.m8n8.x4.shared.b16 {%0,%1,%2,%3}, [%4];"
        : "=r"(r[0]), "=r"(r[1]), "=r"(r[2]), "=r"(r[3]) : "r"(saddr));
}

__device__ __forceinline__ void cp16(uint32_t saddr, const void* gptr) {
    asm volatile("cp.async.cg.shared.global [%0], [%1], 16;" :: "r"(saddr), "l"(gptr));
}

__device__ __forceinline__ uint32_t smem_u32(const void* p) {
    uint32_t a;
    asm("{ .reg .u64 t; cvta.to.shared.u64 t, %1; cvt.u32.u64 %0, t; }" : "=r"(a) : "l"(p));
    return a;
}

// ---------------- weight tf32 pre-round (single z-batched launch) --------------------
struct CvtBatch {
    const float* src[7];
    int off[7];
    int n4[7];
};

__global__ void cvt_all_k(CvtBatch cb, float* __restrict__ wt) {
    const float* src = cb.src[blockIdx.z];
    float* dst = wt + cb.off[blockIdx.z];
    int n4 = cb.n4[blockIdx.z];
    int stride = gridDim.x * blockDim.x;
    for (int i = blockIdx.x * blockDim.x + threadIdx.x; i < n4; i += stride) {
        float4 v = ((const float4*)src)[i];
        v.x = rtf32(v.x); v.y = rtf32(v.y); v.z = rtf32(v.z); v.w = rtf32(v.w);
        ((float4*)dst)[i] = v;
    }
}

// ---------------- RoPE tables in double precision ------------------------------------
__global__ void rope_tables_k(float* __restrict__ c, float* __restrict__ s) {
    int idx = blockIdx.x * blockDim.x + threadIdx.x;
    int pos = idx >> 5;
    int i   = idx & 31;
    double inv = exp(-((double)(2 * i) / (double)HD) * log(10000.0));
    double ang = (double)pos * inv;
    double cs, sn;
    sincos(ang, &sn, &cs);
    c[idx] = (float)cs;
    s[idx] = (float)sn;
}

// ---------------- RMSNorm (tf32-rounded output) ---------------------------------------
__global__ void rmsnorm_k(const float* __restrict__ x, const float* __restrict__ g,
                          float* __restrict__ o) {
    int row = blockIdx.x;
    const float4* xr = (const float4*)(x + (size_t)row * DIM);
    float4*       orow = (float4*)(o + (size_t)row * DIM);
    int t = threadIdx.x;
    float4 v = xr[t];
    float ss = v.x * v.x + v.y * v.y + v.z * v.z + v.w * v.w;
    #pragma unroll
    for (int off = 16; off; off >>= 1) ss += __shfl_xor_sync(0xffffffffu, ss, off);
    __shared__ float sp[8];
    if ((t & 31) == 0) sp[t >> 5] = ss;
    __syncthreads();
    if (t < 8) {
        float s2 = sp[t];
        #pragma unroll
        for (int off = 4; off; off >>= 1) s2 += __shfl_xor_sync(0xffu, s2, off);
        if (t == 0) sp[0] = s2;
    }
    __syncthreads();
    float rs = rsqrtf(sp[0] * (1.0f / DIM) + 1e-6f);
    float4 gg = ((const float4*)g)[t];
    float4 out;
    out.x = rtf32(v.x * rs * gg.x);
    out.y = rtf32(v.y * rs * gg.y);
    out.z = rtf32(v.z * rs * gg.z);
    out.w = rtf32(v.w * rs * gg.w);
    orow[t] = out;
}

// ---------------- tf32 GEMM: CTA 128x128, warp 64x32, ldmatrix + cp.async ------------
#define BM 128
#define BN 128
#define BK 16
#define SST 20
#define STAGES 3

struct Batch3 {
    const float* B[3];
    float*       C[3];
    const float* R[3];
};

template <bool RESID>
__global__ __launch_bounds__(256, 2)
void gemm_tc(const float* __restrict__ A, Batch3 bt, int M, int N, int K) {
    const float* __restrict__ Bp = bt.B[blockIdx.z];
    float*       __restrict__ Cp = bt.C[blockIdx.z];
    const float* __restrict__ Rp = bt.R[blockIdx.z];

    __shared__ uint32_t As[STAGES][BM][SST];
    __shared__ uint32_t Bs[STAGES][BN][SST];

    const int bm = blockIdx.y * BM;
    const int bn = blockIdx.x * BN;
    const int tid  = threadIdx.x;
    const int warp = tid >> 5;
    const int lane = tid & 31;
    const int grp  = lane >> 2;
    const int tig  = lane & 3;
    const int wm = (warp >> 2) * 64;
    const int wn = (warp & 3) * 32;

    const int arow = lane & 15;
    const int acol = (lane >> 4) * 4;
    const int brow = ((lane >> 4) << 3) + (lane & 7);
    const int bcol = ((lane >> 3) & 1) * 4;

    const int r0 = tid >> 2;
    const int r1 = r0 + 64;
    const int c4 = (tid & 3) * 4;

    float acc[4][4][4];
    #pragma unroll
    for (int i = 0; i < 4; i++)
        #pragma unroll
        for (int j = 0; j < 4; j++)
            #pragma unroll
            for (int r = 0; r < 4; r++) acc[i][j][r] = 0.0f;

    const int NT = K / BK;

    auto issue = [&](int kt) {
        const int st = kt % STAGES;
        cp16(smem_u32(&As[st][r0][c4]), A  + (size_t)(bm + r0) * K + kt * BK + c4);
        cp16(smem_u32(&As[st][r1][c4]), A  + (size_t)(bm + r1) * K + kt * BK + c4);
        cp16(smem_u32(&Bs[st][r0][c4]), Bp + (size_t)(bn + r0) * K + kt * BK + c4);
        cp16(smem_u32(&Bs[st][r1][c4]), Bp + (size_t)(bn + r1) * K + kt * BK + c4);
        asm volatile("cp.async.commit_group;");
    };

    issue(0);
    issue(1);

    for (int kt = 0; kt < NT; kt++) {
        if (kt + 1 < NT) {
            asm volatile("cp.async.wait_group 1;");
        } else {
            asm volatile("cp.async.wait_group 0;");
        }
        __syncthreads();
        if (kt + 2 < NT) issue(kt + 2);

        const int cur = kt % STAGES;
        const uint32_t ab = smem_u32(&As[cur][0][0]);
        const uint32_t bb = smem_u32(&Bs[cur][0][0]);

        #pragma unroll
        for (int ks = 0; ks < 2; ks++) {
            const int kb = ks * 8;
            uint32_t af[4][4], b2[2][4];
            #pragma unroll
            for (int mt = 0; mt < 4; mt++)
                ldsm4(af[mt], ab + (((wm + mt * 16 + arow) * SST) + kb + acol) * 4);
            ldsm4(b2[0], bb + (((wn +  0 + brow) * SST) + kb + bcol) * 4);
            ldsm4(b2[1], bb + (((wn + 16 + brow) * SST) + kb + bcol) * 4);
            #pragma unroll
            for (int mt = 0; mt < 4; mt++)
                #pragma unroll
                for (int nt = 0; nt < 4; nt++)
                    mma_tf32(acc[mt][nt],
                             af[mt],
                             b2[nt >> 1][(nt & 1) * 2],
                             b2[nt >> 1][(nt & 1) * 2 + 1]);
        }
    }

    #pragma unroll
    for (int mt = 0; mt < 4; mt++) {
        const int row = bm + wm + mt * 16 + grp;
        #pragma unroll
        for (int nt = 0; nt < 4; nt++) {
            const int col = bn + wn + nt * 8 + 2 * tig;
            size_t i0 = (size_t)row * N + col;
            size_t i1 = (size_t)(row + 8) * N + col;
            float2 v0 = make_float2(acc[mt][nt][0], acc[mt][nt][1]);
            float2 v1 = make_float2(acc[mt][nt][2], acc[mt][nt][3]);
            if (RESID) {
                float2 r0v = *(const float2*)&Rp[i0];
                float2 r1v = *(const float2*)&Rp[i1];
                v0.x += r0v.x; v0.y += r0v.y;
                v1.x += r1v.x; v1.y += r1v.y;
            }
            *(float2*)&Cp[i0] = v0;
            *(float2*)&Cp[i1] = v1;
        }
    }
}

// ---------------- RoPE ---------------------------------------------------------------
__global__ void rope_k(float* __restrict__ q, float* __restrict__ k,
                       const float* __restrict__ ct, const float* __restrict__ st) {
    int pos = blockIdx.x;
    int t = threadIdx.x;
    int h = t >> 5;
    int i = t & 31;
    float c = ct[pos * 32 + i];
    float s = st[pos * 32 + i];
    size_t base = (size_t)pos * DIM + h * HD + 2 * i;
    float2 qq = *(float2*)&q[base];
    float2 qo; qo.x = qq.x * c - qq.y * s; qo.y = qq.x * s + qq.y * c;
    *(float2*)&q[base] = qo;
    float2 kk = *(float2*)&k[base];
    float2 ko; ko.x = kk.x * c - kk.y * s; ko.y = kk.x * s + kk.y * c;
    *(float2*)&k[base] = ko;
}

// ---------------- Tensor-core flash attention -----------------------------------------
// BQ=128 (8 warps), BKV=64. K/V loaded via cp.async double-buffer, fed to MMA as raw
// fp32 bits (HW truncates to tf32). K stride 68 (ldsm-clean); V stride 72 (scalar PV
// B-loads conflict-free: bank = 8*(tig+dt+kb)+grp covers 0..31); P stride 68.
#define BQ   128
#define BKV  64
#define KP   68
#define VP   72
#define KW   (BKV * KP)             // K stage words
#define VW   (BKV * VP)             // V stage words
#define AST  (KW + VW)              // words per stage
#define PSO  (2 * AST)              // Ps offset (words)
#define ASMEM ((PSO + BQ * KP) * 4) // bytes = 106496

__global__ __launch_bounds__(256, 2)
void flash_attn_tc(const float* __restrict__ Q, const float* __restrict__ K,
                   const float* __restrict__ V, float* __restrict__ O) {
    extern __shared__ uint32_t asm_[];

    const int h  = blockIdx.y;
    const int q0 = blockIdx.x * BQ;
    const int tid  = threadIdx.x;
    const int warp = tid >> 5;
    const int lane = tid & 31;
    const int grp  = lane >> 2;
    const int tig  = lane & 3;
    const int wm   = warp * 16;       // 8 warps x 16 rows = 128

    const int arow = lane & 15;
    const int acol = (lane >> 4) * 4;
    const int brow = ((lane >> 4) << 3) + (lane & 7);
    const int bcol = ((lane >> 3) & 1) * 4;

    const uint32_t smb = smem_u32(asm_);
    const uint32_t psb = smb + PSO * 4;

    uint32_t qf[8][4];
    {
        const float* qb = Q + (size_t)(q0 + wm) * DIM + h * HD;
        #pragma unroll
        for (int ks = 0; ks < 8; ks++) {
            qf[ks][0] = f2tf32(0.125f * qb[(size_t)grp       * DIM + ks * 8 + tig]);
            qf[ks][1] = f2tf32(0.125f * qb[(size_t)(grp + 8) * DIM + ks * 8 + tig]);
            qf[ks][2] = f2tf32(0.125f * qb[(size_t)grp       * DIM + ks * 8 + tig + 4]);
            qf[ks][3] = f2tf32(0.125f * qb[(size_t)(grp + 8) * DIM + ks * 8 + tig + 4]);
        }
    }

    float o[8][4];
    #pragma unroll
    for (int dt = 0; dt < 8; dt++)
        #pragma unroll
        for (int r = 0; r < 4; r++) o[dt][r] = 0.0f;
    float m0 = -1e30f, m1 = -1e30f, l0 = 0.0f, l1 = 0.0f;

    const int NT = SEQ / BKV;
    const int lrow = tid >> 4;          // 0..15
    const int lc4  = (tid & 15) * 4;    // 0..60

    auto issue = [&](int t) {
        const uint32_t kb = smb + (t & 1) * AST * 4;
        const uint32_t vb = kb + KW * 4;
        const float* Kg = K + (size_t)(t * BKV) * DIM + h * HD;
        const float* Vg = V + (size_t)(t * BKV) * DIM + h * HD;
        #pragma unroll
        for (int i = 0; i < 4; i++) {
            int row = lrow + i * 16;
            cp16(kb + (row * KP + lc4) * 4, Kg + (size_t)row * DIM + lc4);
            cp16(vb + (row * VP + lc4) * 4, Vg + (size_t)row * DIM + lc4);
        }
        asm volatile("cp.async.commit_group;");
    };

    issue(0);

    for (int t = 0; t < NT; t++) {
        if (t + 1 < NT) {
            issue(t + 1);
            asm volatile("cp.async.wait_group 1;");
        } else {
            asm volatile("cp.async.wait_group 0;");
        }
        __syncthreads();

        const uint32_t ksb = smb + (t & 1) * AST * 4;
        const uint32_t vsb = ksb + KW * 4;
        const uint32_t* Vs = (const uint32_t*)(asm_ + (t & 1) * AST + KW);

        // S = Q K^T
        float sc[8][4];
        #pragma unroll
        for (int nt = 0; nt < 8; nt++)
            #pragma unroll
            for (int r = 0; r < 4; r++) sc[nt][r] = 0.0f;
        #pragma unroll
        for (int ks = 0; ks < 8; ks++) {
            const int kb = ks * 8;
            uint32_t kf[4][4];
            #pragma unroll
            for (int g = 0; g < 4; g++)
                ldsm4(kf[g], ksb + (((g * 16 + brow) * KP) + kb + bcol) * 4);
            #pragma unroll
            for (int nt = 0; nt < 8; nt++)
                mma_tf32(sc[nt], qf[ks],
                         kf[nt >> 1][(nt & 1) * 2],
                         kf[nt >> 1][(nt & 1) * 2 + 1]);
        }

        float mx0 = -1e30f, mx1 = -1e30f;
        #pragma unroll
        for (int nt = 0; nt < 8; nt++) {
            mx0 = fmaxf(mx0, fmaxf(sc[nt][0], sc[nt][1]));
            mx1 = fmaxf(mx1, fmaxf(sc[nt][2], sc[nt][3]));
        }
        mx0 = fmaxf(mx0, __shfl_xor_sync(0xffffffffu, mx0, 1));
        mx0 = fmaxf(mx0, __shfl_xor_sync(0xffffffffu, mx0, 2));
        mx1 = fmaxf(mx1, __shfl_xor_sync(0xffffffffu, mx1, 1));
        mx1 = fmaxf(mx1, __shfl_xor_sync(0xffffffffu, mx1, 2));

        float mn0 = fmaxf(m0, mx0);
        float mn1 = fmaxf(m1, mx1);
        float cr0 = __expf(m0 - mn0);
        float cr1 = __expf(m1 - mn1);
        m0 = mn0; m1 = mn1;

        float s0 = 0.0f, s1 = 0.0f;
        #pragma unroll
        for (int nt = 0; nt < 8; nt++) {
            sc[nt][0] = __expf(sc[nt][0] - mn0);
            sc[nt][1] = __expf(sc[nt][1] - mn0);
            sc[nt][2] = __expf(sc[nt][2] - mn1);
            sc[nt][3] = __expf(sc[nt][3] - mn1);
            s0 += sc[nt][0] + sc[nt][1];
            s1 += sc[nt][2] + sc[nt][3];
        }
        s0 += __shfl_xor_sync(0xffffffffu, s0, 1);
        s0 += __shfl_xor_sync(0xffffffffu, s0, 2);
        s1 += __shfl_xor_sync(0xffffffffu, s1, 1);
        s1 += __shfl_xor_sync(0xffffffffu, s1, 2);
        l0 = l0 * cr0 + s0;
        l1 = l1 * cr1 + s1;

        #pragma unroll
        for (int dt = 0; dt < 8; dt++) {
            o[dt][0] *= cr0; o[dt][1] *= cr0;
            o[dt][2] *= cr1; o[dt][3] *= cr1;
        }

        #pragma unroll
        for (int nt = 0; nt < 8; nt++) {
            uint2 u0 = make_uint2(f2tf32(sc[nt][0]), f2tf32(sc[nt][1]));
            uint2 u1 = make_uint2(f2tf32(sc[nt][2]), f2tf32(sc[nt][3]));
            *(uint2*)(asm_ + PSO + (wm + grp    ) * KP + nt * 8 + 2 * tig) = u0;
            *(uint2*)(asm_ + PSO + (wm + grp + 8) * KP + nt * 8 + 2 * tig) = u1;
        }
        __syncwarp();

        // O += P V
        #pragma unroll
        for (int ks = 0; ks < 8; ks++) {
            const int kb = ks * 8;
            uint32_t pa[4];
            ldsm4(pa, psb + (((wm + arow) * KP) + kb + acol) * 4);
            #pragma unroll
            for (int dt = 0; dt < 8; dt++) {
                uint32_t b0 = Vs[(kb + tig    ) * VP + dt * 8 + grp];
                uint32_t b1 = Vs[(kb + tig + 4) * VP + dt * 8 + grp];
                mma_tf32(o[dt], pa, b0, b1);
            }
        }
        __syncthreads();
    }

    float il0 = 1.0f / l0;
    float il1 = 1.0f / l1;
    #pragma unroll
    for (int dt = 0; dt < 8; dt++) {
        size_t i0 = (size_t)(q0 + wm + grp    ) * DIM + h * HD + dt * 8 + 2 * tig;
        size_t i1 = (size_t)(q0 + wm + grp + 8) * DIM + h * HD + dt * 8 + 2 * tig;
        *(float2*)&O[i0] = make_float2(rtf32(o[dt][0] * il0), rtf32(o[dt][1] * il0));
        *(float2*)&O[i1] = make_float2(rtf32(o[dt][2] * il1), rtf32(o[dt][3] * il1));
    }
}

// ---------------- SwiGLU elementwise (tf32-rounded output) ---------------------------
__global__ void silu_mul_k(float* __restrict__ a, const float* __restrict__ b, int n4) {
    int i = blockIdx.x * blockDim.x + threadIdx.x;
    if (i < n4) {
        float4 x = ((float4*)a)[i];
        float4 y = ((const float4*)b)[i];
        x.x = rtf32(x.x / (1.0f + __expf(-x.x)) * y.x);
        x.y = rtf32(x.y / (1.0f + __expf(-x.y)) * y.y);
        x.z = rtf32(x.z / (1.0f + __expf(-x.z)) * y.z);
        x.w = rtf32(x.w / (1.0f + __expf(-x.w)) * y.w);
        ((float4*)a)[i] = x;
    }
}

// ---------------- launch --------------------------------------------------------------
extern "C" void kernel_launch(void* const* d_in, const int* in_sizes, int n_in,
                              void* d_out, int out_size) {
    const float* x  = (const float*)d_in[0];
    const float* wq = (const float*)d_in[1];
    const float* wk = (const float*)d_in[2];
    const float* wv = (const float*)d_in[3];
    const float* wo = (const float*)d_in[4];
    const float* w1 = (const float*)d_in[5];
    const float* w2 = (const float*)d_in[6];
    const float* w3 = (const float*)d_in[7];
    const float* ga = (const float*)d_in[8];
    const float* gf = (const float*)d_in[9];
    float* out = (float*)d_out;

    float *xn, *q, *k, *v, *at, *hn, *t1, *t3, *ct, *st, *wt;
    cudaGetSymbolAddress((void**)&xn, g_xn);
    cudaGetSymbolAddress((void**)&q,  g_q);
    cudaGetSymbolAddress((void**)&k,  g_k);
    cudaGetSymbolAddress((void**)&v,  g_v);
    cudaGetSymbolAddress((void**)&at, g_at);
    cudaGetSymbolAddress((void**)&hn, g_hn);
    cudaGetSymbolAddress((void**)&t1, g_t1);
    cudaGetSymbolAddress((void**)&t3, g_t3);
    cudaGetSymbolAddress((void**)&ct, g_cos);
    cudaGetSymbolAddress((void**)&st, g_sin);
    cudaGetSymbolAddress((void**)&wt, g_wt);

    cudaFuncSetAttribute(flash_attn_tc, cudaFuncAttributeMaxDynamicSharedMemorySize, ASMEM);

    // all weights -> tf32 (one z-batched launch)
    {
        CvtBatch cb;
        cb.src[0] = wq; cb.off[0] = WQO; cb.n4[0] = DIM * DIM / 4;
        cb.src[1] = wk; cb.off[1] = WKO; cb.n4[1] = DIM * DIM / 4;
        cb.src[2] = wv; cb.off[2] = WVO; cb.n4[2] = DIM * DIM / 4;
        cb.src[3] = wo; cb.off[3] = WOO; cb.n4[3] = DIM * DIM / 4;
        cb.src[4] = w1; cb.off[4] = W1O; cb.n4[4] = HIDDEN * DIM / 4;
        cb.src[5] = w3; cb.off[5] = W3O; cb.n4[5] = HIDDEN * DIM / 4;
        cb.src[6] = w2; cb.off[6] = W2O; cb.n4[6] = DIM * HIDDEN / 4;
        cvt_all_k<<<dim3(256, 1, 7), 256>>>(cb, wt);
    }

    rope_tables_k<<<(SEQ * 32) / 256, 256>>>(ct, st);
    rmsnorm_k<<<SEQ, 256>>>(x, ga, xn);

    // QKV batched (z = 3)
    {
        Batch3 bt;
        bt.B[0] = wt + WQO; bt.B[1] = wt + WKO; bt.B[2] = wt + WVO;
        bt.C[0] = q; bt.C[1] = k; bt.C[2] = v;
        bt.R[0] = bt.R[1] = bt.R[2] = nullptr;
        gemm_tc<false><<<dim3(DIM / BN, SEQ / BM, 3), 256>>>(xn, bt, SEQ, DIM, DIM);
    }

    rope_k<<<SEQ, 512>>>(q, k, ct, st);
    flash_attn_tc<<<dim3(SEQ / BQ, NH), 256, ASMEM>>>(q, k, v, at);

    // Wo + residual -> out
    {
        Batch3 bt;
        bt.B[0] = wt + WOO; bt.C[0] = out; bt.R[0] = x;
        bt.B[1] = bt.B[2] = nullptr; bt.C[1] = bt.C[2] = nullptr; bt.R[1] = bt.R[2] = nullptr;
        gemm_tc<true><<<dim3(DIM / BN, SEQ / BM, 1), 256>>>(at, bt, SEQ, DIM, DIM);
    }

    rmsnorm_k<<<SEQ, 256>>>(out, gf, hn);

    // w1 / w3 batched (z = 2)
    {
        Batch3 bt;
        bt.B[0] = wt + W1O; bt.B[1] = wt + W3O; bt.B[2] = nullptr;
        bt.C[0] = t1; bt.C[1] = t3; bt.C[2] = nullptr;
        bt.R[0] = bt.R[1] = bt.R[2] = nullptr;
        gemm_tc<false><<<dim3(HIDDEN / BN, SEQ / BM, 2), 256>>>(hn, bt, SEQ, HIDDEN, DIM);
    }

    silu_mul_k<<<(SEQ * HIDDEN / 4 + 255) / 256, 256>>>(t1, t3, SEQ * HIDDEN / 4);

    // W2 + residual -> out
    {
        Batch3 bt;
        bt.B[0] = wt + W2O; bt.C[0] = out; bt.R[0] = out;
        bt.B[1] = bt.B[2] = nullptr; bt.C[1] = bt.C[2] = nullptr; bt.R[1] = bt.R[2] = nullptr;
        gemm_tc<true><<<dim3(DIM / BN, SEQ / BM, 1), 256>>>(t1, bt, SEQ, DIM, HIDDEN);
    }
}

// round 12
// speedup vs baseline: 1.7216x; 1.5582x over previous
#include <cuda_runtime.h>
#include <cuda_fp16.h>
#include <math.h>
#include <stdint.h>

#define SEQ    4096
#define DIM    1024
#define NH     16
#define HD     64
#define HIDDEN 4096

// ---------------- scratch (fp16 activations/weights) ---------------------------------
__device__ __half g_xn[SEQ * DIM];
__device__ __half g_q [SEQ * DIM];
__device__ __half g_k [SEQ * DIM];
__device__ __half g_v [SEQ * DIM];
__device__ __half g_at[SEQ * DIM];
__device__ __half g_hn[SEQ * DIM];
__device__ __half g_t1[SEQ * HIDDEN];
__device__ __half g_t3[SEQ * HIDDEN];
__device__ float  g_cos[SEQ * (HD / 2)];
__device__ float  g_sin[SEQ * (HD / 2)];
__device__ __half g_wt[16777216];          // fp16 weights (32MB)

#define WQO 0
#define WKO 1048576
#define WVO 2097152
#define WOO 3145728
#define W1O 4194304
#define W3O 8388608
#define W2O 12582912

__device__ __forceinline__ uint32_t h2pack(float a, float b) {
    __half2 h = __floats2half2_rn(a, b);
    return *reinterpret_cast<uint32_t*>(&h);
}

__device__ __forceinline__ void mma_f16(float* c, const uint32_t* a, uint32_t b0, uint32_t b1) {
    asm volatile(
        "mma.sync.aligned.m16n8k16.row.col.f32.f16.f16.f32 "
        "{%0,%1,%2,%3}, {%4,%5,%6,%7}, {%8,%9}, {%0,%1,%2,%3};\n"
        : "+f"(c[0]), "+f"(c[1]), "+f"(c[2]), "+f"(c[3])
        : "r"(a[0]), "r"(a[1]), "r"(a[2]), "r"(a[3]), "r"(b0), "r"(b1));
}

__device__ __forceinline__ void ldsm4(uint32_t* r, uint32_t saddr) {
    asm volatile("ldmatrix.sync.aligned.m8n8.x4.shared.b16 {%0,%1,%2,%3}, [%4];"
        : "=r"(r[0]), "=r"(r[1]), "=r"(r[2]), "=r"(r[3]) : "r"(saddr));
}

__device__ __forceinline__ void ldsm4t(uint32_t* r, uint32_t saddr) {
    asm volatile("ldmatrix.sync.aligned.m8n8.x4.trans.shared.b16 {%0,%1,%2,%3}, [%4];"
        : "=r"(r[0]), "=r"(r[1]), "=r"(r[2]), "=r"(r[3]) : "r"(saddr));
}

__device__ __forceinline__ void cp16(uint32_t saddr, const void* gptr) {
    asm volatile("cp.async.cg.shared.global [%0], [%1], 16;" :: "r"(saddr), "l"(gptr));
}

__device__ __forceinline__ uint32_t smem_u32(const void* p) {
    uint32_t a;
    asm("{ .reg .u64 t; cvta.to.shared.u64 t, %1; cvt.u32.u64 %0, t; }" : "=r"(a) : "l"(p));
    return a;
}

// ---------------- weight fp16 convert (single z-batched launch) ----------------------
struct CvtBatch {
    const float* src[7];
    int off[7];
    int n4[7];
};

__global__ void cvt_all_k(CvtBatch cb, __half* __restrict__ wt) {
    const float* src = cb.src[blockIdx.z];
    __half* dst = wt + cb.off[blockIdx.z];
    int n4 = cb.n4[blockIdx.z];
    int stride = gridDim.x * blockDim.x;
    for (int i = blockIdx.x * blockDim.x + threadIdx.x; i < n4; i += stride) {
        float4 v = ((const float4*)src)[i];
        uint2 o;
        o.x = h2pack(v.x, v.y);
        o.y = h2pack(v.z, v.w);
        ((uint2*)dst)[i] = o;
    }
}

// ---------------- RoPE tables in double precision ------------------------------------
__global__ void rope_tables_k(float* __restrict__ c, float* __restrict__ s) {
    int idx = blockIdx.x * blockDim.x + threadIdx.x;
    int pos = idx >> 5;
    int i   = idx & 31;
    double inv = exp(-((double)(2 * i) / (double)HD) * log(10000.0));
    double ang = (double)pos * inv;
    double cs, sn;
    sincos(ang, &sn, &cs);
    c[idx] = (float)cs;
    s[idx] = (float)sn;
}

// ---------------- RMSNorm: float in -> half out ---------------------------------------
__global__ void rmsnorm_k(const float* __restrict__ x, const float* __restrict__ g,
                          __half* __restrict__ o) {
    int row = blockIdx.x;
    const float4* xr = (const float4*)(x + (size_t)row * DIM);
    uint2* orow = (uint2*)(o + (size_t)row * DIM);
    int t = threadIdx.x;
    float4 v = xr[t];
    float ss = v.x * v.x + v.y * v.y + v.z * v.z + v.w * v.w;
    #pragma unroll
    for (int off = 16; off; off >>= 1) ss += __shfl_xor_sync(0xffffffffu, ss, off);
    __shared__ float sp[8];
    if ((t & 31) == 0) sp[t >> 5] = ss;
    __syncthreads();
    if (t < 8) {
        float s2 = sp[t];
        #pragma unroll
        for (int off = 4; off; off >>= 1) s2 += __shfl_xor_sync(0xffu, s2, off);
        if (t == 0) sp[0] = s2;
    }
    __syncthreads();
    float rs = rsqrtf(sp[0] * (1.0f / DIM) + 1e-6f);
    float4 gg = ((const float4*)g)[t];
    uint2 out;
    out.x = h2pack(v.x * rs * gg.x, v.y * rs * gg.y);
    out.y = h2pack(v.z * rs * gg.z, v.w * rs * gg.w);
    orow[t] = out;
}

// ---------------- fp16 GEMM: CTA 128x128, warp 64x32, BK=32 halves, ldmatrix ---------
#define BM 128
#define BN 128
#define BKH 32                      // K per tile (halves)
#define SSTH 40                     // smem row stride (halves): 80B rows, ldsm-clean
#define STAGES 3
#define AWH  (BM * SSTH)            // halves per A stage
#define STGH (2 * AWH)              // halves per stage
#define GSMEM (STAGES * STGH * 2)   // bytes = 61440

struct Batch3 {
    const __half* B[3];
    void*         C[3];
    const float*  R[3];
};

template <bool RESID, bool HOUT>
__global__ __launch_bounds__(256, 2)
void gemm_tc(const __half* __restrict__ A, Batch3 bt, int M, int N, int K) {
    extern __shared__ uint32_t smw[];
    const __half* __restrict__ Bp = bt.B[blockIdx.z];
    const float*  __restrict__ Rp = bt.R[blockIdx.z];

    const int bm = blockIdx.y * BM;
    const int bn = blockIdx.x * BN;
    const int tid  = threadIdx.x;
    const int warp = tid >> 5;
    const int lane = tid & 31;
    const int grp  = lane >> 2;
    const int tig  = lane & 3;
    const int wm = (warp >> 2) * 64;
    const int wn = (warp & 3) * 32;

    const int frow = lane & 15;           // ldmatrix row-within-16
    const int fcol = (lane >> 4) * 8;     // ldmatrix col half-group

    float acc[4][4][4];
    #pragma unroll
    for (int i = 0; i < 4; i++)
        #pragma unroll
        for (int j = 0; j < 4; j++)
            #pragma unroll
            for (int r = 0; r < 4; r++) acc[i][j][r] = 0.0f;

    const int NT = K / BKH;
    const uint32_t smb = smem_u32(smw);

    const int lrow = tid >> 2;            // 0..63 (base row for chunk 0)
    const int loff = (tid & 3) * 8;       // half offset within row

    auto issue = [&](int kt) {
        const int st = kt % STAGES;
        const uint32_t ab = smb + st * STGH * 2;
        const uint32_t bb = ab + AWH * 2;
        const __half* Ag = A  + (size_t)bm * K + kt * BKH;
        const __half* Bg = Bp + (size_t)bn * K + kt * BKH;
        #pragma unroll
        for (int i = 0; i < 2; i++) {
            int row = lrow + i * 64;
            cp16(ab + (row * SSTH + loff) * 2, Ag + (size_t)row * K + loff);
            cp16(bb + (row * SSTH + loff) * 2, Bg + (size_t)row * K + loff);
        }
        asm volatile("cp.async.commit_group;");
    };

    issue(0);
    issue(1);

    for (int kt = 0; kt < NT; kt++) {
        if (kt + 1 < NT) {
            asm volatile("cp.async.wait_group 1;");
        } else {
            asm volatile("cp.async.wait_group 0;");
        }
        __syncthreads();
        if (kt + 2 < NT) issue(kt + 2);

        const int st = kt % STAGES;
        const uint32_t ab = smb + st * STGH * 2;
        const uint32_t bb = ab + AWH * 2;

        #pragma unroll
        for (int ks = 0; ks < 2; ks++) {
            const int kb = ks * 16;
            uint32_t af[4][4], bf[2][4];
            #pragma unroll
            for (int mt = 0; mt < 4; mt++)
                ldsm4(af[mt], ab + (((wm + mt * 16 + frow) * SSTH) + kb + fcol) * 2);
            #pragma unroll
            for (int bk = 0; bk < 2; bk++)
                ldsm4(bf[bk], bb + (((wn + bk * 16 + frow) * SSTH) + kb + fcol) * 2);
            #pragma unroll
            for (int mt = 0; mt < 4; mt++)
                #pragma unroll
                for (int nt = 0; nt < 4; nt++)
                    mma_f16(acc[mt][nt], af[mt],
                            bf[nt >> 1][nt & 1], bf[nt >> 1][(nt & 1) + 2]);
        }
    }

    #pragma unroll
    for (int mt = 0; mt < 4; mt++) {
        const int row = bm + wm + mt * 16 + grp;
        #pragma unroll
        for (int nt = 0; nt < 4; nt++) {
            const int col = bn + wn + nt * 8 + 2 * tig;
            size_t i0 = (size_t)row * N + col;
            size_t i1 = (size_t)(row + 8) * N + col;
            if (HOUT) {
                __half* Cp = (__half*)bt.C[blockIdx.z];
                *(uint32_t*)&Cp[i0] = h2pack(acc[mt][nt][0], acc[mt][nt][1]);
                *(uint32_t*)&Cp[i1] = h2pack(acc[mt][nt][2], acc[mt][nt][3]);
            } else {
                float* Cp = (float*)bt.C[blockIdx.z];
                float2 v0 = make_float2(acc[mt][nt][0], acc[mt][nt][1]);
                float2 v1 = make_float2(acc[mt][nt][2], acc[mt][nt][3]);
                if (RESID) {
                    float2 r0v = *(const float2*)&Rp[i0];
                    float2 r1v = *(const float2*)&Rp[i1];
                    v0.x += r0v.x; v0.y += r0v.y;
                    v1.x += r1v.x; v1.y += r1v.y;
                }
                *(float2*)&Cp[i0] = v0;
                *(float2*)&Cp[i1] = v1;
            }
        }
    }
}

// ---------------- RoPE on half q/k -----------------------------------------------------
__global__ void rope_k(__half* __restrict__ q, __half* __restrict__ k,
                       const float* __restrict__ ct, const float* __restrict__ st) {
    int pos = blockIdx.x;
    int t = threadIdx.x;
    int h = t >> 5;
    int i = t & 31;
    float c = ct[pos * 32 + i];
    float s = st[pos * 32 + i];
    size_t base = (size_t)pos * DIM + h * HD + 2 * i;
    __half2 qh = *(__half2*)&q[base];
    float2 qq = __half22float2(qh);
    *(uint32_t*)&q[base] = h2pack(qq.x * c - qq.y * s, qq.x * s + qq.y * c);
    __half2 kh = *(__half2*)&k[base];
    float2 kk = __half22float2(kh);
    *(uint32_t*)&k[base] = h2pack(kk.x * c - kk.y * s, kk.x * s + kk.y * c);
}

// ---------------- fp16 flash attention: BQ=128 (8 warps), BKV=64, cp.async x2 --------
// K/V/P smem stride 72 halves (144B rows -> ldsm-clean). V B-frags via ldmatrix.trans.
#define BQ   128
#define BKV  64
#define KP2  72
#define KW2  (BKV * KP2)              // halves per K stage
#define AST2 (2 * KW2)                // halves per stage (K+V)
#define PSO2 (2 * AST2)               // Ps offset (halves)
#define ASMEM ((PSO2 + BQ * KP2) * 2) // bytes = 55296

__global__ __launch_bounds__(256, 2)
void flash_attn_tc(const __half* __restrict__ Q, const __half* __restrict__ K,
                   const __half* __restrict__ V, __half* __restrict__ O) {
    extern __shared__ uint32_t smw[];

    const int h  = blockIdx.y;
    const int q0 = blockIdx.x * BQ;
    const int tid  = threadIdx.x;
    const int warp = tid >> 5;
    const int lane = tid & 31;
    const int grp  = lane >> 2;
    const int tig  = lane & 3;
    const int wm   = warp * 16;

    const int frow = lane & 15;
    const int fcol = (lane >> 4) * 8;

    const uint32_t smb = smem_u32(smw);
    const uint32_t psb = smb + PSO2 * 2;

    // Q fragments: packed half2 straight from global (scale folded into softmax)
    uint32_t qf[4][4];
    {
        const __half* qb = Q + (size_t)(q0 + wm) * DIM + h * HD;
        #pragma unroll
        for (int ks = 0; ks < 4; ks++) {
            qf[ks][0] = *(const uint32_t*)&qb[(size_t)grp       * DIM + ks * 16 + 2 * tig];
            qf[ks][1] = *(const uint32_t*)&qb[(size_t)(grp + 8) * DIM + ks * 16 + 2 * tig];
            qf[ks][2] = *(const uint32_t*)&qb[(size_t)grp       * DIM + ks * 16 + 8 + 2 * tig];
            qf[ks][3] = *(const uint32_t*)&qb[(size_t)(grp + 8) * DIM + ks * 16 + 8 + 2 * tig];
        }
    }

    float o[8][4];
    #pragma unroll
    for (int dt = 0; dt < 8; dt++)
        #pragma unroll
        for (int r = 0; r < 4; r++) o[dt][r] = 0.0f;
    float m0 = -1e30f, m1 = -1e30f, l0 = 0.0f, l1 = 0.0f;

    const int NT = SEQ / BKV;
    const int lrow = tid >> 3;            // 0..31
    const int loff = (tid & 7) * 8;       // 0..56 halves

    auto issue = [&](int t) {
        const uint32_t kb = smb + (t & 1) * AST2 * 2;
        const uint32_t vb = kb + KW2 * 2;
        const __half* Kg = K + (size_t)(t * BKV) * DIM + h * HD;
        const __half* Vg = V + (size_t)(t * BKV) * DIM + h * HD;
        #pragma unroll
        for (int i = 0; i < 2; i++) {
            int row = lrow + i * 32;
            cp16(kb + (row * KP2 + loff) * 2, Kg + (size_t)row * DIM + loff);
            cp16(vb + (row * KP2 + loff) * 2, Vg + (size_t)row * DIM + loff);
        }
        asm volatile("cp.async.commit_group;");
    };

    issue(0);

    for (int t = 0; t < NT; t++) {
        if (t + 1 < NT) {
            issue(t + 1);
            asm volatile("cp.async.wait_group 1;");
        } else {
            asm volatile("cp.async.wait_group 0;");
        }
        __syncthreads();

        const uint32_t ksb = smb + (t & 1) * AST2 * 2;
        const uint32_t vsb = ksb + KW2 * 2;

        // S = Q K^T  (scores scaled by 1/8 afterwards, in fp32)
        float sc[8][4];
        #pragma unroll
        for (int nt = 0; nt < 8; nt++)
            #pragma unroll
            for (int r = 0; r < 4; r++) sc[nt][r] = 0.0f;
        #pragma unroll
        for (int ks = 0; ks < 4; ks++) {
            const int kb = ks * 16;
            uint32_t kf[4][4];
            #pragma unroll
            for (int g = 0; g < 4; g++)
                ldsm4(kf[g], ksb + (((g * 16 + frow) * KP2) + kb + fcol) * 2);
            #pragma unroll
            for (int nt = 0; nt < 8; nt++)
                mma_f16(sc[nt], qf[ks],
                        kf[nt >> 1][nt & 1], kf[nt >> 1][(nt & 1) + 2]);
        }
        #pragma unroll
        for (int nt = 0; nt < 8; nt++) {
            sc[nt][0] *= 0.125f; sc[nt][1] *= 0.125f;
            sc[nt][2] *= 0.125f; sc[nt][3] *= 0.125f;
        }

        float mx0 = -1e30f, mx1 = -1e30f;
        #pragma unroll
        for (int nt = 0; nt < 8; nt++) {
            mx0 = fmaxf(mx0, fmaxf(sc[nt][0], sc[nt][1]));
            mx1 = fmaxf(mx1, fmaxf(sc[nt][2], sc[nt][3]));
        }
        mx0 = fmaxf(mx0, __shfl_xor_sync(0xffffffffu, mx0, 1));
        mx0 = fmaxf(mx0, __shfl_xor_sync(0xffffffffu, mx0, 2));
        mx1 = fmaxf(mx1, __shfl_xor_sync(0xffffffffu, mx1, 1));
        mx1 = fmaxf(mx1, __shfl_xor_sync(0xffffffffu, mx1, 2));

        float mn0 = fmaxf(m0, mx0);
        float mn1 = fmaxf(m1, mx1);
        float cr0 = __expf(m0 - mn0);
        float cr1 = __expf(m1 - mn1);
        m0 = mn0; m1 = mn1;

        float s0 = 0.0f, s1 = 0.0f;
        #pragma unroll
        for (int nt = 0; nt < 8; nt++) {
            sc[nt][0] = __expf(sc[nt][0] - mn0);
            sc[nt][1] = __expf(sc[nt][1] - mn0);
            sc[nt][2] = __expf(sc[nt][2] - mn1);
            sc[nt][3] = __expf(sc[nt][3] - mn1);
            s0 += sc[nt][0] + sc[nt][1];
            s1 += sc[nt][2] + sc[nt][3];
        }
        s0 += __shfl_xor_sync(0xffffffffu, s0, 1);
        s0 += __shfl_xor_sync(0xffffffffu, s0, 2);
        s1 += __shfl_xor_sync(0xffffffffu, s1, 1);
        s1 += __shfl_xor_sync(0xffffffffu, s1, 2);
        l0 = l0 * cr0 + s0;
        l1 = l1 * cr1 + s1;

        #pragma unroll
        for (int dt = 0; dt < 8; dt++) {
            o[dt][0] *= cr0; o[dt][1] *= cr0;
            o[dt][2] *= cr1; o[dt][3] *= cr1;
        }

        // P -> smem (half2), per-warp private rows
        #pragma unroll
        for (int nt = 0; nt < 8; nt++) {
            *(uint32_t*)((char*)smw + (PSO2 + (wm + grp    ) * KP2 + nt * 8 + 2 * tig) * 2)
                = h2pack(sc[nt][0], sc[nt][1]);
            *(uint32_t*)((char*)smw + (PSO2 + (wm + grp + 8) * KP2 + nt * 8 + 2 * tig) * 2)
                = h2pack(sc[nt][2], sc[nt][3]);
        }
        __syncwarp();

        // O += P V   (V B-frags via ldmatrix.trans)
        #pragma unroll
        for (int ks = 0; ks < 4; ks++) {
            const int kb = ks * 16;
            uint32_t pa[4], vf[4][4];
            ldsm4(pa, psb + (((wm + frow) * KP2) + kb + fcol) * 2);
            #pragma unroll
            for (int db = 0; db < 4; db++)
                ldsm4t(vf[db], vsb + (((kb + frow) * KP2) + db * 16 + fcol) * 2);
            #pragma unroll
            for (int dt = 0; dt < 8; dt++)
                mma_f16(o[dt], pa,
                        vf[dt >> 1][(dt & 1) * 2], vf[dt >> 1][(dt & 1) * 2 + 1]);
        }
        __syncthreads();
    }

    float il0 = 1.0f / l0;
    float il1 = 1.0f / l1;
    #pragma unroll
    for (int dt = 0; dt < 8; dt++) {
        size_t i0 = (size_t)(q0 + wm + grp    ) * DIM + h * HD + dt * 8 + 2 * tig;
        size_t i1 = (size_t)(q0 + wm + grp + 8) * DIM + h * HD + dt * 8 + 2 * tig;
        *(uint32_t*)&O[i0] = h2pack(o[dt][0] * il0, o[dt][1] * il0);
        *(uint32_t*)&O[i1] = h2pack(o[dt][2] * il1, o[dt][3] * il1);
    }
}

// ---------------- SwiGLU elementwise (half) -------------------------------------------
__global__ void silu_mul_k(__half* __restrict__ a, const __half* __restrict__ b, int n4) {
    int i = blockIdx.x * blockDim.x + threadIdx.x;
    if (i < n4) {
        uint2 ua = ((uint2*)a)[i];
        uint2 ub = ((const uint2*)b)[i];
        float2 x0 = __half22float2(*(__half2*)&ua.x);
        float2 x1 = __half22float2(*(__half2*)&ua.y);
        float2 y0 = __half22float2(*(__half2*)&ub.x);
        float2 y1 = __half22float2(*(__half2*)&ub.y);
        uint2 o;
        o.x = h2pack(x0.x / (1.0f + __expf(-x0.x)) * y0.x,
                     x0.y / (1.0f + __expf(-x0.y)) * y0.y);
        o.y = h2pack(x1.x / (1.0f + __expf(-x1.x)) * y1.x,
                     x1.y / (1.0f + __expf(-x1.y)) * y1.y);
        ((uint2*)a)[i] = o;
    }
}

// ---------------- launch --------------------------------------------------------------
extern "C" void kernel_launch(void* const* d_in, const int* in_sizes, int n_in,
                              void* d_out, int out_size) {
    const float* x  = (const float*)d_in[0];
    const float* wq = (const float*)d_in[1];
    const float* wk = (const float*)d_in[2];
    const float* wv = (const float*)d_in[3];
    const float* wo = (const float*)d_in[4];
    const float* w1 = (const float*)d_in[5];
    const float* w2 = (const float*)d_in[6];
    const float* w3 = (const float*)d_in[7];
    const float* ga = (const float*)d_in[8];
    const float* gf = (const float*)d_in[9];
    float* out = (float*)d_out;

    __half *xn, *q, *k, *v, *at, *hn, *t1, *t3, *wt;
    float *ct, *st;
    cudaGetSymbolAddress((void**)&xn, g_xn);
    cudaGetSymbolAddress((void**)&q,  g_q);
    cudaGetSymbolAddress((void**)&k,  g_k);
    cudaGetSymbolAddress((void**)&v,  g_v);
    cudaGetSymbolAddress((void**)&at, g_at);
    cudaGetSymbolAddress((void**)&hn, g_hn);
    cudaGetSymbolAddress((void**)&t1, g_t1);
    cudaGetSymbolAddress((void**)&t3, g_t3);
    cudaGetSymbolAddress((void**)&ct, g_cos);
    cudaGetSymbolAddress((void**)&st, g_sin);
    cudaGetSymbolAddress((void**)&wt, g_wt);

    cudaFuncSetAttribute(gemm_tc<false, true>,  cudaFuncAttributeMaxDynamicSharedMemorySize, GSMEM);
    cudaFuncSetAttribute(gemm_tc<true,  false>, cudaFuncAttributeMaxDynamicSharedMemorySize, GSMEM);
    cudaFuncSetAttribute(flash_attn_tc, cudaFuncAttributeMaxDynamicSharedMemorySize, ASMEM);

    // all weights -> fp16 (one z-batched launch)
    {
        CvtBatch cb;
        cb.src[0] = wq; cb.off[0] = WQO; cb.n4[0] = DIM * DIM / 4;
        cb.src[1] = wk; cb.off[1] = WKO; cb.n4[1] = DIM * DIM / 4;
        cb.src[2] = wv; cb.off[2] = WVO; cb.n4[2] = DIM * DIM / 4;
        cb.src[3] = wo; cb.off[3] = WOO; cb.n4[3] = DIM * DIM / 4;
        cb.src[4] = w1; cb.off[4] = W1O; cb.n4[4] = HIDDEN * DIM / 4;
        cb.src[5] = w3; cb.off[5] = W3O; cb.n4[5] = HIDDEN * DIM / 4;
        cb.src[6] = w2; cb.off[6] = W2O; cb.n4[6] = DIM * HIDDEN / 4;
        cvt_all_k<<<dim3(256, 1, 7), 256>>>(cb, wt);
    }

    rope_tables_k<<<(SEQ * 32) / 256, 256>>>(ct, st);
    rmsnorm_k<<<SEQ, 256>>>(x, ga, xn);

    // QKV batched (z = 3), half out
    {
        Batch3 bt;
        bt.B[0] = wt + WQO; bt.B[1] = wt + WKO; bt.B[2] = wt + WVO;
        bt.C[0] = q; bt.C[1] = k; bt.C[2] = v;
        bt.R[0] = bt.R[1] = bt.R[2] = nullptr;
        gemm_tc<false, true><<<dim3(DIM / BN, SEQ / BM, 3), 256, GSMEM>>>(xn, bt, SEQ, DIM, DIM);
    }

    rope_k<<<SEQ, 512>>>(q, k, ct, st);
    flash_attn_tc<<<dim3(SEQ / BQ, NH), 256, ASMEM>>>(q, k, v, at);

    // Wo + residual -> out (float)
    {
        Batch3 bt;
        bt.B[0] = wt + WOO; bt.C[0] = out; bt.R[0] = x;
        bt.B[1] = bt.B[2] = nullptr; bt.C[1] = bt.C[2] = nullptr; bt.R[1] = bt.R[2] = nullptr;
        gemm_tc<true, false><<<dim3(DIM / BN, SEQ / BM, 1), 256, GSMEM>>>(at, bt, SEQ, DIM, DIM);
    }

    rmsnorm_k<<<SEQ, 256>>>(out, gf, hn);

    // w1 / w3 batched (z = 2), half out
    {
        Batch3 bt;
        bt.B[0] = wt + W1O; bt.B[1] = wt + W3O; bt.B[2] = nullptr;
        bt.C[0] = t1; bt.C[1] = t3; bt.C[2] = nullptr;
        bt.R[0] = bt.R[1] = bt.R[2] = nullptr;
        gemm_tc<false, true><<<dim3(HIDDEN / BN, SEQ / BM, 2), 256, GSMEM>>>(hn, bt, SEQ, HIDDEN, DIM);
    }

    silu_mul_k<<<(SEQ * HIDDEN / 4 + 255) / 256, 256>>>(t1, t3, SEQ * HIDDEN / 4);

    // W2 + residual -> out (float, in-place residual)
    {
        Batch3 bt;
        bt.B[0] = wt + W2O; bt.C[0] = out; bt.R[0] = out;
        bt.B[1] = bt.B[2] = nullptr; bt.C[1] = bt.C[2] = nullptr; bt.R[1] = bt.R[2] = nullptr;
        gemm_tc<true, false><<<dim3(DIM / BN, SEQ / BM, 1), 256, GSMEM>>>(t1, bt, SEQ, DIM, HIDDEN);
    }
}

// round 13
// speedup vs baseline: 1.7412x; 1.0114x over previous
#include <cuda_runtime.h>
#include <cuda_fp16.h>
#include <math.h>
#include <stdint.h>

#define SEQ    4096
#define DIM    1024
#define NH     16
#define HD     64
#define HIDDEN 4096

// ---------------- scratch (fp16 activations/weights) ---------------------------------
__device__ __half g_xn[SEQ * DIM];
__device__ __half g_q [SEQ * DIM];
__device__ __half g_k [SEQ * DIM];
__device__ __half g_v [SEQ * DIM];
__device__ __half g_at[SEQ * DIM];
__device__ __half g_hn[SEQ * DIM];
__device__ __half g_t1[SEQ * HIDDEN];
__device__ __half g_t3[SEQ * HIDDEN];
__device__ float  g_cos[SEQ * (HD / 2)];
__device__ float  g_sin[SEQ * (HD / 2)];
__device__ __half g_wt[16777216];          // fp16 weights (32MB)

#define WQO 0
#define WKO 1048576
#define WVO 2097152
#define WOO 3145728
#define W1O 4194304
#define W3O 8388608
#define W2O 12582912

__device__ __forceinline__ uint32_t h2pack(float a, float b) {
    __half2 h = __floats2half2_rn(a, b);
    return *reinterpret_cast<uint32_t*>(&h);
}

__device__ __forceinline__ void mma_f16(float* c, const uint32_t* a, uint32_t b0, uint32_t b1) {
    asm volatile(
        "mma.sync.aligned.m16n8k16.row.col.f32.f16.f16.f32 "
        "{%0,%1,%2,%3}, {%4,%5,%6,%7}, {%8,%9}, {%0,%1,%2,%3};\n"
        : "+f"(c[0]), "+f"(c[1]), "+f"(c[2]), "+f"(c[3])
        : "r"(a[0]), "r"(a[1]), "r"(a[2]), "r"(a[3]), "r"(b0), "r"(b1));
}

__device__ __forceinline__ void ldsm4(uint32_t* r, uint32_t saddr) {
    asm volatile("ldmatrix.sync.aligned.m8n8.x4.shared.b16 {%0,%1,%2,%3}, [%4];"
        : "=r"(r[0]), "=r"(r[1]), "=r"(r[2]), "=r"(r[3]) : "r"(saddr));
}

__device__ __forceinline__ void ldsm4t(uint32_t* r, uint32_t saddr) {
    asm volatile("ldmatrix.sync.aligned.m8n8.x4.trans.shared.b16 {%0,%1,%2,%3}, [%4];"
        : "=r"(r[0]), "=r"(r[1]), "=r"(r[2]), "=r"(r[3]) : "r"(saddr));
}

__device__ __forceinline__ void cp16(uint32_t saddr, const void* gptr) {
    asm volatile("cp.async.cg.shared.global [%0], [%1], 16;" :: "r"(saddr), "l"(gptr));
}

__device__ __forceinline__ uint32_t smem_u32(const void* p) {
    uint32_t a;
    asm("{ .reg .u64 t; cvta.to.shared.u64 t, %1; cvt.u32.u64 %0, t; }" : "=r"(a) : "l"(p));
    return a;
}

// ---------------- weight fp16 convert (single z-batched launch) ----------------------
struct CvtBatch {
    const float* src[7];
    int off[7];
    int n4[7];
};

__global__ void cvt_all_k(CvtBatch cb, __half* __restrict__ wt) {
    const float* src = cb.src[blockIdx.z];
    __half* dst = wt + cb.off[blockIdx.z];
    int n4 = cb.n4[blockIdx.z];
    int stride = gridDim.x * blockDim.x;
    for (int i = blockIdx.x * blockDim.x + threadIdx.x; i < n4; i += stride) {
        float4 v = ((const float4*)src)[i];
        uint2 o;
        o.x = h2pack(v.x, v.y);
        o.y = h2pack(v.z, v.w);
        ((uint2*)dst)[i] = o;
    }
}

// ---------------- RoPE tables in double precision ------------------------------------
__global__ void rope_tables_k(float* __restrict__ c, float* __restrict__ s) {
    int idx = blockIdx.x * blockDim.x + threadIdx.x;
    int pos = idx >> 5;
    int i   = idx & 31;
    double inv = exp(-((double)(2 * i) / (double)HD) * log(10000.0));
    double ang = (double)pos * inv;
    double cs, sn;
    sincos(ang, &sn, &cs);
    c[idx] = (float)cs;
    s[idx] = (float)sn;
}

// ---------------- RMSNorm: float in -> half out ---------------------------------------
__global__ void rmsnorm_k(const float* __restrict__ x, const float* __restrict__ g,
                          __half* __restrict__ o) {
    int row = blockIdx.x;
    const float4* xr = (const float4*)(x + (size_t)row * DIM);
    uint2* orow = (uint2*)(o + (size_t)row * DIM);
    int t = threadIdx.x;
    float4 v = xr[t];
    float ss = v.x * v.x + v.y * v.y + v.z * v.z + v.w * v.w;
    #pragma unroll
    for (int off = 16; off; off >>= 1) ss += __shfl_xor_sync(0xffffffffu, ss, off);
    __shared__ float sp[8];
    if ((t & 31) == 0) sp[t >> 5] = ss;
    __syncthreads();
    if (t < 8) {
        float s2 = sp[t];
        #pragma unroll
        for (int off = 4; off; off >>= 1) s2 += __shfl_xor_sync(0xffu, s2, off);
        if (t == 0) sp[0] = s2;
    }
    __syncthreads();
    float rs = rsqrtf(sp[0] * (1.0f / DIM) + 1e-6f);
    float4 gg = ((const float4*)g)[t];
    uint2 out;
    out.x = h2pack(v.x * rs * gg.x, v.y * rs * gg.y);
    out.y = h2pack(v.z * rs * gg.z, v.w * rs * gg.w);
    orow[t] = out;
}

// ---------------- fp16 GEMM: CTA 128x128, warp 64x32, 4-stage cp.async ---------------
#define BM 128
#define BN 128
#define BKH 32                      // K per tile (halves)
#define SSTH 40                     // smem row stride (halves): 80B rows, ldsm-clean
#define STAGES 4
#define AWH  (BM * SSTH)            // halves per A stage
#define STGH (2 * AWH)              // halves per stage
#define GSMEM (STAGES * STGH * 2)   // bytes = 81920

struct Batch3 {
    const __half* B[3];
    void*         C[3];
    const float*  R[3];
};

template <bool RESID, bool HOUT>
__global__ __launch_bounds__(256, 2)
void gemm_tc(const __half* __restrict__ A, Batch3 bt, int M, int N, int K) {
    extern __shared__ uint32_t smw[];
    const __half* __restrict__ Bp = bt.B[blockIdx.z];
    const float*  __restrict__ Rp = bt.R[blockIdx.z];

    const int bm = blockIdx.y * BM;
    const int bn = blockIdx.x * BN;
    const int tid  = threadIdx.x;
    const int warp = tid >> 5;
    const int lane = tid & 31;
    const int grp  = lane >> 2;
    const int tig  = lane & 3;
    const int wm = (warp >> 2) * 64;
    const int wn = (warp & 3) * 32;

    const int frow = lane & 15;
    const int fcol = (lane >> 4) * 8;

    float acc[4][4][4];
    #pragma unroll
    for (int i = 0; i < 4; i++)
        #pragma unroll
        for (int j = 0; j < 4; j++)
            #pragma unroll
            for (int r = 0; r < 4; r++) acc[i][j][r] = 0.0f;

    const int NT = K / BKH;
    const uint32_t smb = smem_u32(smw);

    const int lrow = tid >> 2;
    const int loff = (tid & 3) * 8;

    auto issue = [&](int kt) {
        const int st = kt % STAGES;
        const uint32_t ab = smb + st * STGH * 2;
        const uint32_t bb = ab + AWH * 2;
        const __half* Ag = A  + (size_t)bm * K + kt * BKH;
        const __half* Bg = Bp + (size_t)bn * K + kt * BKH;
        #pragma unroll
        for (int i = 0; i < 2; i++) {
            int row = lrow + i * 64;
            cp16(ab + (row * SSTH + loff) * 2, Ag + (size_t)row * K + loff);
            cp16(bb + (row * SSTH + loff) * 2, Bg + (size_t)row * K + loff);
        }
        asm volatile("cp.async.commit_group;");
    };

    issue(0);
    issue(1);
    issue(2);

    for (int kt = 0; kt < NT; kt++) {
        const int rem = NT - 1 - kt;
        if (rem >= 2) {
            asm volatile("cp.async.wait_group 2;");
        } else if (rem == 1) {
            asm volatile("cp.async.wait_group 1;");
        } else {
            asm volatile("cp.async.wait_group 0;");
        }
        __syncthreads();
        if (kt + 3 < NT) issue(kt + 3);

        const int st = kt % STAGES;
        const uint32_t ab = smb + st * STGH * 2;
        const uint32_t bb = ab + AWH * 2;

        #pragma unroll
        for (int ks = 0; ks < 2; ks++) {
            const int kb = ks * 16;
            uint32_t af[4][4], bf[2][4];
            #pragma unroll
            for (int mt = 0; mt < 4; mt++)
                ldsm4(af[mt], ab + (((wm + mt * 16 + frow) * SSTH) + kb + fcol) * 2);
            #pragma unroll
            for (int bk = 0; bk < 2; bk++)
                ldsm4(bf[bk], bb + (((wn + bk * 16 + frow) * SSTH) + kb + fcol) * 2);
            #pragma unroll
            for (int mt = 0; mt < 4; mt++)
                #pragma unroll
                for (int nt = 0; nt < 4; nt++)
                    mma_f16(acc[mt][nt], af[mt],
                            bf[nt >> 1][nt & 1], bf[nt >> 1][(nt & 1) + 2]);
        }
    }

    #pragma unroll
    for (int mt = 0; mt < 4; mt++) {
        const int row = bm + wm + mt * 16 + grp;
        #pragma unroll
        for (int nt = 0; nt < 4; nt++) {
            const int col = bn + wn + nt * 8 + 2 * tig;
            size_t i0 = (size_t)row * N + col;
            size_t i1 = (size_t)(row + 8) * N + col;
            if (HOUT) {
                __half* Cp = (__half*)bt.C[blockIdx.z];
                *(uint32_t*)&Cp[i0] = h2pack(acc[mt][nt][0], acc[mt][nt][1]);
                *(uint32_t*)&Cp[i1] = h2pack(acc[mt][nt][2], acc[mt][nt][3]);
            } else {
                float* Cp = (float*)bt.C[blockIdx.z];
                float2 v0 = make_float2(acc[mt][nt][0], acc[mt][nt][1]);
                float2 v1 = make_float2(acc[mt][nt][2], acc[mt][nt][3]);
                if (RESID) {
                    float2 r0v = *(const float2*)&Rp[i0];
                    float2 r1v = *(const float2*)&Rp[i1];
                    v0.x += r0v.x; v0.y += r0v.y;
                    v1.x += r1v.x; v1.y += r1v.y;
                }
                *(float2*)&Cp[i0] = v0;
                *(float2*)&Cp[i1] = v1;
            }
        }
    }
}

// ---------------- RoPE on half q/k -----------------------------------------------------
__global__ void rope_k(__half* __restrict__ q, __half* __restrict__ k,
                       const float* __restrict__ ct, const float* __restrict__ st) {
    int pos = blockIdx.x;
    int t = threadIdx.x;
    int h = t >> 5;
    int i = t & 31;
    float c = ct[pos * 32 + i];
    float s = st[pos * 32 + i];
    size_t base = (size_t)pos * DIM + h * HD + 2 * i;
    __half2 qh = *(__half2*)&q[base];
    float2 qq = __half22float2(qh);
    *(uint32_t*)&q[base] = h2pack(qq.x * c - qq.y * s, qq.x * s + qq.y * c);
    __half2 kh = *(__half2*)&k[base];
    float2 kk = __half22float2(kh);
    *(uint32_t*)&k[base] = h2pack(kk.x * c - kk.y * s, kk.x * s + kk.y * c);
}

// ---------------- fp16 flash attention: BQ=128, stage BKV=128 (2x64 halves) ----------
#define BQ   128
#define BKV  128
#define KP2  72
#define KW2  (BKV * KP2)              // halves per K stage (128 rows)
#define AST2 (2 * KW2)                // halves per stage (K+V)
#define PSO2 (2 * AST2)               // Ps offset (halves)
#define ASMEM ((PSO2 + BQ * KP2) * 2) // bytes = 92160

__global__ __launch_bounds__(256, 2)
void flash_attn_tc(const __half* __restrict__ Q, const __half* __restrict__ K,
                   const __half* __restrict__ V, __half* __restrict__ O) {
    extern __shared__ uint32_t smw[];

    const int h  = blockIdx.y;
    const int q0 = blockIdx.x * BQ;
    const int tid  = threadIdx.x;
    const int warp = tid >> 5;
    const int lane = tid & 31;
    const int grp  = lane >> 2;
    const int tig  = lane & 3;
    const int wm   = warp * 16;

    const int frow = lane & 15;
    const int fcol = (lane >> 4) * 8;

    const uint32_t smb = smem_u32(smw);
    const uint32_t psb = smb + PSO2 * 2;

    uint32_t qf[4][4];
    {
        const __half* qb = Q + (size_t)(q0 + wm) * DIM + h * HD;
        #pragma unroll
        for (int ks = 0; ks < 4; ks++) {
            qf[ks][0] = *(const uint32_t*)&qb[(size_t)grp       * DIM + ks * 16 + 2 * tig];
            qf[ks][1] = *(const uint32_t*)&qb[(size_t)(grp + 8) * DIM + ks * 16 + 2 * tig];
            qf[ks][2] = *(const uint32_t*)&qb[(size_t)grp       * DIM + ks * 16 + 8 + 2 * tig];
            qf[ks][3] = *(const uint32_t*)&qb[(size_t)(grp + 8) * DIM + ks * 16 + 8 + 2 * tig];
        }
    }

    float o[8][4];
    #pragma unroll
    for (int dt = 0; dt < 8; dt++)
        #pragma unroll
        for (int r = 0; r < 4; r++) o[dt][r] = 0.0f;
    float m0 = -1e30f, m1 = -1e30f, l0 = 0.0f, l1 = 0.0f;

    const int NT = SEQ / BKV;            // 32 stages of 128 rows
    const int lrow = tid >> 3;           // 0..31
    const int loff = (tid & 7) * 8;      // 0..56 halves

    auto issue = [&](int t) {
        const uint32_t kb = smb + (t & 1) * AST2 * 2;
        const uint32_t vb = kb + KW2 * 2;
        const __half* Kg = K + (size_t)(t * BKV) * DIM + h * HD;
        const __half* Vg = V + (size_t)(t * BKV) * DIM + h * HD;
        #pragma unroll
        for (int i = 0; i < 4; i++) {
            int row = lrow + i * 32;
            cp16(kb + (row * KP2 + loff) * 2, Kg + (size_t)row * DIM + loff);
            cp16(vb + (row * KP2 + loff) * 2, Vg + (size_t)row * DIM + loff);
        }
        asm volatile("cp.async.commit_group;");
    };

    issue(0);

    for (int t = 0; t < NT; t++) {
        if (t + 1 < NT) {
            issue(t + 1);
            asm volatile("cp.async.wait_group 1;");
        } else {
            asm volatile("cp.async.wait_group 0;");
        }
        __syncthreads();

        #pragma unroll
        for (int half = 0; half < 2; half++) {
            const uint32_t ksb = smb + (t & 1) * AST2 * 2 + half * (64 * KP2) * 2;
            const uint32_t vsb = smb + ((t & 1) * AST2 + KW2 + half * (64 * KP2)) * 2;

            // S = Q K^T over this 64-row half
            float sc[8][4];
            #pragma unroll
            for (int nt = 0; nt < 8; nt++)
                #pragma unroll
                for (int r = 0; r < 4; r++) sc[nt][r] = 0.0f;
            #pragma unroll
            for (int ks = 0; ks < 4; ks++) {
                const int kb = ks * 16;
                uint32_t kf[4][4];
                #pragma unroll
                for (int g = 0; g < 4; g++)
                    ldsm4(kf[g], ksb + (((g * 16 + frow) * KP2) + kb + fcol) * 2);
                #pragma unroll
                for (int nt = 0; nt < 8; nt++)
                    mma_f16(sc[nt], qf[ks],
                            kf[nt >> 1][nt & 1], kf[nt >> 1][(nt & 1) + 2]);
            }
            #pragma unroll
            for (int nt = 0; nt < 8; nt++) {
                sc[nt][0] *= 0.125f; sc[nt][1] *= 0.125f;
                sc[nt][2] *= 0.125f; sc[nt][3] *= 0.125f;
            }

            float mx0 = -1e30f, mx1 = -1e30f;
            #pragma unroll
            for (int nt = 0; nt < 8; nt++) {
                mx0 = fmaxf(mx0, fmaxf(sc[nt][0], sc[nt][1]));
                mx1 = fmaxf(mx1, fmaxf(sc[nt][2], sc[nt][3]));
            }
            mx0 = fmaxf(mx0, __shfl_xor_sync(0xffffffffu, mx0, 1));
            mx0 = fmaxf(mx0, __shfl_xor_sync(0xffffffffu, mx0, 2));
            mx1 = fmaxf(mx1, __shfl_xor_sync(0xffffffffu, mx1, 1));
            mx1 = fmaxf(mx1, __shfl_xor_sync(0xffffffffu, mx1, 2));

            float mn0 = fmaxf(m0, mx0);
            float mn1 = fmaxf(m1, mx1);
            float cr0 = __expf(m0 - mn0);
            float cr1 = __expf(m1 - mn1);
            m0 = mn0; m1 = mn1;

            float s0 = 0.0f, s1 = 0.0f;
            #pragma unroll
            for (int nt = 0; nt < 8; nt++) {
                sc[nt][0] = __expf(sc[nt][0] - mn0);
                sc[nt][1] = __expf(sc[nt][1] - mn0);
                sc[nt][2] = __expf(sc[nt][2] - mn1);
                sc[nt][3] = __expf(sc[nt][3] - mn1);
                s0 += sc[nt][0] + sc[nt][1];
                s1 += sc[nt][2] + sc[nt][3];
            }
            s0 += __shfl_xor_sync(0xffffffffu, s0, 1);
            s0 += __shfl_xor_sync(0xffffffffu, s0, 2);
            s1 += __shfl_xor_sync(0xffffffffu, s1, 1);
            s1 += __shfl_xor_sync(0xffffffffu, s1, 2);
            l0 = l0 * cr0 + s0;
            l1 = l1 * cr1 + s1;

            #pragma unroll
            for (int dt = 0; dt < 8; dt++) {
                o[dt][0] *= cr0; o[dt][1] *= cr0;
                o[dt][2] *= cr1; o[dt][3] *= cr1;
            }

            // P -> smem (half2), per-warp private rows
            #pragma unroll
            for (int nt = 0; nt < 8; nt++) {
                *(uint32_t*)((char*)smw + (PSO2 + (wm + grp    ) * KP2 + nt * 8 + 2 * tig) * 2)
                    = h2pack(sc[nt][0], sc[nt][1]);
                *(uint32_t*)((char*)smw + (PSO2 + (wm + grp + 8) * KP2 + nt * 8 + 2 * tig) * 2)
                    = h2pack(sc[nt][2], sc[nt][3]);
            }
            __syncwarp();

            // O += P V
            #pragma unroll
            for (int ks = 0; ks < 4; ks++) {
                const int kb = ks * 16;
                uint32_t pa[4], vf[4][4];
                ldsm4(pa, psb + (((wm + frow) * KP2) + kb + fcol) * 2);
                #pragma unroll
                for (int db = 0; db < 4; db++)
                    ldsm4t(vf[db], vsb + (((kb + frow) * KP2) + db * 16 + fcol) * 2);
                #pragma unroll
                for (int dt = 0; dt < 8; dt++)
                    mma_f16(o[dt], pa,
                            vf[dt >> 1][(dt & 1) * 2], vf[dt >> 1][(dt & 1) * 2 + 1]);
            }
            __syncwarp();
        }
        __syncthreads();
    }

    float il0 = 1.0f / l0;
    float il1 = 1.0f / l1;
    #pragma unroll
    for (int dt = 0; dt < 8; dt++) {
        size_t i0 = (size_t)(q0 + wm + grp    ) * DIM + h * HD + dt * 8 + 2 * tig;
        size_t i1 = (size_t)(q0 + wm + grp + 8) * DIM + h * HD + dt * 8 + 2 * tig;
        *(uint32_t*)&O[i0] = h2pack(o[dt][0] * il0, o[dt][1] * il0);
        *(uint32_t*)&O[i1] = h2pack(o[dt][2] * il1, o[dt][3] * il1);
    }
}

// ---------------- SwiGLU elementwise (half) -------------------------------------------
__global__ void silu_mul_k(__half* __restrict__ a, const __half* __restrict__ b, int n4) {
    int i = blockIdx.x * blockDim.x + threadIdx.x;
    if (i < n4) {
        uint2 ua = ((uint2*)a)[i];
        uint2 ub = ((const uint2*)b)[i];
        float2 x0 = __half22float2(*(__half2*)&ua.x);
        float2 x1 = __half22float2(*(__half2*)&ua.y);
        float2 y0 = __half22float2(*(__half2*)&ub.x);
        float2 y1 = __half22float2(*(__half2*)&ub.y);
        uint2 o;
        o.x = h2pack(x0.x / (1.0f + __expf(-x0.x)) * y0.x,
                     x0.y / (1.0f + __expf(-x0.y)) * y0.y);
        o.y = h2pack(x1.x / (1.0f + __expf(-x1.x)) * y1.x,
                     x1.y / (1.0f + __expf(-x1.y)) * y1.y);
        ((uint2*)a)[i] = o;
    }
}

// ---------------- launch --------------------------------------------------------------
extern "C" void kernel_launch(void* const* d_in, const int* in_sizes, int n_in,
                              void* d_out, int out_size) {
    const float* x  = (const float*)d_in[0];
    const float* wq = (const float*)d_in[1];
    const float* wk = (const float*)d_in[2];
    const float* wv = (const float*)d_in[3];
    const float* wo = (const float*)d_in[4];
    const float* w1 = (const float*)d_in[5];
    const float* w2 = (const float*)d_in[6];
    const float* w3 = (const float*)d_in[7];
    const float* ga = (const float*)d_in[8];
    const float* gf = (const float*)d_in[9];
    float* out = (float*)d_out;

    __half *xn, *q, *k, *v, *at, *hn, *t1, *t3, *wt;
    float *ct, *st;
    cudaGetSymbolAddress((void**)&xn, g_xn);
    cudaGetSymbolAddress((void**)&q,  g_q);
    cudaGetSymbolAddress((void**)&k,  g_k);
    cudaGetSymbolAddress((void**)&v,  g_v);
    cudaGetSymbolAddress((void**)&at, g_at);
    cudaGetSymbolAddress((void**)&hn, g_hn);
    cudaGetSymbolAddress((void**)&t1, g_t1);
    cudaGetSymbolAddress((void**)&t3, g_t3);
    cudaGetSymbolAddress((void**)&ct, g_cos);
    cudaGetSymbolAddress((void**)&st, g_sin);
    cudaGetSymbolAddress((void**)&wt, g_wt);

    cudaFuncSetAttribute(gemm_tc<false, true>,  cudaFuncAttributeMaxDynamicSharedMemorySize, GSMEM);
    cudaFuncSetAttribute(gemm_tc<true,  false>, cudaFuncAttributeMaxDynamicSharedMemorySize, GSMEM);
    cudaFuncSetAttribute(flash_attn_tc, cudaFuncAttributeMaxDynamicSharedMemorySize, ASMEM);

    // all weights -> fp16 (one z-batched launch)
    {
        CvtBatch cb;
        cb.src[0] = wq; cb.off[0] = WQO; cb.n4[0] = DIM * DIM / 4;
        cb.src[1] = wk; cb.off[1] = WKO; cb.n4[1] = DIM * DIM / 4;
        cb.src[2] = wv; cb.off[2] = WVO; cb.n4[2] = DIM * DIM / 4;
        cb.src[3] = wo; cb.off[3] = WOO; cb.n4[3] = DIM * DIM / 4;
        cb.src[4] = w1; cb.off[4] = W1O; cb.n4[4] = HIDDEN * DIM / 4;
        cb.src[5] = w3; cb.off[5] = W3O; cb.n4[5] = HIDDEN * DIM / 4;
        cb.src[6] = w2; cb.off[6] = W2O; cb.n4[6] = DIM * HIDDEN / 4;
        cvt_all_k<<<dim3(256, 1, 7), 256>>>(cb, wt);
    }

    rope_tables_k<<<(SEQ * 32) / 256, 256>>>(ct, st);
    rmsnorm_k<<<SEQ, 256>>>(x, ga, xn);

    // QKV batched (z = 3), half out
    {
        Batch3 bt;
        bt.B[0] = wt + WQO; bt.B[1] = wt + WKO; bt.B[2] = wt + WVO;
        bt.C[0] = q; bt.C[1] = k; bt.C[2] = v;
        bt.R[0] = bt.R[1] = bt.R[2] = nullptr;
        gemm_tc<false, true><<<dim3(DIM / BN, SEQ / BM, 3), 256, GSMEM>>>(xn, bt, SEQ, DIM, DIM);
    }

    rope_k<<<SEQ, 512>>>(q, k, ct, st);
    flash_attn_tc<<<dim3(SEQ / BQ, NH), 256, ASMEM>>>(q, k, v, at);

    // Wo + residual -> out (float)
    {
        Batch3 bt;
        bt.B[0] = wt + WOO; bt.C[0] = out; bt.R[0] = x;
        bt.B[1] = bt.B[2] = nullptr; bt.C[1] = bt.C[2] = nullptr; bt.R[1] = bt.R[2] = nullptr;
        gemm_tc<true, false><<<dim3(DIM / BN, SEQ / BM, 1), 256, GSMEM>>>(at, bt, SEQ, DIM, DIM);
    }

    rmsnorm_k<<<SEQ, 256>>>(out, gf, hn);

    // w1 / w3 batched (z = 2), half out
    {
        Batch3 bt;
        bt.B[0] = wt + W1O; bt.B[1] = wt + W3O; bt.B[2] = nullptr;
        bt.C[0] = t1; bt.C[1] = t3; bt.C[2] = nullptr;
        bt.R[0] = bt.R[1] = bt.R[2] = nullptr;
        gemm_tc<false, true><<<dim3(HIDDEN / BN, SEQ / BM, 2), 256, GSMEM>>>(hn, bt, SEQ, HIDDEN, DIM);
    }

    silu_mul_k<<<(SEQ * HIDDEN / 4 + 255) / 256, 256>>>(t1, t3, SEQ * HIDDEN / 4);

    // W2 + residual -> out (float, in-place residual)
    {
        Batch3 bt;
        bt.B[0] = wt + W2O; bt.C[0] = out; bt.R[0] = out;
        bt.B[1] = bt.B[2] = nullptr; bt.C[1] = bt.C[2] = nullptr; bt.R[1] = bt.R[2] = nullptr;
        gemm_tc<true, false><<<dim3(DIM / BN, SEQ / BM, 1), 256, GSMEM>>>(t1, bt, SEQ, DIM, HIDDEN);
    }
}

// round 14
// speedup vs baseline: 1.7553x; 1.0081x over previous
#include <cuda_runtime.h>
#include <cuda_fp16.h>
#include <math.h>
#include <stdint.h>

#define SEQ    4096
#define DIM    1024
#define NH     16
#define HD     64
#define HIDDEN 4096

// ---------------- scratch (fp16 activations/weights) ---------------------------------
__device__ __half g_xn[SEQ * DIM];
__device__ __half g_q [SEQ * DIM];
__device__ __half g_k [SEQ * DIM];
__device__ __half g_v [SEQ * DIM];
__device__ __half g_at[SEQ * DIM];
__device__ __half g_hn[SEQ * DIM];
__device__ __half g_t1[SEQ * HIDDEN];
__device__ __half g_t3[SEQ * HIDDEN];
__device__ float  g_cos[SEQ * (HD / 2)];
__device__ float  g_sin[SEQ * (HD / 2)];
__device__ __half g_wt[16777216];          // fp16 weights (32MB)

#define WQO 0
#define WKO 1048576
#define WVO 2097152
#define WOO 3145728
#define W1O 4194304
#define W3O 8388608
#define W2O 12582912

__device__ __forceinline__ uint32_t h2pack(float a, float b) {
    __half2 h = __floats2half2_rn(a, b);
    return *reinterpret_cast<uint32_t*>(&h);
}

__device__ __forceinline__ void mma_f16(float* c, const uint32_t* a, uint32_t b0, uint32_t b1) {
    asm volatile(
        "mma.sync.aligned.m16n8k16.row.col.f32.f16.f16.f32 "
        "{%0,%1,%2,%3}, {%4,%5,%6,%7}, {%8,%9}, {%0,%1,%2,%3};\n"
        : "+f"(c[0]), "+f"(c[1]), "+f"(c[2]), "+f"(c[3])
        : "r"(a[0]), "r"(a[1]), "r"(a[2]), "r"(a[3]), "r"(b0), "r"(b1));
}

__device__ __forceinline__ void ldsm4(uint32_t* r, uint32_t saddr) {
    asm volatile("ldmatrix.sync.aligned.m8n8.x4.shared.b16 {%0,%1,%2,%3}, [%4];"
        : "=r"(r[0]), "=r"(r[1]), "=r"(r[2]), "=r"(r[3]) : "r"(saddr));
}

__device__ __forceinline__ void ldsm4t(uint32_t* r, uint32_t saddr) {
    asm volatile("ldmatrix.sync.aligned.m8n8.x4.trans.shared.b16 {%0,%1,%2,%3}, [%4];"
        : "=r"(r[0]), "=r"(r[1]), "=r"(r[2]), "=r"(r[3]) : "r"(saddr));
}

__device__ __forceinline__ void cp16(uint32_t saddr, const void* gptr) {
    asm volatile("cp.async.cg.shared.global [%0], [%1], 16;" :: "r"(saddr), "l"(gptr));
}

__device__ __forceinline__ uint32_t smem_u32(const void* p) {
    uint32_t a;
    asm("{ .reg .u64 t; cvta.to.shared.u64 t, %1; cvt.u32.u64 %0, t; }" : "=r"(a) : "l"(p));
    return a;
}

// ---------------- weight fp16 convert (single z-batched launch) ----------------------
struct CvtBatch {
    const float* src[7];
    int off[7];
    int n4[7];
};

__global__ void cvt_all_k(CvtBatch cb, __half* __restrict__ wt) {
    const float* src = cb.src[blockIdx.z];
    __half* dst = wt + cb.off[blockIdx.z];
    int n4 = cb.n4[blockIdx.z];
    int stride = gridDim.x * blockDim.x;
    for (int i = blockIdx.x * blockDim.x + threadIdx.x; i < n4; i += stride) {
        float4 v = ((const float4*)src)[i];
        uint2 o;
        o.x = h2pack(v.x, v.y);
        o.y = h2pack(v.z, v.w);
        ((uint2*)dst)[i] = o;
    }
}

// ---------------- RoPE tables in double precision ------------------------------------
__global__ void rope_tables_k(float* __restrict__ c, float* __restrict__ s) {
    int idx = blockIdx.x * blockDim.x + threadIdx.x;
    int pos = idx >> 5;
    int i   = idx & 31;
    double inv = exp(-((double)(2 * i) / (double)HD) * log(10000.0));
    double ang = (double)pos * inv;
    double cs, sn;
    sincos(ang, &sn, &cs);
    c[idx] = (float)cs;
    s[idx] = (float)sn;
}

// ---------------- RMSNorm: float in -> half out ---------------------------------------
__global__ void rmsnorm_k(const float* __restrict__ x, const float* __restrict__ g,
                          __half* __restrict__ o) {
    int row = blockIdx.x;
    const float4* xr = (const float4*)(x + (size_t)row * DIM);
    uint2* orow = (uint2*)(o + (size_t)row * DIM);
    int t = threadIdx.x;
    float4 v = xr[t];
    float ss = v.x * v.x + v.y * v.y + v.z * v.z + v.w * v.w;
    #pragma unroll
    for (int off = 16; off; off >>= 1) ss += __shfl_xor_sync(0xffffffffu, ss, off);
    __shared__ float sp[8];
    if ((t & 31) == 0) sp[t >> 5] = ss;
    __syncthreads();
    if (t < 8) {
        float s2 = sp[t];
        #pragma unroll
        for (int off = 4; off; off >>= 1) s2 += __shfl_xor_sync(0xffu, s2, off);
        if (t == 0) sp[0] = s2;
    }
    __syncthreads();
    float rs = rsqrtf(sp[0] * (1.0f / DIM) + 1e-6f);
    float4 gg = ((const float4*)g)[t];
    uint2 out;
    out.x = h2pack(v.x * rs * gg.x, v.y * rs * gg.y);
    out.y = h2pack(v.z * rs * gg.z, v.w * rs * gg.w);
    orow[t] = out;
}

// ---------------- fp16 GEMM: CTA 128x128, warp 64x32, 4-stage cp.async ---------------
// Optional fused RoPE in the half-output epilogue (for z = 0/1 of the QKV launch).
#define BM 128
#define BN 128
#define BKH 32
#define SSTH 40
#define STAGES 4
#define AWH  (BM * SSTH)
#define STGH (2 * AWH)
#define GSMEM (STAGES * STGH * 2)

struct Batch3 {
    const __half* B[3];
    void*         C[3];
    const float*  R[3];
};

template <bool RESID, bool HOUT, bool ROPE>
__global__ __launch_bounds__(256, 2)
void gemm_tc(const __half* __restrict__ A, Batch3 bt, int M, int N, int K,
             const float* __restrict__ ct, const float* __restrict__ st) {
    extern __shared__ uint32_t smw[];
    const __half* __restrict__ Bp = bt.B[blockIdx.z];
    const float*  __restrict__ Rp = bt.R[blockIdx.z];

    const int bm = blockIdx.y * BM;
    const int bn = blockIdx.x * BN;
    const int tid  = threadIdx.x;
    const int warp = tid >> 5;
    const int lane = tid & 31;
    const int grp  = lane >> 2;
    const int tig  = lane & 3;
    const int wm = (warp >> 2) * 64;
    const int wn = (warp & 3) * 32;

    const int frow = lane & 15;
    const int fcol = (lane >> 4) * 8;

    float acc[4][4][4];
    #pragma unroll
    for (int i = 0; i < 4; i++)
        #pragma unroll
        for (int j = 0; j < 4; j++)
            #pragma unroll
            for (int r = 0; r < 4; r++) acc[i][j][r] = 0.0f;

    const int NT = K / BKH;
    const uint32_t smb = smem_u32(smw);

    const int lrow = tid >> 2;
    const int loff = (tid & 3) * 8;

    auto issue = [&](int kt) {
        const int st = kt % STAGES;
        const uint32_t ab = smb + st * STGH * 2;
        const uint32_t bb = ab + AWH * 2;
        const __half* Ag = A  + (size_t)bm * K + kt * BKH;
        const __half* Bg = Bp + (size_t)bn * K + kt * BKH;
        #pragma unroll
        for (int i = 0; i < 2; i++) {
            int row = lrow + i * 64;
            cp16(ab + (row * SSTH + loff) * 2, Ag + (size_t)row * K + loff);
            cp16(bb + (row * SSTH + loff) * 2, Bg + (size_t)row * K + loff);
        }
        asm volatile("cp.async.commit_group;");
    };

    issue(0);
    issue(1);
    issue(2);

    for (int kt = 0; kt < NT; kt++) {
        const int rem = NT - 1 - kt;
        if (rem >= 2) {
            asm volatile("cp.async.wait_group 2;");
        } else if (rem == 1) {
            asm volatile("cp.async.wait_group 1;");
        } else {
            asm volatile("cp.async.wait_group 0;");
        }
        __syncthreads();
        if (kt + 3 < NT) issue(kt + 3);

        const int st = kt % STAGES;
        const uint32_t ab = smb + st * STGH * 2;
        const uint32_t bb = ab + AWH * 2;

        #pragma unroll
        for (int ks = 0; ks < 2; ks++) {
            const int kb = ks * 16;
            uint32_t af[4][4], bf[2][4];
            #pragma unroll
            for (int mt = 0; mt < 4; mt++)
                ldsm4(af[mt], ab + (((wm + mt * 16 + frow) * SSTH) + kb + fcol) * 2);
            #pragma unroll
            for (int bk = 0; bk < 2; bk++)
                ldsm4(bf[bk], bb + (((wn + bk * 16 + frow) * SSTH) + kb + fcol) * 2);
            #pragma unroll
            for (int mt = 0; mt < 4; mt++)
                #pragma unroll
                for (int nt = 0; nt < 4; nt++)
                    mma_f16(acc[mt][nt], af[mt],
                            bf[nt >> 1][nt & 1], bf[nt >> 1][(nt & 1) + 2]);
        }
    }

    const bool do_rope = ROPE && (blockIdx.z < 2);

    #pragma unroll
    for (int mt = 0; mt < 4; mt++) {
        const int row = bm + wm + mt * 16 + grp;
        #pragma unroll
        for (int nt = 0; nt < 4; nt++) {
            const int col = bn + wn + nt * 8 + 2 * tig;   // even
            size_t i0 = (size_t)row * N + col;
            size_t i1 = (size_t)(row + 8) * N + col;
            if (HOUT) {
                __half* Cp = (__half*)bt.C[blockIdx.z];
                float a0 = acc[mt][nt][0], a1 = acc[mt][nt][1];
                float a2 = acc[mt][nt][2], a3 = acc[mt][nt][3];
                if (do_rope) {
                    int ri = (col & 63) >> 1;
                    float c0 = ct[row * 32 + ri],       s0 = st[row * 32 + ri];
                    float c1 = ct[(row + 8) * 32 + ri], s1 = st[(row + 8) * 32 + ri];
                    float r0 = a0 * c0 - a1 * s0, r1 = a0 * s0 + a1 * c0;
                    float r2 = a2 * c1 - a3 * s1, r3 = a2 * s1 + a3 * c1;
                    a0 = r0; a1 = r1; a2 = r2; a3 = r3;
                }
                *(uint32_t*)&Cp[i0] = h2pack(a0, a1);
                *(uint32_t*)&Cp[i1] = h2pack(a2, a3);
            } else {
                float* Cp = (float*)bt.C[blockIdx.z];
                float2 v0 = make_float2(acc[mt][nt][0], acc[mt][nt][1]);
                float2 v1 = make_float2(acc[mt][nt][2], acc[mt][nt][3]);
                if (RESID) {
                    float2 r0v = *(const float2*)&Rp[i0];
                    float2 r1v = *(const float2*)&Rp[i1];
                    v0.x += r0v.x; v0.y += r0v.y;
                    v1.x += r1v.x; v1.y += r1v.y;
                }
                *(float2*)&Cp[i0] = v0;
                *(float2*)&Cp[i1] = v1;
            }
        }
    }
}

// ---------------- fp16 flash attention: BQ=256 (16 warps), stage BKV=128 -------------
#define BQ   256
#define BKV  128
#define KP2  72
#define KW2  (BKV * KP2)
#define AST2 (2 * KW2)
#define PSO2 (2 * AST2)
#define ASMEM ((PSO2 + BQ * KP2) * 2)   // 110592 bytes

__global__ __launch_bounds__(512, 1)
void flash_attn_tc(const __half* __restrict__ Q, const __half* __restrict__ K,
                   const __half* __restrict__ V, __half* __restrict__ O) {
    extern __shared__ uint32_t smw[];

    const int h  = blockIdx.y;
    const int q0 = blockIdx.x * BQ;
    const int tid  = threadIdx.x;
    const int warp = tid >> 5;
    const int lane = tid & 31;
    const int grp  = lane >> 2;
    const int tig  = lane & 3;
    const int wm   = warp * 16;          // 16 warps x 16 rows = 256

    const int frow = lane & 15;
    const int fcol = (lane >> 4) * 8;

    const uint32_t smb = smem_u32(smw);
    const uint32_t psb = smb + PSO2 * 2;

    uint32_t qf[4][4];
    {
        const __half* qb = Q + (size_t)(q0 + wm) * DIM + h * HD;
        #pragma unroll
        for (int ks = 0; ks < 4; ks++) {
            qf[ks][0] = *(const uint32_t*)&qb[(size_t)grp       * DIM + ks * 16 + 2 * tig];
            qf[ks][1] = *(const uint32_t*)&qb[(size_t)(grp + 8) * DIM + ks * 16 + 2 * tig];
            qf[ks][2] = *(const uint32_t*)&qb[(size_t)grp       * DIM + ks * 16 + 8 + 2 * tig];
            qf[ks][3] = *(const uint32_t*)&qb[(size_t)(grp + 8) * DIM + ks * 16 + 8 + 2 * tig];
        }
    }

    float o[8][4];
    #pragma unroll
    for (int dt = 0; dt < 8; dt++)
        #pragma unroll
        for (int r = 0; r < 4; r++) o[dt][r] = 0.0f;
    float m0 = -1e30f, m1 = -1e30f, l0 = 0.0f, l1 = 0.0f;

    const int NT = SEQ / BKV;            // 32 stages of 128 rows
    const int lrow = tid >> 3;           // 0..63
    const int loff = (tid & 7) * 8;      // 0..56 halves

    auto issue = [&](int t) {
        const uint32_t kb = smb + (t & 1) * AST2 * 2;
        const uint32_t vb = kb + KW2 * 2;
        const __half* Kg = K + (size_t)(t * BKV) * DIM + h * HD;
        const __half* Vg = V + (size_t)(t * BKV) * DIM + h * HD;
        #pragma unroll
        for (int i = 0; i < 2; i++) {
            int row = lrow + i * 64;
            cp16(kb + (row * KP2 + loff) * 2, Kg + (size_t)row * DIM + loff);
            cp16(vb + (row * KP2 + loff) * 2, Vg + (size_t)row * DIM + loff);
        }
        asm volatile("cp.async.commit_group;");
    };

    issue(0);

    for (int t = 0; t < NT; t++) {
        if (t + 1 < NT) {
            issue(t + 1);
            asm volatile("cp.async.wait_group 1;");
        } else {
            asm volatile("cp.async.wait_group 0;");
        }
        __syncthreads();

        #pragma unroll
        for (int half = 0; half < 2; half++) {
            const uint32_t ksb = smb + (t & 1) * AST2 * 2 + half * (64 * KP2) * 2;
            const uint32_t vsb = smb + ((t & 1) * AST2 + KW2 + half * (64 * KP2)) * 2;

            float sc[8][4];
            #pragma unroll
            for (int nt = 0; nt < 8; nt++)
                #pragma unroll
                for (int r = 0; r < 4; r++) sc[nt][r] = 0.0f;
            #pragma unroll
            for (int ks = 0; ks < 4; ks++) {
                const int kb = ks * 16;
                uint32_t kf[4][4];
                #pragma unroll
                for (int g = 0; g < 4; g++)
                    ldsm4(kf[g], ksb + (((g * 16 + frow) * KP2) + kb + fcol) * 2);
                #pragma unroll
                for (int nt = 0; nt < 8; nt++)
                    mma_f16(sc[nt], qf[ks],
                            kf[nt >> 1][nt & 1], kf[nt >> 1][(nt & 1) + 2]);
            }
            #pragma unroll
            for (int nt = 0; nt < 8; nt++) {
                sc[nt][0] *= 0.125f; sc[nt][1] *= 0.125f;
                sc[nt][2] *= 0.125f; sc[nt][3] *= 0.125f;
            }

            float mx0 = -1e30f, mx1 = -1e30f;
            #pragma unroll
            for (int nt = 0; nt < 8; nt++) {
                mx0 = fmaxf(mx0, fmaxf(sc[nt][0], sc[nt][1]));
                mx1 = fmaxf(mx1, fmaxf(sc[nt][2], sc[nt][3]));
            }
            mx0 = fmaxf(mx0, __shfl_xor_sync(0xffffffffu, mx0, 1));
            mx0 = fmaxf(mx0, __shfl_xor_sync(0xffffffffu, mx0, 2));
            mx1 = fmaxf(mx1, __shfl_xor_sync(0xffffffffu, mx1, 1));
            mx1 = fmaxf(mx1, __shfl_xor_sync(0xffffffffu, mx1, 2));

            float mn0 = fmaxf(m0, mx0);
            float mn1 = fmaxf(m1, mx1);
            float cr0 = __expf(m0 - mn0);
            float cr1 = __expf(m1 - mn1);
            m0 = mn0; m1 = mn1;

            float s0 = 0.0f, s1 = 0.0f;
            #pragma unroll
            for (int nt = 0; nt < 8; nt++) {
                sc[nt][0] = __expf(sc[nt][0] - mn0);
                sc[nt][1] = __expf(sc[nt][1] - mn0);
                sc[nt][2] = __expf(sc[nt][2] - mn1);
                sc[nt][3] = __expf(sc[nt][3] - mn1);
                s0 += sc[nt][0] + sc[nt][1];
                s1 += sc[nt][2] + sc[nt][3];
            }
            s0 += __shfl_xor_sync(0xffffffffu, s0, 1);
            s0 += __shfl_xor_sync(0xffffffffu, s0, 2);
            s1 += __shfl_xor_sync(0xffffffffu, s1, 1);
            s1 += __shfl_xor_sync(0xffffffffu, s1, 2);
            l0 = l0 * cr0 + s0;
            l1 = l1 * cr1 + s1;

            #pragma unroll
            for (int dt = 0; dt < 8; dt++) {
                o[dt][0] *= cr0; o[dt][1] *= cr0;
                o[dt][2] *= cr1; o[dt][3] *= cr1;
            }

            #pragma unroll
            for (int nt = 0; nt < 8; nt++) {
                *(uint32_t*)((char*)smw + (PSO2 + (wm + grp    ) * KP2 + nt * 8 + 2 * tig) * 2)
                    = h2pack(sc[nt][0], sc[nt][1]);
                *(uint32_t*)((char*)smw + (PSO2 + (wm + grp + 8) * KP2 + nt * 8 + 2 * tig) * 2)
                    = h2pack(sc[nt][2], sc[nt][3]);
            }
            __syncwarp();

            #pragma unroll
            for (int ks = 0; ks < 4; ks++) {
                const int kb = ks * 16;
                uint32_t pa[4], vf[4][4];
                ldsm4(pa, psb + (((wm + frow) * KP2) + kb + fcol) * 2);
                #pragma unroll
                for (int db = 0; db < 4; db++)
                    ldsm4t(vf[db], vsb + (((kb + frow) * KP2) + db * 16 + fcol) * 2);
                #pragma unroll
                for (int dt = 0; dt < 8; dt++)
                    mma_f16(o[dt], pa,
                            vf[dt >> 1][(dt & 1) * 2], vf[dt >> 1][(dt & 1) * 2 + 1]);
            }
            __syncwarp();
        }
        __syncthreads();
    }

    float il0 = 1.0f / l0;
    float il1 = 1.0f / l1;
    #pragma unroll
    for (int dt = 0; dt < 8; dt++) {
        size_t i0 = (size_t)(q0 + wm + grp    ) * DIM + h * HD + dt * 8 + 2 * tig;
        size_t i1 = (size_t)(q0 + wm + grp + 8) * DIM + h * HD + dt * 8 + 2 * tig;
        *(uint32_t*)&O[i0] = h2pack(o[dt][0] * il0, o[dt][1] * il0);
        *(uint32_t*)&O[i1] = h2pack(o[dt][2] * il1, o[dt][3] * il1);
    }
}

// ---------------- SwiGLU elementwise (half) -------------------------------------------
__global__ void silu_mul_k(__half* __restrict__ a, const __half* __restrict__ b, int n4) {
    int i = blockIdx.x * blockDim.x + threadIdx.x;
    if (i < n4) {
        uint2 ua = ((uint2*)a)[i];
        uint2 ub = ((const uint2*)b)[i];
        float2 x0 = __half22float2(*(__half2*)&ua.x);
        float2 x1 = __half22float2(*(__half2*)&ua.y);
        float2 y0 = __half22float2(*(__half2*)&ub.x);
        float2 y1 = __half22float2(*(__half2*)&ub.y);
        uint2 o;
        o.x = h2pack(x0.x / (1.0f + __expf(-x0.x)) * y0.x,
                     x0.y / (1.0f + __expf(-x0.y)) * y0.y);
        o.y = h2pack(x1.x / (1.0f + __expf(-x1.x)) * y1.x,
                     x1.y / (1.0f + __expf(-x1.y)) * y1.y);
        ((uint2*)a)[i] = o;
    }
}

// ---------------- launch --------------------------------------------------------------
extern "C" void kernel_launch(void* const* d_in, const int* in_sizes, int n_in,
                              void* d_out, int out_size) {
    const float* x  = (const float*)d_in[0];
    const float* wq = (const float*)d_in[1];
    const float* wk = (const float*)d_in[2];
    const float* wv = (const float*)d_in[3];
    const float* wo = (const float*)d_in[4];
    const float* w1 = (const float*)d_in[5];
    const float* w2 = (const float*)d_in[6];
    const float* w3 = (const float*)d_in[7];
    const float* ga = (const float*)d_in[8];
    const float* gf = (const float*)d_in[9];
    float* out = (float*)d_out;

    __half *xn, *q, *k, *v, *at, *hn, *t1, *t3, *wt;
    float *ct, *st;
    cudaGetSymbolAddress((void**)&xn, g_xn);
    cudaGetSymbolAddress((void**)&q,  g_q);
    cudaGetSymbolAddress((void**)&k,  g_k);
    cudaGetSymbolAddress((void**)&v,  g_v);
    cudaGetSymbolAddress((void**)&at, g_at);
    cudaGetSymbolAddress((void**)&hn, g_hn);
    cudaGetSymbolAddress((void**)&t1, g_t1);
    cudaGetSymbolAddress((void**)&t3, g_t3);
    cudaGetSymbolAddress((void**)&ct, g_cos);
    cudaGetSymbolAddress((void**)&st, g_sin);
    cudaGetSymbolAddress((void**)&wt, g_wt);

    cudaFuncSetAttribute((const void*)gemm_tc<false, true,  true>,  cudaFuncAttributeMaxDynamicSharedMemorySize, GSMEM);
    cudaFuncSetAttribute((const void*)gemm_tc<false, true,  false>, cudaFuncAttributeMaxDynamicSharedMemorySize, GSMEM);
    cudaFuncSetAttribute((const void*)gemm_tc<true,  false, false>, cudaFuncAttributeMaxDynamicSharedMemorySize, GSMEM);
    cudaFuncSetAttribute((const void*)flash_attn_tc, cudaFuncAttributeMaxDynamicSharedMemorySize, ASMEM);

    // all weights -> fp16 (one z-batched launch)
    {
        CvtBatch cb;
        cb.src[0] = wq; cb.off[0] = WQO; cb.n4[0] = DIM * DIM / 4;
        cb.src[1] = wk; cb.off[1] = WKO; cb.n4[1] = DIM * DIM / 4;
        cb.src[2] = wv; cb.off[2] = WVO; cb.n4[2] = DIM * DIM / 4;
        cb.src[3] = wo; cb.off[3] = WOO; cb.n4[3] = DIM * DIM / 4;
        cb.src[4] = w1; cb.off[4] = W1O; cb.n4[4] = HIDDEN * DIM / 4;
        cb.src[5] = w3; cb.off[5] = W3O; cb.n4[5] = HIDDEN * DIM / 4;
        cb.src[6] = w2; cb.off[6] = W2O; cb.n4[6] = DIM * HIDDEN / 4;
        cvt_all_k<<<dim3(256, 1, 7), 256>>>(cb, wt);
    }

    rope_tables_k<<<(SEQ * 32) / 256, 256>>>(ct, st);
    rmsnorm_k<<<SEQ, 256>>>(x, ga, xn);

    // QKV batched (z = 3), half out, RoPE fused for z=0 (q) and z=1 (k)
    {
        Batch3 bt;
        bt.B[0] = wt + WQO; bt.B[1] = wt + WKO; bt.B[2] = wt + WVO;
        bt.C[0] = q; bt.C[1] = k; bt.C[2] = v;
        bt.R[0] = bt.R[1] = bt.R[2] = nullptr;
        gemm_tc<false, true, true><<<dim3(DIM / BN, SEQ / BM, 3), 256, GSMEM>>>(
            xn, bt, SEQ, DIM, DIM, ct, st);
    }

    flash_attn_tc<<<dim3(SEQ / BQ, NH), 512, ASMEM>>>(q, k, v, at);

    // Wo + residual -> out (float)
    {
        Batch3 bt;
        bt.B[0] = wt + WOO; bt.C[0] = out; bt.R[0] = x;
        bt.B[1] = bt.B[2] = nullptr; bt.C[1] = bt.C[2] = nullptr; bt.R[1] = bt.R[2] = nullptr;
        gemm_tc<true, false, false><<<dim3(DIM / BN, SEQ / BM, 1), 256, GSMEM>>>(
            at, bt, SEQ, DIM, DIM, nullptr, nullptr);
    }

    rmsnorm_k<<<SEQ, 256>>>(out, gf, hn);

    // w1 / w3 batched (z = 2), half out
    {
        Batch3 bt;
        bt.B[0] = wt + W1O; bt.B[1] = wt + W3O; bt.B[2] = nullptr;
        bt.C[0] = t1; bt.C[1] = t3; bt.C[2] = nullptr;
        bt.R[0] = bt.R[1] = bt.R[2] = nullptr;
        gemm_tc<false, true, false><<<dim3(HIDDEN / BN, SEQ / BM, 2), 256, GSMEM>>>(
            hn, bt, SEQ, HIDDEN, DIM, nullptr, nullptr);
    }

    silu_mul_k<<<(SEQ * HIDDEN / 4 + 255) / 256, 256>>>(t1, t3, SEQ * HIDDEN / 4);

    // W2 + residual -> out (float, in-place residual)
    {
        Batch3 bt;
        bt.B[0] = wt + W2O; bt.C[0] = out; bt.R[0] = out;
        bt.B[1] = bt.B[2] = nullptr; bt.C[1] = bt.C[2] = nullptr; bt.R[1] = bt.R[2] = nullptr;
        gemm_tc<true, false, false><<<dim3(DIM / BN, SEQ / BM, 1), 256, GSMEM>>>(
            t1, bt, SEQ, DIM, HIDDEN, nullptr, nullptr);
    }
}

// round 15
// speedup vs baseline: 1.7755x; 1.0115x over previous
#include <cuda_runtime.h>
#include <cuda_fp16.h>
#include <math.h>
#include <stdint.h>

#define SEQ    4096
#define DIM    1024
#define NH     16
#define HD     64
#define HIDDEN 4096

// ---------------- scratch (fp16 activations/weights) ---------------------------------
__device__ __half g_xn[SEQ * DIM];
__device__ __half g_q [SEQ * DIM];
__device__ __half g_k [SEQ * DIM];
__device__ __half g_v [SEQ * DIM];
__device__ __half g_at[SEQ * DIM];
__device__ __half g_hn[SEQ * DIM];
__device__ __half g_t1[SEQ * HIDDEN];
__device__ __half g_t3[SEQ * HIDDEN];
__device__ float  g_cos[SEQ * (HD / 2)];
__device__ float  g_sin[SEQ * (HD / 2)];
__device__ __half g_wt[16777216];          // fp16 weights (32MB)

#define WQO 0
#define WKO 1048576
#define WVO 2097152
#define WOO 3145728
#define W1O 4194304
#define W3O 8388608
#define W2O 12582912

__device__ __forceinline__ uint32_t h2pack(float a, float b) {
    __half2 h = __floats2half2_rn(a, b);
    return *reinterpret_cast<uint32_t*>(&h);
}

__device__ __forceinline__ void mma_f16(float* c, const uint32_t* a, uint32_t b0, uint32_t b1) {
    asm volatile(
        "mma.sync.aligned.m16n8k16.row.col.f32.f16.f16.f32 "
        "{%0,%1,%2,%3}, {%4,%5,%6,%7}, {%8,%9}, {%0,%1,%2,%3};\n"
        : "+f"(c[0]), "+f"(c[1]), "+f"(c[2]), "+f"(c[3])
        : "r"(a[0]), "r"(a[1]), "r"(a[2]), "r"(a[3]), "r"(b0), "r"(b1));
}

__device__ __forceinline__ void ldsm4(uint32_t* r, uint32_t saddr) {
    asm volatile("ldmatrix.sync.aligned.m8n8.x4.shared.b16 {%0,%1,%2,%3}, [%4];"
        : "=r"(r[0]), "=r"(r[1]), "=r"(r[2]), "=r"(r[3]) : "r"(saddr));
}

__device__ __forceinline__ void ldsm4t(uint32_t* r, uint32_t saddr) {
    asm volatile("ldmatrix.sync.aligned.m8n8.x4.trans.shared.b16 {%0,%1,%2,%3}, [%4];"
        : "=r"(r[0]), "=r"(r[1]), "=r"(r[2]), "=r"(r[3]) : "r"(saddr));
}

__device__ __forceinline__ void cp16(uint32_t saddr, const void* gptr) {
    asm volatile("cp.async.cg.shared.global [%0], [%1], 16;" :: "r"(saddr), "l"(gptr));
}

__device__ __forceinline__ uint32_t smem_u32(const void* p) {
    uint32_t a;
    asm("{ .reg .u64 t; cvta.to.shared.u64 t, %1; cvt.u32.u64 %0, t; }" : "=r"(a) : "l"(p));
    return a;
}

// ---------------- weight fp16 convert (single z-batched launch) ----------------------
struct CvtBatch {
    const float* src[7];
    int off[7];
    int n4[7];
};

__global__ void cvt_all_k(CvtBatch cb, __half* __restrict__ wt) {
    const float* src = cb.src[blockIdx.z];
    __half* dst = wt + cb.off[blockIdx.z];
    int n4 = cb.n4[blockIdx.z];
    int stride = gridDim.x * blockDim.x;
    for (int i = blockIdx.x * blockDim.x + threadIdx.x; i < n4; i += stride) {
        float4 v = ((const float4*)src)[i];
        uint2 o;
        o.x = h2pack(v.x, v.y);
        o.y = h2pack(v.z, v.w);
        ((uint2*)dst)[i] = o;
    }
}

// ---------------- RoPE tables in double precision ------------------------------------
__global__ void rope_tables_k(float* __restrict__ c, float* __restrict__ s) {
    int idx = blockIdx.x * blockDim.x + threadIdx.x;
    int pos = idx >> 5;
    int i   = idx & 31;
    double inv = exp(-((double)(2 * i) / (double)HD) * log(10000.0));
    double ang = (double)pos * inv;
    double cs, sn;
    sincos(ang, &sn, &cs);
    c[idx] = (float)cs;
    s[idx] = (float)sn;
}

// ---------------- RMSNorm: float in -> half out ---------------------------------------
__global__ void rmsnorm_k(const float* __restrict__ x, const float* __restrict__ g,
                          __half* __restrict__ o) {
    int row = blockIdx.x;
    const float4* xr = (const float4*)(x + (size_t)row * DIM);
    uint2* orow = (uint2*)(o + (size_t)row * DIM);
    int t = threadIdx.x;
    float4 v = xr[t];
    float ss = v.x * v.x + v.y * v.y + v.z * v.z + v.w * v.w;
    #pragma unroll
    for (int off = 16; off; off >>= 1) ss += __shfl_xor_sync(0xffffffffu, ss, off);
    __shared__ float sp[8];
    if ((t & 31) == 0) sp[t >> 5] = ss;
    __syncthreads();
    if (t < 8) {
        float s2 = sp[t];
        #pragma unroll
        for (int off = 4; off; off >>= 1) s2 += __shfl_xor_sync(0xffu, s2, off);
        if (t == 0) sp[0] = s2;
    }
    __syncthreads();
    float rs = rsqrtf(sp[0] * (1.0f / DIM) + 1e-6f);
    float4 gg = ((const float4*)g)[t];
    uint2 out;
    out.x = h2pack(v.x * rs * gg.x, v.y * rs * gg.y);
    out.y = h2pack(v.z * rs * gg.z, v.w * rs * gg.w);
    orow[t] = out;
}

// ---------------- fp16 GEMM: CTA 128x128, warp 64x32, 4-stage cp.async ---------------
// Optional fused RoPE in the half-output epilogue (QKV launch z=0/1); z=0 also folds
// the attention score scale 0.125 into Q (power-of-two: bit-exact in fp16).
#define BM 128
#define BN 128
#define BKH 32
#define SSTH 40
#define STAGES 4
#define AWH  (BM * SSTH)
#define STGH (2 * AWH)
#define GSMEM (STAGES * STGH * 2)

struct Batch3 {
    const __half* B[3];
    void*         C[3];
    const float*  R[3];
};

template <bool RESID, bool HOUT, bool ROPE>
__global__ __launch_bounds__(256, 2)
void gemm_tc(const __half* __restrict__ A, Batch3 bt, int M, int N, int K,
             const float* __restrict__ ct, const float* __restrict__ st) {
    extern __shared__ uint32_t smw[];
    const __half* __restrict__ Bp = bt.B[blockIdx.z];
    const float*  __restrict__ Rp = bt.R[blockIdx.z];

    const int bm = blockIdx.y * BM;
    const int bn = blockIdx.x * BN;
    const int tid  = threadIdx.x;
    const int warp = tid >> 5;
    const int lane = tid & 31;
    const int grp  = lane >> 2;
    const int tig  = lane & 3;
    const int wm = (warp >> 2) * 64;
    const int wn = (warp & 3) * 32;

    const int frow = lane & 15;
    const int fcol = (lane >> 4) * 8;

    float acc[4][4][4];
    #pragma unroll
    for (int i = 0; i < 4; i++)
        #pragma unroll
        for (int j = 0; j < 4; j++)
            #pragma unroll
            for (int r = 0; r < 4; r++) acc[i][j][r] = 0.0f;

    const int NT = K / BKH;
    const uint32_t smb = smem_u32(smw);

    const int lrow = tid >> 2;
    const int loff = (tid & 3) * 8;

    auto issue = [&](int kt) {
        const int st = kt % STAGES;
        const uint32_t ab = smb + st * STGH * 2;
        const uint32_t bb = ab + AWH * 2;
        const __half* Ag = A  + (size_t)bm * K + kt * BKH;
        const __half* Bg = Bp + (size_t)bn * K + kt * BKH;
        #pragma unroll
        for (int i = 0; i < 2; i++) {
            int row = lrow + i * 64;
            cp16(ab + (row * SSTH + loff) * 2, Ag + (size_t)row * K + loff);
            cp16(bb + (row * SSTH + loff) * 2, Bg + (size_t)row * K + loff);
        }
        asm volatile("cp.async.commit_group;");
    };

    issue(0);
    issue(1);
    issue(2);

    for (int kt = 0; kt < NT; kt++) {
        const int rem = NT - 1 - kt;
        if (rem >= 2) {
            asm volatile("cp.async.wait_group 2;");
        } else if (rem == 1) {
            asm volatile("cp.async.wait_group 1;");
        } else {
            asm volatile("cp.async.wait_group 0;");
        }
        __syncthreads();
        if (kt + 3 < NT) issue(kt + 3);

        const int st = kt % STAGES;
        const uint32_t ab = smb + st * STGH * 2;
        const uint32_t bb = ab + AWH * 2;

        #pragma unroll
        for (int ks = 0; ks < 2; ks++) {
            const int kb = ks * 16;
            uint32_t af[4][4], bf[2][4];
            #pragma unroll
            for (int mt = 0; mt < 4; mt++)
                ldsm4(af[mt], ab + (((wm + mt * 16 + frow) * SSTH) + kb + fcol) * 2);
            #pragma unroll
            for (int bk = 0; bk < 2; bk++)
                ldsm4(bf[bk], bb + (((wn + bk * 16 + frow) * SSTH) + kb + fcol) * 2);
            #pragma unroll
            for (int mt = 0; mt < 4; mt++)
                #pragma unroll
                for (int nt = 0; nt < 4; nt++)
                    mma_f16(acc[mt][nt], af[mt],
                            bf[nt >> 1][nt & 1], bf[nt >> 1][(nt & 1) + 2]);
        }
    }

    const bool do_rope = ROPE && (blockIdx.z < 2);
    const float qscale = (ROPE && blockIdx.z == 0) ? 0.125f : 1.0f;

    #pragma unroll
    for (int mt = 0; mt < 4; mt++) {
        const int row = bm + wm + mt * 16 + grp;
        // hoisted per-row rope table base (index depends on col within head: recomputed
        // per nt as ri, but row*32 base hoisted here)
        const int rb0 = row * 32;
        const int rb1 = (row + 8) * 32;
        #pragma unroll
        for (int nt = 0; nt < 4; nt++) {
            const int col = bn + wn + nt * 8 + 2 * tig;   // even
            size_t i0 = (size_t)row * N + col;
            size_t i1 = (size_t)(row + 8) * N + col;
            if (HOUT) {
                __half* Cp = (__half*)bt.C[blockIdx.z];
                float a0 = acc[mt][nt][0], a1 = acc[mt][nt][1];
                float a2 = acc[mt][nt][2], a3 = acc[mt][nt][3];
                if (do_rope) {
                    int ri = (col & 63) >> 1;
                    float c0 = ct[rb0 + ri], s0 = st[rb0 + ri];
                    float c1 = ct[rb1 + ri], s1 = st[rb1 + ri];
                    float r0 = a0 * c0 - a1 * s0, r1 = a0 * s0 + a1 * c0;
                    float r2 = a2 * c1 - a3 * s1, r3 = a2 * s1 + a3 * c1;
                    a0 = r0 * qscale; a1 = r1 * qscale;
                    a2 = r2 * qscale; a3 = r3 * qscale;
                }
                *(uint32_t*)&Cp[i0] = h2pack(a0, a1);
                *(uint32_t*)&Cp[i1] = h2pack(a2, a3);
            } else {
                float* Cp = (float*)bt.C[blockIdx.z];
                float2 v0 = make_float2(acc[mt][nt][0], acc[mt][nt][1]);
                float2 v1 = make_float2(acc[mt][nt][2], acc[mt][nt][3]);
                if (RESID) {
                    float2 r0v = *(const float2*)&Rp[i0];
                    float2 r1v = *(const float2*)&Rp[i1];
                    v0.x += r0v.x; v0.y += r0v.y;
                    v1.x += r1v.x; v1.y += r1v.y;
                }
                *(float2*)&Cp[i0] = v0;
                *(float2*)&Cp[i1] = v1;
            }
        }
    }
}

// ---------------- fp16 flash attention: BQ=256 (16 warps), stage BKV=128 -------------
// Q pre-scaled by 0.125 in QKV epilogue: no score scaling here (bit-exact fold).
#define BQ   256
#define BKV  128
#define KP2  72
#define KW2  (BKV * KP2)
#define AST2 (2 * KW2)
#define PSO2 (2 * AST2)
#define ASMEM ((PSO2 + BQ * KP2) * 2)   // 110592 bytes

__global__ __launch_bounds__(512, 1)
void flash_attn_tc(const __half* __restrict__ Q, const __half* __restrict__ K,
                   const __half* __restrict__ V, __half* __restrict__ O) {
    extern __shared__ uint32_t smw[];

    const int h  = blockIdx.y;
    const int q0 = blockIdx.x * BQ;
    const int tid  = threadIdx.x;
    const int warp = tid >> 5;
    const int lane = tid & 31;
    const int grp  = lane >> 2;
    const int tig  = lane & 3;
    const int wm   = warp * 16;

    const int frow = lane & 15;
    const int fcol = (lane >> 4) * 8;

    const uint32_t smb = smem_u32(smw);
    const uint32_t psb = smb + PSO2 * 2;

    uint32_t qf[4][4];
    {
        const __half* qb = Q + (size_t)(q0 + wm) * DIM + h * HD;
        #pragma unroll
        for (int ks = 0; ks < 4; ks++) {
            qf[ks][0] = *(const uint32_t*)&qb[(size_t)grp       * DIM + ks * 16 + 2 * tig];
            qf[ks][1] = *(const uint32_t*)&qb[(size_t)(grp + 8) * DIM + ks * 16 + 2 * tig];
            qf[ks][2] = *(const uint32_t*)&qb[(size_t)grp       * DIM + ks * 16 + 8 + 2 * tig];
            qf[ks][3] = *(const uint32_t*)&qb[(size_t)(grp + 8) * DIM + ks * 16 + 8 + 2 * tig];
        }
    }

    float o[8][4];
    #pragma unroll
    for (int dt = 0; dt < 8; dt++)
        #pragma unroll
        for (int r = 0; r < 4; r++) o[dt][r] = 0.0f;
    float m0 = -1e30f, m1 = -1e30f, l0 = 0.0f, l1 = 0.0f;

    const int NT = SEQ / BKV;
    const int lrow = tid >> 3;
    const int loff = (tid & 7) * 8;

    auto issue = [&](int t) {
        const uint32_t kb = smb + (t & 1) * AST2 * 2;
        const uint32_t vb = kb + KW2 * 2;
        const __half* Kg = K + (size_t)(t * BKV) * DIM + h * HD;
        const __half* Vg = V + (size_t)(t * BKV) * DIM + h * HD;
        #pragma unroll
        for (int i = 0; i < 2; i++) {
            int row = lrow + i * 64;
            cp16(kb + (row * KP2 + loff) * 2, Kg + (size_t)row * DIM + loff);
            cp16(vb + (row * KP2 + loff) * 2, Vg + (size_t)row * DIM + loff);
        }
        asm volatile("cp.async.commit_group;");
    };

    issue(0);

    for (int t = 0; t < NT; t++) {
        if (t + 1 < NT) {
            issue(t + 1);
            asm volatile("cp.async.wait_group 1;");
        } else {
            asm volatile("cp.async.wait_group 0;");
        }
        __syncthreads();

        #pragma unroll
        for (int half = 0; half < 2; half++) {
            const uint32_t ksb = smb + (t & 1) * AST2 * 2 + half * (64 * KP2) * 2;
            const uint32_t vsb = smb + ((t & 1) * AST2 + KW2 + half * (64 * KP2)) * 2;

            float sc[8][4];
            #pragma unroll
            for (int nt = 0; nt < 8; nt++)
                #pragma unroll
                for (int r = 0; r < 4; r++) sc[nt][r] = 0.0f;
            #pragma unroll
            for (int ks = 0; ks < 4; ks++) {
                const int kb = ks * 16;
                uint32_t kf[4][4];
                #pragma unroll
                for (int g = 0; g < 4; g++)
                    ldsm4(kf[g], ksb + (((g * 16 + frow) * KP2) + kb + fcol) * 2);
                #pragma unroll
                for (int nt = 0; nt < 8; nt++)
                    mma_f16(sc[nt], qf[ks],
                            kf[nt >> 1][nt & 1], kf[nt >> 1][(nt & 1) + 2]);
            }

            float mx0 = -1e30f, mx1 = -1e30f;
            #pragma unroll
            for (int nt = 0; nt < 8; nt++) {
                mx0 = fmaxf(mx0, fmaxf(sc[nt][0], sc[nt][1]));
                mx1 = fmaxf(mx1, fmaxf(sc[nt][2], sc[nt][3]));
            }
            mx0 = fmaxf(mx0, __shfl_xor_sync(0xffffffffu, mx0, 1));
            mx0 = fmaxf(mx0, __shfl_xor_sync(0xffffffffu, mx0, 2));
            mx1 = fmaxf(mx1, __shfl_xor_sync(0xffffffffu, mx1, 1));
            mx1 = fmaxf(mx1, __shfl_xor_sync(0xffffffffu, mx1, 2));

            float mn0 = fmaxf(m0, mx0);
            float mn1 = fmaxf(m1, mx1);
            float cr0 = __expf(m0 - mn0);
            float cr1 = __expf(m1 - mn1);
            m0 = mn0; m1 = mn1;

            float s0 = 0.0f, s1 = 0.0f;
            #pragma unroll
            for (int nt = 0; nt < 8; nt++) {
                sc[nt][0] = __expf(sc[nt][0] - mn0);
                sc[nt][1] = __expf(sc[nt][1] - mn0);
                sc[nt][2] = __expf(sc[nt][2] - mn1);
                sc[nt][3] = __expf(sc[nt][3] - mn1);
                s0 += sc[nt][0] + sc[nt][1];
                s1 += sc[nt][2] + sc[nt][3];
            }
            s0 += __shfl_xor_sync(0xffffffffu, s0, 1);
            s0 += __shfl_xor_sync(0xffffffffu, s0, 2);
            s1 += __shfl_xor_sync(0xffffffffu, s1, 1);
            s1 += __shfl_xor_sync(0xffffffffu, s1, 2);
            l0 = l0 * cr0 + s0;
            l1 = l1 * cr1 + s1;

            #pragma unroll
            for (int dt = 0; dt < 8; dt++) {
                o[dt][0] *= cr0; o[dt][1] *= cr0;
                o[dt][2] *= cr1; o[dt][3] *= cr1;
            }

            #pragma unroll
            for (int nt = 0; nt < 8; nt++) {
                *(uint32_t*)((char*)smw + (PSO2 + (wm + grp    ) * KP2 + nt * 8 + 2 * tig) * 2)
                    = h2pack(sc[nt][0], sc[nt][1]);
                *(uint32_t*)((char*)smw + (PSO2 + (wm + grp + 8) * KP2 + nt * 8 + 2 * tig) * 2)
                    = h2pack(sc[nt][2], sc[nt][3]);
            }
            __syncwarp();

            #pragma unroll
            for (int ks = 0; ks < 4; ks++) {
                const int kb = ks * 16;
                uint32_t pa[4], vf[4][4];
                ldsm4(pa, psb + (((wm + frow) * KP2) + kb + fcol) * 2);
                #pragma unroll
                for (int db = 0; db < 4; db++)
                    ldsm4t(vf[db], vsb + (((kb + frow) * KP2) + db * 16 + fcol) * 2);
                #pragma unroll
                for (int dt = 0; dt < 8; dt++)
                    mma_f16(o[dt], pa,
                            vf[dt >> 1][(dt & 1) * 2], vf[dt >> 1][(dt & 1) * 2 + 1]);
            }
            __syncwarp();
        }
        __syncthreads();
    }

    float il0 = 1.0f / l0;
    float il1 = 1.0f / l1;
    #pragma unroll
    for (int dt = 0; dt < 8; dt++) {
        size_t i0 = (size_t)(q0 + wm + grp    ) * DIM + h * HD + dt * 8 + 2 * tig;
        size_t i1 = (size_t)(q0 + wm + grp + 8) * DIM + h * HD + dt * 8 + 2 * tig;
        *(uint32_t*)&O[i0] = h2pack(o[dt][0] * il0, o[dt][1] * il0);
        *(uint32_t*)&O[i1] = h2pack(o[dt][2] * il1, o[dt][3] * il1);
    }
}

// ---------------- SwiGLU elementwise (half) -------------------------------------------
__global__ void silu_mul_k(__half* __restrict__ a, const __half* __restrict__ b, int n4) {
    int i = blockIdx.x * blockDim.x + threadIdx.x;
    if (i < n4) {
        uint2 ua = ((uint2*)a)[i];
        uint2 ub = ((const uint2*)b)[i];
        float2 x0 = __half22float2(*(__half2*)&ua.x);
        float2 x1 = __half22float2(*(__half2*)&ua.y);
        float2 y0 = __half22float2(*(__half2*)&ub.x);
        float2 y1 = __half22float2(*(__half2*)&ub.y);
        uint2 o;
        o.x = h2pack(x0.x / (1.0f + __expf(-x0.x)) * y0.x,
                     x0.y / (1.0f + __expf(-x0.y)) * y0.y);
        o.y = h2pack(x1.x / (1.0f + __expf(-x1.x)) * y1.x,
                     x1.y / (1.0f + __expf(-x1.y)) * y1.y);
        ((uint2*)a)[i] = o;
    }
}

// ---------------- launch --------------------------------------------------------------
extern "C" void kernel_launch(void* const* d_in, const int* in_sizes, int n_in,
                              void* d_out, int out_size) {
    const float* x  = (const float*)d_in[0];
    const float* wq = (const float*)d_in[1];
    const float* wk = (const float*)d_in[2];
    const float* wv = (const float*)d_in[3];
    const float* wo = (const float*)d_in[4];
    const float* w1 = (const float*)d_in[5];
    const float* w2 = (const float*)d_in[6];
    const float* w3 = (const float*)d_in[7];
    const float* ga = (const float*)d_in[8];
    const float* gf = (const float*)d_in[9];
    float* out = (float*)d_out;

    __half *xn, *q, *k, *v, *at, *hn, *t1, *t3, *wt;
    float *ct, *st;
    cudaGetSymbolAddress((void**)&xn, g_xn);
    cudaGetSymbolAddress((void**)&q,  g_q);
    cudaGetSymbolAddress((void**)&k,  g_k);
    cudaGetSymbolAddress((void**)&v,  g_v);
    cudaGetSymbolAddress((void**)&at, g_at);
    cudaGetSymbolAddress((void**)&hn, g_hn);
    cudaGetSymbolAddress((void**)&t1, g_t1);
    cudaGetSymbolAddress((void**)&t3, g_t3);
    cudaGetSymbolAddress((void**)&ct, g_cos);
    cudaGetSymbolAddress((void**)&st, g_sin);
    cudaGetSymbolAddress((void**)&wt, g_wt);

    cudaFuncSetAttribute((const void*)gemm_tc<false, true,  true>,  cudaFuncAttributeMaxDynamicSharedMemorySize, GSMEM);
    cudaFuncSetAttribute((const void*)gemm_tc<false, true,  false>, cudaFuncAttributeMaxDynamicSharedMemorySize, GSMEM);
    cudaFuncSetAttribute((const void*)gemm_tc<true,  false, false>, cudaFuncAttributeMaxDynamicSharedMemorySize, GSMEM);
    cudaFuncSetAttribute((const void*)flash_attn_tc, cudaFuncAttributeMaxDynamicSharedMemorySize, ASMEM);

    // all weights -> fp16 (one z-batched launch)
    {
        CvtBatch cb;
        cb.src[0] = wq; cb.off[0] = WQO; cb.n4[0] = DIM * DIM / 4;
        cb.src[1] = wk; cb.off[1] = WKO; cb.n4[1] = DIM * DIM / 4;
        cb.src[2] = wv; cb.off[2] = WVO; cb.n4[2] = DIM * DIM / 4;
        cb.src[3] = wo; cb.off[3] = WOO; cb.n4[3] = DIM * DIM / 4;
        cb.src[4] = w1; cb.off[4] = W1O; cb.n4[4] = HIDDEN * DIM / 4;
        cb.src[5] = w3; cb.off[5] = W3O; cb.n4[5] = HIDDEN * DIM / 4;
        cb.src[6] = w2; cb.off[6] = W2O; cb.n4[6] = DIM * HIDDEN / 4;
        cvt_all_k<<<dim3(256, 1, 7), 256>>>(cb, wt);
    }

    rope_tables_k<<<(SEQ * 32) / 256, 256>>>(ct, st);
    rmsnorm_k<<<SEQ, 256>>>(x, ga, xn);

    // QKV batched (z = 3): RoPE fused for q/k, 0.125 scale folded into q
    {
        Batch3 bt;
        bt.B[0] = wt + WQO; bt.B[1] = wt + WKO; bt.B[2] = wt + WVO;
        bt.C[0] = q; bt.C[1] = k; bt.C[2] = v;
        bt.R[0] = bt.R[1] = bt.R[2] = nullptr;
        gemm_tc<false, true, true><<<dim3(DIM / BN, SEQ / BM, 3), 256, GSMEM>>>(
            xn, bt, SEQ, DIM, DIM, ct, st);
    }

    flash_attn_tc<<<dim3(SEQ / BQ, NH), 512, ASMEM>>>(q, k, v, at);

    // Wo + residual -> out (float)
    {
        Batch3 bt;
        bt.B[0] = wt + WOO; bt.C[0] = out; bt.R[0] = x;
        bt.B[1] = bt.B[2] = nullptr; bt.C[1] = bt.C[2] = nullptr; bt.R[1] = bt.R[2] = nullptr;
        gemm_tc<true, false, false><<<dim3(DIM / BN, SEQ / BM, 1), 256, GSMEM>>>(
            at, bt, SEQ, DIM, DIM, nullptr, nullptr);
    }

    rmsnorm_k<<<SEQ, 256>>>(out, gf, hn);

    // w1 / w3 batched (z = 2), half out
    {
        Batch3 bt;
        bt.B[0] = wt + W1O; bt.B[1] = wt + W3O; bt.B[2] = nullptr;
        bt.C[0] = t1; bt.C[1] = t3; bt.C[2] = nullptr;
        bt.R[0] = bt.R[1] = bt.R[2] = nullptr;
        gemm_tc<false, true, false><<<dim3(HIDDEN / BN, SEQ / BM, 2), 256, GSMEM>>>(
            hn, bt, SEQ, HIDDEN, DIM, nullptr, nullptr);
    }

    silu_mul_k<<<(SEQ * HIDDEN / 4 + 255) / 256, 256>>>(t1, t3, SEQ * HIDDEN / 4);

    // W2 + residual -> out (float, in-place residual)
    {
        Batch3 bt;
        bt.B[0] = wt + W2O; bt.C[0] = out; bt.R[0] = out;
        bt.B[1] = bt.B[2] = nullptr; bt.C[1] = bt.C[2] = nullptr; bt.R[1] = bt.R[2] = nullptr;
        gemm_tc<true, false, false><<<dim3(DIM / BN, SEQ / BM, 1), 256, GSMEM>>>(
            t1, bt, SEQ, DIM, HIDDEN, nullptr, nullptr);
    }
}

// round 16
// speedup vs baseline: 1.8742x; 1.0556x over previous
#include <cuda_runtime.h>
#include <cuda_fp16.h>
#include <math.h>
#include <stdint.h>

#define SEQ    4096
#define DIM    1024
#define NH     16
#define HD     64
#define HIDDEN 4096

// ---------------- scratch (fp16 activations/weights) ---------------------------------
__device__ __half g_xn[SEQ * DIM];
__device__ __half g_q [SEQ * DIM];
__device__ __half g_k [SEQ * DIM];
__device__ __half g_v [SEQ * DIM];
__device__ __half g_at[SEQ * DIM];
__device__ __half g_hn[SEQ * DIM];
__device__ __half g_t1[SEQ * HIDDEN];
__device__ __half g_t3[SEQ * HIDDEN];
__device__ float  g_cos[SEQ * (HD / 2)];
__device__ float  g_sin[SEQ * (HD / 2)];
__device__ __half g_wt[16777216];          // fp16 weights (32MB)

#define WQO 0
#define WKO 1048576
#define WVO 2097152
#define WOO 3145728
#define W1O 4194304
#define W3O 8388608
#define W2O 12582912

__device__ __forceinline__ uint32_t h2pack(float a, float b) {
    __half2 h = __floats2half2_rn(a, b);
    return *reinterpret_cast<uint32_t*>(&h);
}

__device__ __forceinline__ void mma_f16(float* c, const uint32_t* a, uint32_t b0, uint32_t b1) {
    asm volatile(
        "mma.sync.aligned.m16n8k16.row.col.f32.f16.f16.f32 "
        "{%0,%1,%2,%3}, {%4,%5,%6,%7}, {%8,%9}, {%0,%1,%2,%3};\n"
        : "+f"(c[0]), "+f"(c[1]), "+f"(c[2]), "+f"(c[3])
        : "r"(a[0]), "r"(a[1]), "r"(a[2]), "r"(a[3]), "r"(b0), "r"(b1));
}

__device__ __forceinline__ void ldsm4(uint32_t* r, uint32_t saddr) {
    asm volatile("ldmatrix.sync.aligned.m8n8.x4.shared.b16 {%0,%1,%2,%3}, [%4];"
        : "=r"(r[0]), "=r"(r[1]), "=r"(r[2]), "=r"(r[3]) : "r"(saddr));
}

__device__ __forceinline__ void ldsm4t(uint32_t* r, uint32_t saddr) {
    asm volatile("ldmatrix.sync.aligned.m8n8.x4.trans.shared.b16 {%0,%1,%2,%3}, [%4];"
        : "=r"(r[0]), "=r"(r[1]), "=r"(r[2]), "=r"(r[3]) : "r"(saddr));
}

__device__ __forceinline__ void cp16(uint32_t saddr, const void* gptr) {
    asm volatile("cp.async.cg.shared.global [%0], [%1], 16;" :: "r"(saddr), "l"(gptr));
}

__device__ __forceinline__ uint32_t smem_u32(const void* p) {
    uint32_t a;
    asm("{ .reg .u64 t; cvta.to.shared.u64 t, %1; cvt.u32.u64 %0, t; }" : "=r"(a) : "l"(p));
    return a;
}

// ---------------- weight fp16 convert (single z-batched launch) ----------------------
struct CvtBatch {
    const float* src[7];
    int off[7];
    int n4[7];
};

__global__ void cvt_all_k(CvtBatch cb, __half* __restrict__ wt) {
    const float* src = cb.src[blockIdx.z];
    __half* dst = wt + cb.off[blockIdx.z];
    int n4 = cb.n4[blockIdx.z];
    int stride = gridDim.x * blockDim.x;
    for (int i = blockIdx.x * blockDim.x + threadIdx.x; i < n4; i += stride) {
        float4 v = ((const float4*)src)[i];
        uint2 o;
        o.x = h2pack(v.x, v.y);
        o.y = h2pack(v.z, v.w);
        ((uint2*)dst)[i] = o;
    }
}

// ---------------- RoPE tables in double precision ------------------------------------
__global__ void rope_tables_k(float* __restrict__ c, float* __restrict__ s) {
    int idx = blockIdx.x * blockDim.x + threadIdx.x;
    int pos = idx >> 5;
    int i   = idx & 31;
    double inv = exp(-((double)(2 * i) / (double)HD) * log(10000.0));
    double ang = (double)pos * inv;
    double cs, sn;
    sincos(ang, &sn, &cs);
    c[idx] = (float)cs;
    s[idx] = (float)sn;
}

// ---------------- RMSNorm: float in -> half out ---------------------------------------
__global__ void rmsnorm_k(const float* __restrict__ x, const float* __restrict__ g,
                          __half* __restrict__ o) {
    int row = blockIdx.x;
    const float4* xr = (const float4*)(x + (size_t)row * DIM);
    uint2* orow = (uint2*)(o + (size_t)row * DIM);
    int t = threadIdx.x;
    float4 v = xr[t];
    float ss = v.x * v.x + v.y * v.y + v.z * v.z + v.w * v.w;
    #pragma unroll
    for (int off = 16; off; off >>= 1) ss += __shfl_xor_sync(0xffffffffu, ss, off);
    __shared__ float sp[8];
    if ((t & 31) == 0) sp[t >> 5] = ss;
    __syncthreads();
    if (t < 8) {
        float s2 = sp[t];
        #pragma unroll
        for (int off = 4; off; off >>= 1) s2 += __shfl_xor_sync(0xffu, s2, off);
        if (t == 0) sp[0] = s2;
    }
    __syncthreads();
    float rs = rsqrtf(sp[0] * (1.0f / DIM) + 1e-6f);
    float4 gg = ((const float4*)g)[t];
    uint2 out;
    out.x = h2pack(v.x * rs * gg.x, v.y * rs * gg.y);
    out.y = h2pack(v.z * rs * gg.z, v.w * rs * gg.w);
    orow[t] = out;
}

// ---------------- fp16 GEMM: CTA 128x128, warp 64x32, BK=64 halves, 3 stages ---------
// Row stride 72 halves (144B): ldmatrix phases 0,16,..,112 -> conflict-free.
#define BM 128
#define BN 128
#define BKH 64
#define SSTH 72
#define STAGES 3
#define AWH  (BM * SSTH)
#define STGH (2 * AWH)
#define GSMEM (STAGES * STGH * 2)   // 110592 bytes

struct Batch3 {
    const __half* B[3];
    void*         C[3];
    const float*  R[3];
};

template <bool RESID, bool HOUT, bool ROPE>
__global__ __launch_bounds__(256, 2)
void gemm_tc(const __half* __restrict__ A, Batch3 bt, int M, int N, int K,
             const float* __restrict__ ct, const float* __restrict__ st) {
    extern __shared__ uint32_t smw[];
    const __half* __restrict__ Bp = bt.B[blockIdx.z];
    const float*  __restrict__ Rp = bt.R[blockIdx.z];

    const int bm = blockIdx.y * BM;
    const int bn = blockIdx.x * BN;
    const int tid  = threadIdx.x;
    const int warp = tid >> 5;
    const int lane = tid & 31;
    const int grp  = lane >> 2;
    const int tig  = lane & 3;
    const int wm = (warp >> 2) * 64;
    const int wn = (warp & 3) * 32;

    const int frow = lane & 15;
    const int fcol = (lane >> 4) * 8;

    float acc[4][4][4];
    #pragma unroll
    for (int i = 0; i < 4; i++)
        #pragma unroll
        for (int j = 0; j < 4; j++)
            #pragma unroll
            for (int r = 0; r < 4; r++) acc[i][j][r] = 0.0f;

    const int NT = K / BKH;
    const uint32_t smb = smem_u32(smw);

    auto issue = [&](int kt) {
        const int st = kt % STAGES;
        const uint32_t ab = smb + st * STGH * 2;
        const uint32_t bb = ab + AWH * 2;
        const __half* Ag = A  + (size_t)bm * K + kt * BKH;
        const __half* Bg = Bp + (size_t)bn * K + kt * BKH;
        #pragma unroll
        for (int i = 0; i < 4; i++) {
            int idx = tid + i * 256;          // 1024 chunks each tensor
            int row = idx >> 3;
            int c8  = (idx & 7) * 8;          // halves
            cp16(ab + (row * SSTH + c8) * 2, Ag + (size_t)row * K + c8);
            cp16(bb + (row * SSTH + c8) * 2, Bg + (size_t)row * K + c8);
        }
        asm volatile("cp.async.commit_group;");
    };

    issue(0);
    issue(1);

    for (int kt = 0; kt < NT; kt++) {
        if (kt + 1 < NT) {
            asm volatile("cp.async.wait_group 1;");
        } else {
            asm volatile("cp.async.wait_group 0;");
        }
        __syncthreads();
        if (kt + 2 < NT) issue(kt + 2);

        const int st = kt % STAGES;
        const uint32_t ab = smb + st * STGH * 2;
        const uint32_t bb = ab + AWH * 2;

        #pragma unroll
        for (int ks = 0; ks < 4; ks++) {
            const int kb = ks * 16;
            uint32_t af[4][4], bf[2][4];
            #pragma unroll
            for (int mt = 0; mt < 4; mt++)
                ldsm4(af[mt], ab + (((wm + mt * 16 + frow) * SSTH) + kb + fcol) * 2);
            #pragma unroll
            for (int bk = 0; bk < 2; bk++)
                ldsm4(bf[bk], bb + (((wn + bk * 16 + frow) * SSTH) + kb + fcol) * 2);
            #pragma unroll
            for (int mt = 0; mt < 4; mt++)
                #pragma unroll
                for (int nt = 0; nt < 4; nt++)
                    mma_f16(acc[mt][nt], af[mt],
                            bf[nt >> 1][nt & 1], bf[nt >> 1][(nt & 1) + 2]);
        }
    }

    const bool do_rope = ROPE && (blockIdx.z < 2);
    const float qscale = (ROPE && blockIdx.z == 0) ? 0.125f : 1.0f;

    #pragma unroll
    for (int mt = 0; mt < 4; mt++) {
        const int row = bm + wm + mt * 16 + grp;
        const int rb0 = row * 32;
        const int rb1 = (row + 8) * 32;
        #pragma unroll
        for (int nt = 0; nt < 4; nt++) {
            const int col = bn + wn + nt * 8 + 2 * tig;   // even
            size_t i0 = (size_t)row * N + col;
            size_t i1 = (size_t)(row + 8) * N + col;
            if (HOUT) {
                __half* Cp = (__half*)bt.C[blockIdx.z];
                float a0 = acc[mt][nt][0], a1 = acc[mt][nt][1];
                float a2 = acc[mt][nt][2], a3 = acc[mt][nt][3];
                if (do_rope) {
                    int ri = (col & 63) >> 1;
                    float c0 = ct[rb0 + ri], s0 = st[rb0 + ri];
                    float c1 = ct[rb1 + ri], s1 = st[rb1 + ri];
                    float r0 = a0 * c0 - a1 * s0, r1 = a0 * s0 + a1 * c0;
                    float r2 = a2 * c1 - a3 * s1, r3 = a2 * s1 + a3 * c1;
                    a0 = r0 * qscale; a1 = r1 * qscale;
                    a2 = r2 * qscale; a3 = r3 * qscale;
                }
                *(uint32_t*)&Cp[i0] = h2pack(a0, a1);
                *(uint32_t*)&Cp[i1] = h2pack(a2, a3);
            } else {
                float* Cp = (float*)bt.C[blockIdx.z];
                float2 v0 = make_float2(acc[mt][nt][0], acc[mt][nt][1]);
                float2 v1 = make_float2(acc[mt][nt][2], acc[mt][nt][3]);
                if (RESID) {
                    float2 r0v = *(const float2*)&Rp[i0];
                    float2 r1v = *(const float2*)&Rp[i1];
                    v0.x += r0v.x; v0.y += r0v.y;
                    v1.x += r1v.x; v1.y += r1v.y;
                }
                *(float2*)&Cp[i0] = v0;
                *(float2*)&Cp[i1] = v1;
            }
        }
    }
}

// ---------------- fp16 flash attention: BQ=256 (16 warps), stage BKV=128 -------------
// Q pre-scaled by 0.125 in QKV epilogue: no score scaling here (bit-exact fold).
#define BQ   256
#define BKV  128
#define KP2  72
#define KW2  (BKV * KP2)
#define AST2 (2 * KW2)
#define PSO2 (2 * AST2)
#define ASMEM ((PSO2 + BQ * KP2) * 2)   // 110592 bytes

__global__ __launch_bounds__(512, 1)
void flash_attn_tc(const __half* __restrict__ Q, const __half* __restrict__ K,
                   const __half* __restrict__ V, __half* __restrict__ O) {
    extern __shared__ uint32_t smw[];

    const int h  = blockIdx.y;
    const int q0 = blockIdx.x * BQ;
    const int tid  = threadIdx.x;
    const int warp = tid >> 5;
    const int lane = tid & 31;
    const int grp  = lane >> 2;
    const int tig  = lane & 3;
    const int wm   = warp * 16;

    const int frow = lane & 15;
    const int fcol = (lane >> 4) * 8;

    const uint32_t smb = smem_u32(smw);
    const uint32_t psb = smb + PSO2 * 2;

    uint32_t qf[4][4];
    {
        const __half* qb = Q + (size_t)(q0 + wm) * DIM + h * HD;
        #pragma unroll
        for (int ks = 0; ks < 4; ks++) {
            qf[ks][0] = *(const uint32_t*)&qb[(size_t)grp       * DIM + ks * 16 + 2 * tig];
            qf[ks][1] = *(const uint32_t*)&qb[(size_t)(grp + 8) * DIM + ks * 16 + 2 * tig];
            qf[ks][2] = *(const uint32_t*)&qb[(size_t)grp       * DIM + ks * 16 + 8 + 2 * tig];
            qf[ks][3] = *(const uint32_t*)&qb[(size_t)(grp + 8) * DIM + ks * 16 + 8 + 2 * tig];
        }
    }

    float o[8][4];
    #pragma unroll
    for (int dt = 0; dt < 8; dt++)
        #pragma unroll
        for (int r = 0; r < 4; r++) o[dt][r] = 0.0f;
    float m0 = -1e30f, m1 = -1e30f, l0 = 0.0f, l1 = 0.0f;

    const int NT = SEQ / BKV;
    const int lrow = tid >> 3;
    const int loff = (tid & 7) * 8;

    auto issue = [&](int t) {
        const uint32_t kb = smb + (t & 1) * AST2 * 2;
        const uint32_t vb = kb + KW2 * 2;
        const __half* Kg = K + (size_t)(t * BKV) * DIM + h * HD;
        const __half* Vg = V + (size_t)(t * BKV) * DIM + h * HD;
        #pragma unroll
        for (int i = 0; i < 2; i++) {
            int row = lrow + i * 64;
            cp16(kb + (row * KP2 + loff) * 2, Kg + (size_t)row * DIM + loff);
            cp16(vb + (row * KP2 + loff) * 2, Vg + (size_t)row * DIM + loff);
        }
        asm volatile("cp.async.commit_group;");
    };

    issue(0);

    for (int t = 0; t < NT; t++) {
        if (t + 1 < NT) {
            issue(t + 1);
            asm volatile("cp.async.wait_group 1;");
        } else {
            asm volatile("cp.async.wait_group 0;");
        }
        __syncthreads();

        #pragma unroll
        for (int half = 0; half < 2; half++) {
            const uint32_t ksb = smb + (t & 1) * AST2 * 2 + half * (64 * KP2) * 2;
            const uint32_t vsb = smb + ((t & 1) * AST2 + KW2 + half * (64 * KP2)) * 2;

            float sc[8][4];
            #pragma unroll
            for (int nt = 0; nt < 8; nt++)
                #pragma unroll
                for (int r = 0; r < 4; r++) sc[nt][r] = 0.0f;
            #pragma unroll
            for (int ks = 0; ks < 4; ks++) {
                const int kb = ks * 16;
                uint32_t kf[4][4];
                #pragma unroll
                for (int g = 0; g < 4; g++)
                    ldsm4(kf[g], ksb + (((g * 16 + frow) * KP2) + kb + fcol) * 2);
                #pragma unroll
                for (int nt = 0; nt < 8; nt++)
                    mma_f16(sc[nt], qf[ks],
                            kf[nt >> 1][nt & 1], kf[nt >> 1][(nt & 1) + 2]);
            }

            float mx0 = -1e30f, mx1 = -1e30f;
            #pragma unroll
            for (int nt = 0; nt < 8; nt++) {
                mx0 = fmaxf(mx0, fmaxf(sc[nt][0], sc[nt][1]));
                mx1 = fmaxf(mx1, fmaxf(sc[nt][2], sc[nt][3]));
            }
            mx0 = fmaxf(mx0, __shfl_xor_sync(0xffffffffu, mx0, 1));
            mx0 = fmaxf(mx0, __shfl_xor_sync(0xffffffffu, mx0, 2));
            mx1 = fmaxf(mx1, __shfl_xor_sync(0xffffffffu, mx1, 1));
            mx1 = fmaxf(mx1, __shfl_xor_sync(0xffffffffu, mx1, 2));

            float mn0 = fmaxf(m0, mx0);
            float mn1 = fmaxf(m1, mx1);
            float cr0 = __expf(m0 - mn0);
            float cr1 = __expf(m1 - mn1);
            m0 = mn0; m1 = mn1;

            float s0 = 0.0f, s1 = 0.0f;
            #pragma unroll
            for (int nt = 0; nt < 8; nt++) {
                sc[nt][0] = __expf(sc[nt][0] - mn0);
                sc[nt][1] = __expf(sc[nt][1] - mn0);
                sc[nt][2] = __expf(sc[nt][2] - mn1);
                sc[nt][3] = __expf(sc[nt][3] - mn1);
                s0 += sc[nt][0] + sc[nt][1];
                s1 += sc[nt][2] + sc[nt][3];
            }
            s0 += __shfl_xor_sync(0xffffffffu, s0, 1);
            s0 += __shfl_xor_sync(0xffffffffu, s0, 2);
            s1 += __shfl_xor_sync(0xffffffffu, s1, 1);
            s1 += __shfl_xor_sync(0xffffffffu, s1, 2);
            l0 = l0 * cr0 + s0;
            l1 = l1 * cr1 + s1;

            #pragma unroll
            for (int dt = 0; dt < 8; dt++) {
                o[dt][0] *= cr0; o[dt][1] *= cr0;
                o[dt][2] *= cr1; o[dt][3] *= cr1;
            }

            #pragma unroll
            for (int nt = 0; nt < 8; nt++) {
                *(uint32_t*)((char*)smw + (PSO2 + (wm + grp    ) * KP2 + nt * 8 + 2 * tig) * 2)
                    = h2pack(sc[nt][0], sc[nt][1]);
                *(uint32_t*)((char*)smw + (PSO2 + (wm + grp + 8) * KP2 + nt * 8 + 2 * tig) * 2)
                    = h2pack(sc[nt][2], sc[nt][3]);
            }
            __syncwarp();

            #pragma unroll
            for (int ks = 0; ks < 4; ks++) {
                const int kb = ks * 16;
                uint32_t pa[4], vf[4][4];
                ldsm4(pa, psb + (((wm + frow) * KP2) + kb + fcol) * 2);
                #pragma unroll
                for (int db = 0; db < 4; db++)
                    ldsm4t(vf[db], vsb + (((kb + frow) * KP2) + db * 16 + fcol) * 2);
                #pragma unroll
                for (int dt = 0; dt < 8; dt++)
                    mma_f16(o[dt], pa,
                            vf[dt >> 1][(dt & 1) * 2], vf[dt >> 1][(dt & 1) * 2 + 1]);
            }
            __syncwarp();
        }
        __syncthreads();
    }

    float il0 = 1.0f / l0;
    float il1 = 1.0f / l1;
    #pragma unroll
    for (int dt = 0; dt < 8; dt++) {
        size_t i0 = (size_t)(q0 + wm + grp    ) * DIM + h * HD + dt * 8 + 2 * tig;
        size_t i1 = (size_t)(q0 + wm + grp + 8) * DIM + h * HD + dt * 8 + 2 * tig;
        *(uint32_t*)&O[i0] = h2pack(o[dt][0] * il0, o[dt][1] * il0);
        *(uint32_t*)&O[i1] = h2pack(o[dt][2] * il1, o[dt][3] * il1);
    }
}

// ---------------- SwiGLU elementwise (half) -------------------------------------------
__global__ void silu_mul_k(__half* __restrict__ a, const __half* __restrict__ b, int n4) {
    int i = blockIdx.x * blockDim.x + threadIdx.x;
    if (i < n4) {
        uint2 ua = ((uint2*)a)[i];
        uint2 ub = ((const uint2*)b)[i];
        float2 x0 = __half22float2(*(__half2*)&ua.x);
        float2 x1 = __half22float2(*(__half2*)&ua.y);
        float2 y0 = __half22float2(*(__half2*)&ub.x);
        float2 y1 = __half22float2(*(__half2*)&ub.y);
        uint2 o;
        o.x = h2pack(x0.x / (1.0f + __expf(-x0.x)) * y0.x,
                     x0.y / (1.0f + __expf(-x0.y)) * y0.y);
        o.y = h2pack(x1.x / (1.0f + __expf(-x1.x)) * y1.x,
                     x1.y / (1.0f + __expf(-x1.y)) * y1.y);
        ((uint2*)a)[i] = o;
    }
}

// ---------------- launch --------------------------------------------------------------
extern "C" void kernel_launch(void* const* d_in, const int* in_sizes, int n_in,
                              void* d_out, int out_size) {
    const float* x  = (const float*)d_in[0];
    const float* wq = (const float*)d_in[1];
    const float* wk = (const float*)d_in[2];
    const float* wv = (const float*)d_in[3];
    const float* wo = (const float*)d_in[4];
    const float* w1 = (const float*)d_in[5];
    const float* w2 = (const float*)d_in[6];
    const float* w3 = (const float*)d_in[7];
    const float* ga = (const float*)d_in[8];
    const float* gf = (const float*)d_in[9];
    float* out = (float*)d_out;

    __half *xn, *q, *k, *v, *at, *hn, *t1, *t3, *wt;
    float *ct, *st;
    cudaGetSymbolAddress((void**)&xn, g_xn);
    cudaGetSymbolAddress((void**)&q,  g_q);
    cudaGetSymbolAddress((void**)&k,  g_k);
    cudaGetSymbolAddress((void**)&v,  g_v);
    cudaGetSymbolAddress((void**)&at, g_at);
    cudaGetSymbolAddress((void**)&hn, g_hn);
    cudaGetSymbolAddress((void**)&t1, g_t1);
    cudaGetSymbolAddress((void**)&t3, g_t3);
    cudaGetSymbolAddress((void**)&ct, g_cos);
    cudaGetSymbolAddress((void**)&st, g_sin);
    cudaGetSymbolAddress((void**)&wt, g_wt);

    cudaFuncSetAttribute((const void*)gemm_tc<false, true,  true>,  cudaFuncAttributeMaxDynamicSharedMemorySize, GSMEM);
    cudaFuncSetAttribute((const void*)gemm_tc<false, true,  false>, cudaFuncAttributeMaxDynamicSharedMemorySize, GSMEM);
    cudaFuncSetAttribute((const void*)gemm_tc<true,  false, false>, cudaFuncAttributeMaxDynamicSharedMemorySize, GSMEM);
    cudaFuncSetAttribute((const void*)flash_attn_tc, cudaFuncAttributeMaxDynamicSharedMemorySize, ASMEM);

    // all weights -> fp16 (one z-batched launch)
    {
        CvtBatch cb;
        cb.src[0] = wq; cb.off[0] = WQO; cb.n4[0] = DIM * DIM / 4;
        cb.src[1] = wk; cb.off[1] = WKO; cb.n4[1] = DIM * DIM / 4;
        cb.src[2] = wv; cb.off[2] = WVO; cb.n4[2] = DIM * DIM / 4;
        cb.src[3] = wo; cb.off[3] = WOO; cb.n4[3] = DIM * DIM / 4;
        cb.src[4] = w1; cb.off[4] = W1O; cb.n4[4] = HIDDEN * DIM / 4;
        cb.src[5] = w3; cb.off[5] = W3O; cb.n4[5] = HIDDEN * DIM / 4;
        cb.src[6] = w2; cb.off[6] = W2O; cb.n4[6] = DIM * HIDDEN / 4;
        cvt_all_k<<<dim3(256, 1, 7), 256>>>(cb, wt);
    }

    rope_tables_k<<<(SEQ * 32) / 256, 256>>>(ct, st);
    rmsnorm_k<<<SEQ, 256>>>(x, ga, xn);

    // QKV batched (z = 3): RoPE fused for q/k, 0.125 scale folded into q
    {
        Batch3 bt;
        bt.B[0] = wt + WQO; bt.B[1] = wt + WKO; bt.B[2] = wt + WVO;
        bt.C[0] = q; bt.C[1] = k; bt.C[2] = v;
        bt.R[0] = bt.R[1] = bt.R[2] = nullptr;
        gemm_tc<false, true, true><<<dim3(DIM / BN, SEQ / BM, 3), 256, GSMEM>>>(
            xn, bt, SEQ, DIM, DIM, ct, st);
    }

    flash_attn_tc<<<dim3(SEQ / BQ, NH), 512, ASMEM>>>(q, k, v, at);

    // Wo + residual -> out (float)
    {
        Batch3 bt;
        bt.B[0] = wt + WOO; bt.C[0] = out; bt.R[0] = x;
        bt.B[1] = bt.B[2] = nullptr; bt.C[1] = bt.C[2] = nullptr; bt.R[1] = bt.R[2] = nullptr;
        gemm_tc<true, false, false><<<dim3(DIM / BN, SEQ / BM, 1), 256, GSMEM>>>(
            at, bt, SEQ, DIM, DIM, nullptr, nullptr);
    }

    rmsnorm_k<<<SEQ, 256>>>(out, gf, hn);

    // w1 / w3 batched (z = 2), half out
    {
        Batch3 bt;
        bt.B[0] = wt + W1O; bt.B[1] = wt + W3O; bt.B[2] = nullptr;
        bt.C[0] = t1; bt.C[1] = t3; bt.C[2] = nullptr;
        bt.R[0] = bt.R[1] = bt.R[2] = nullptr;
        gemm_tc<false, true, false><<<dim3(HIDDEN / BN, SEQ / BM, 2), 256, GSMEM>>>(
            hn, bt, SEQ, HIDDEN, DIM, nullptr, nullptr);
    }

    silu_mul_k<<<(SEQ * HIDDEN / 4 + 255) / 256, 256>>>(t1, t3, SEQ * HIDDEN / 4);

    // W2 + residual -> out (float, in-place residual)
    {
        Batch3 bt;
        bt.B[0] = wt + W2O; bt.C[0] = out; bt.R[0] = out;
        bt.B[1] = bt.B[2] = nullptr; bt.C[1] = bt.C[2] = nullptr; bt.R[1] = bt.R[2] = nullptr;
        gemm_tc<true, false, false><<<dim3(DIM / BN, SEQ / BM, 1), 256, GSMEM>>>(
            t1, bt, SEQ, DIM, HIDDEN, nullptr, nullptr);
    }
}

// round 17
// speedup vs baseline: 1.9517x; 1.0414x over previous
#include <cuda_runtime.h>
#include <cuda_fp16.h>
#include <math.h>
#include <stdint.h>

#define SEQ    4096
#define DIM    1024
#define NH     16
#define HD     64
#define HIDDEN 4096

// ---------------- scratch (fp16 activations/weights) ---------------------------------
__device__ __half g_xn[SEQ * DIM];
__device__ __half g_q [SEQ * DIM];
__device__ __half g_k [SEQ * DIM];
__device__ __half g_v [SEQ * DIM];
__device__ __half g_at[SEQ * DIM];
__device__ __half g_hn[SEQ * DIM];
__device__ __half g_t1[SEQ * HIDDEN];
__device__ __half g_t3[SEQ * HIDDEN];
__device__ float  g_cos[SEQ * (HD / 2)];
__device__ float  g_sin[SEQ * (HD / 2)];
__device__ __half g_wt[16777216];          // fp16 weights (32MB)

#define WQO 0
#define WKO 1048576
#define WVO 2097152
#define WOO 3145728
#define W1O 4194304
#define W3O 8388608
#define W2O 12582912

__device__ __forceinline__ uint32_t h2pack(float a, float b) {
    __half2 h = __floats2half2_rn(a, b);
    return *reinterpret_cast<uint32_t*>(&h);
}

__device__ __forceinline__ uint32_t h2ex2(uint32_t x) {
    uint32_t r;
    asm("ex2.approx.f16x2 %0, %1;" : "=r"(r) : "r"(x));
    return r;
}

__device__ __forceinline__ void mma_f16(float* c, const uint32_t* a, uint32_t b0, uint32_t b1) {
    asm volatile(
        "mma.sync.aligned.m16n8k16.row.col.f32.f16.f16.f32 "
        "{%0,%1,%2,%3}, {%4,%5,%6,%7}, {%8,%9}, {%0,%1,%2,%3};\n"
        : "+f"(c[0]), "+f"(c[1]), "+f"(c[2]), "+f"(c[3])
        : "r"(a[0]), "r"(a[1]), "r"(a[2]), "r"(a[3]), "r"(b0), "r"(b1));
}

__device__ __forceinline__ void ldsm4(uint32_t* r, uint32_t saddr) {
    asm volatile("ldmatrix.sync.aligned.m8n8.x4.shared.b16 {%0,%1,%2,%3}, [%4];"
        : "=r"(r[0]), "=r"(r[1]), "=r"(r[2]), "=r"(r[3]) : "r"(saddr));
}

__device__ __forceinline__ void ldsm4t(uint32_t* r, uint32_t saddr) {
    asm volatile("ldmatrix.sync.aligned.m8n8.x4.trans.shared.b16 {%0,%1,%2,%3}, [%4];"
        : "=r"(r[0]), "=r"(r[1]), "=r"(r[2]), "=r"(r[3]) : "r"(saddr));
}

__device__ __forceinline__ void cp16(uint32_t saddr, const void* gptr) {
    asm volatile("cp.async.cg.shared.global [%0], [%1], 16;" :: "r"(saddr), "l"(gptr));
}

__device__ __forceinline__ uint32_t smem_u32(const void* p) {
    uint32_t a;
    asm("{ .reg .u64 t; cvta.to.shared.u64 t, %1; cvt.u32.u64 %0, t; }" : "=r"(a) : "l"(p));
    return a;
}

// ---------------- weight fp16 convert (single z-batched launch) ----------------------
struct CvtBatch {
    const float* src[7];
    int off[7];
    int n4[7];
};

__global__ void cvt_all_k(CvtBatch cb, __half* __restrict__ wt) {
    const float* src = cb.src[blockIdx.z];
    __half* dst = wt + cb.off[blockIdx.z];
    int n4 = cb.n4[blockIdx.z];
    int stride = gridDim.x * blockDim.x;
    for (int i = blockIdx.x * blockDim.x + threadIdx.x; i < n4; i += stride) {
        float4 v = ((const float4*)src)[i];
        uint2 o;
        o.x = h2pack(v.x, v.y);
        o.y = h2pack(v.z, v.w);
        ((uint2*)dst)[i] = o;
    }
}

// ---------------- RoPE tables in double precision ------------------------------------
__global__ void rope_tables_k(float* __restrict__ c, float* __restrict__ s) {
    int idx = blockIdx.x * blockDim.x + threadIdx.x;
    int pos = idx >> 5;
    int i   = idx & 31;
    double inv = exp(-((double)(2 * i) / (double)HD) * log(10000.0));
    double ang = (double)pos * inv;
    double cs, sn;
    sincos(ang, &sn, &cs);
    c[idx] = (float)cs;
    s[idx] = (float)sn;
}

// ---------------- RMSNorm: float in -> half out ---------------------------------------
__global__ void rmsnorm_k(const float* __restrict__ x, const float* __restrict__ g,
                          __half* __restrict__ o) {
    int row = blockIdx.x;
    const float4* xr = (const float4*)(x + (size_t)row * DIM);
    uint2* orow = (uint2*)(o + (size_t)row * DIM);
    int t = threadIdx.x;
    float4 v = xr[t];
    float ss = v.x * v.x + v.y * v.y + v.z * v.z + v.w * v.w;
    #pragma unroll
    for (int off = 16; off; off >>= 1) ss += __shfl_xor_sync(0xffffffffu, ss, off);
    __shared__ float sp[8];
    if ((t & 31) == 0) sp[t >> 5] = ss;
    __syncthreads();
    if (t < 8) {
        float s2 = sp[t];
        #pragma unroll
        for (int off = 4; off; off >>= 1) s2 += __shfl_xor_sync(0xffu, s2, off);
        if (t == 0) sp[0] = s2;
    }
    __syncthreads();
    float rs = rsqrtf(sp[0] * (1.0f / DIM) + 1e-6f);
    float4 gg = ((const float4*)g)[t];
    uint2 out;
    out.x = h2pack(v.x * rs * gg.x, v.y * rs * gg.y);
    out.y = h2pack(v.z * rs * gg.z, v.w * rs * gg.w);
    orow[t] = out;
}

// ---------------- fp16 GEMM: CTA 128x128, warp 64x32, BK=64 halves, 3 stages ---------
#define BM 128
#define BN 128
#define BKH 64
#define SSTH 72
#define STAGES 3
#define AWH  (BM * SSTH)
#define STGH (2 * AWH)
#define GSMEM (STAGES * STGH * 2)   // 110592 bytes

struct Batch3 {
    const __half* B[3];
    void*         C[3];
    const float*  R[3];
};

template <bool RESID, bool HOUT, bool ROPE>
__global__ __launch_bounds__(256, 2)
void gemm_tc(const __half* __restrict__ A, Batch3 bt, int M, int N, int K,
             const float* __restrict__ ct, const float* __restrict__ st) {
    extern __shared__ uint32_t smw[];
    const __half* __restrict__ Bp = bt.B[blockIdx.z];
    const float*  __restrict__ Rp = bt.R[blockIdx.z];

    const int bm = blockIdx.y * BM;
    const int bn = blockIdx.x * BN;
    const int tid  = threadIdx.x;
    const int warp = tid >> 5;
    const int lane = tid & 31;
    const int grp  = lane >> 2;
    const int tig  = lane & 3;
    const int wm = (warp >> 2) * 64;
    const int wn = (warp & 3) * 32;

    const int frow = lane & 15;
    const int fcol = (lane >> 4) * 8;

    float acc[4][4][4];
    #pragma unroll
    for (int i = 0; i < 4; i++)
        #pragma unroll
        for (int j = 0; j < 4; j++)
            #pragma unroll
            for (int r = 0; r < 4; r++) acc[i][j][r] = 0.0f;

    const int NT = K / BKH;
    const uint32_t smb = smem_u32(smw);

    auto issue = [&](int kt) {
        const int st = kt % STAGES;
        const uint32_t ab = smb + st * STGH * 2;
        const uint32_t bb = ab + AWH * 2;
        const __half* Ag = A  + (size_t)bm * K + kt * BKH;
        const __half* Bg = Bp + (size_t)bn * K + kt * BKH;
        #pragma unroll
        for (int i = 0; i < 4; i++) {
            int idx = tid + i * 256;
            int row = idx >> 3;
            int c8  = (idx & 7) * 8;
            cp16(ab + (row * SSTH + c8) * 2, Ag + (size_t)row * K + c8);
            cp16(bb + (row * SSTH + c8) * 2, Bg + (size_t)row * K + c8);
        }
        asm volatile("cp.async.commit_group;");
    };

    issue(0);
    issue(1);

    for (int kt = 0; kt < NT; kt++) {
        if (kt + 1 < NT) {
            asm volatile("cp.async.wait_group 1;");
        } else {
            asm volatile("cp.async.wait_group 0;");
        }
        __syncthreads();
        if (kt + 2 < NT) issue(kt + 2);

        const int st = kt % STAGES;
        const uint32_t ab = smb + st * STGH * 2;
        const uint32_t bb = ab + AWH * 2;

        #pragma unroll
        for (int ks = 0; ks < 4; ks++) {
            const int kb = ks * 16;
            uint32_t af[4][4], bf[2][4];
            #pragma unroll
            for (int mt = 0; mt < 4; mt++)
                ldsm4(af[mt], ab + (((wm + mt * 16 + frow) * SSTH) + kb + fcol) * 2);
            #pragma unroll
            for (int bk = 0; bk < 2; bk++)
                ldsm4(bf[bk], bb + (((wn + bk * 16 + frow) * SSTH) + kb + fcol) * 2);
            #pragma unroll
            for (int mt = 0; mt < 4; mt++)
                #pragma unroll
                for (int nt = 0; nt < 4; nt++)
                    mma_f16(acc[mt][nt], af[mt],
                            bf[nt >> 1][nt & 1], bf[nt >> 1][(nt & 1) + 2]);
        }
    }

    const bool do_rope = ROPE && (blockIdx.z < 2);
    const float qscale = (ROPE && blockIdx.z == 0) ? 0.125f : 1.0f;

    #pragma unroll
    for (int mt = 0; mt < 4; mt++) {
        const int row = bm + wm + mt * 16 + grp;
        const int rb0 = row * 32;
        const int rb1 = (row + 8) * 32;
        #pragma unroll
        for (int nt = 0; nt < 4; nt++) {
            const int col = bn + wn + nt * 8 + 2 * tig;   // even
            size_t i0 = (size_t)row * N + col;
            size_t i1 = (size_t)(row + 8) * N + col;
            if (HOUT) {
                __half* Cp = (__half*)bt.C[blockIdx.z];
                float a0 = acc[mt][nt][0], a1 = acc[mt][nt][1];
                float a2 = acc[mt][nt][2], a3 = acc[mt][nt][3];
                if (do_rope) {
                    int ri = (col & 63) >> 1;
                    float c0 = ct[rb0 + ri], s0 = st[rb0 + ri];
                    float c1 = ct[rb1 + ri], s1 = st[rb1 + ri];
                    float r0 = a0 * c0 - a1 * s0, r1 = a0 * s0 + a1 * c0;
                    float r2 = a2 * c1 - a3 * s1, r3 = a2 * s1 + a3 * c1;
                    a0 = r0 * qscale; a1 = r1 * qscale;
                    a2 = r2 * qscale; a3 = r3 * qscale;
                }
                *(uint32_t*)&Cp[i0] = h2pack(a0, a1);
                *(uint32_t*)&Cp[i1] = h2pack(a2, a3);
            } else {
                float* Cp = (float*)bt.C[blockIdx.z];
                float2 v0 = make_float2(acc[mt][nt][0], acc[mt][nt][1]);
                float2 v1 = make_float2(acc[mt][nt][2], acc[mt][nt][3]);
                if (RESID) {
                    float2 r0v = *(const float2*)&Rp[i0];
                    float2 r1v = *(const float2*)&Rp[i1];
                    v0.x += r0v.x; v0.y += r0v.y;
                    v1.x += r1v.x; v1.y += r1v.y;
                }
                *(float2*)&Cp[i0] = v0;
                *(float2*)&Cp[i1] = v1;
            }
        }
    }
}

// ---------------- fp16 flash attention: BQ=256, stage BKV=256 (4x64 halves) ----------
// Q pre-scaled by 0.125 in QKV epilogue. Softmax exp via ex2.approx.f16x2.
#define BQ   256
#define BKV  256
#define KP2  72
#define KW2  (BKV * KP2)
#define AST2 (2 * KW2)
#define PSO2 (2 * AST2)
#define ASMEM ((PSO2 + BQ * KP2) * 2)   // 184320 bytes

__global__ __launch_bounds__(512, 1)
void flash_attn_tc(const __half* __restrict__ Q, const __half* __restrict__ K,
                   const __half* __restrict__ V, __half* __restrict__ O) {
    extern __shared__ uint32_t smw[];

    const int h  = blockIdx.y;
    const int q0 = blockIdx.x * BQ;
    const int tid  = threadIdx.x;
    const int warp = tid >> 5;
    const int lane = tid & 31;
    const int grp  = lane >> 2;
    const int tig  = lane & 3;
    const int wm   = warp * 16;

    const int frow = lane & 15;
    const int fcol = (lane >> 4) * 8;

    const uint32_t smb = smem_u32(smw);
    const uint32_t psb = smb + PSO2 * 2;

    uint32_t qf[4][4];
    {
        const __half* qb = Q + (size_t)(q0 + wm) * DIM + h * HD;
        #pragma unroll
        for (int ks = 0; ks < 4; ks++) {
            qf[ks][0] = *(const uint32_t*)&qb[(size_t)grp       * DIM + ks * 16 + 2 * tig];
            qf[ks][1] = *(const uint32_t*)&qb[(size_t)(grp + 8) * DIM + ks * 16 + 2 * tig];
            qf[ks][2] = *(const uint32_t*)&qb[(size_t)grp       * DIM + ks * 16 + 8 + 2 * tig];
            qf[ks][3] = *(const uint32_t*)&qb[(size_t)(grp + 8) * DIM + ks * 16 + 8 + 2 * tig];
        }
    }

    float o[8][4];
    #pragma unroll
    for (int dt = 0; dt < 8; dt++)
        #pragma unroll
        for (int r = 0; r < 4; r++) o[dt][r] = 0.0f;
    float m0 = -1e30f, m1 = -1e30f, l0 = 0.0f, l1 = 0.0f;

    const int NT = SEQ / BKV;            // 16 stages of 256 rows
    const int lrow = tid >> 3;           // 0..63
    const int loff = (tid & 7) * 8;      // 0..56 halves
    const float L2E = 1.4426950408889634f;

    auto issue = [&](int t) {
        const uint32_t kb = smb + (t & 1) * AST2 * 2;
        const uint32_t vb = kb + KW2 * 2;
        const __half* Kg = K + (size_t)(t * BKV) * DIM + h * HD;
        const __half* Vg = V + (size_t)(t * BKV) * DIM + h * HD;
        #pragma unroll
        for (int i = 0; i < 4; i++) {
            int row = lrow + i * 64;
            cp16(kb + (row * KP2 + loff) * 2, Kg + (size_t)row * DIM + loff);
            cp16(vb + (row * KP2 + loff) * 2, Vg + (size_t)row * DIM + loff);
        }
        asm volatile("cp.async.commit_group;");
    };

    issue(0);

    for (int t = 0; t < NT; t++) {
        if (t + 1 < NT) {
            issue(t + 1);
            asm volatile("cp.async.wait_group 1;");
        } else {
            asm volatile("cp.async.wait_group 0;");
        }
        __syncthreads();

        #pragma unroll
        for (int half = 0; half < 4; half++) {
            const uint32_t ksb = smb + (t & 1) * AST2 * 2 + half * (64 * KP2) * 2;
            const uint32_t vsb = smb + ((t & 1) * AST2 + KW2 + half * (64 * KP2)) * 2;

            float sc[8][4];
            #pragma unroll
            for (int nt = 0; nt < 8; nt++)
                #pragma unroll
                for (int r = 0; r < 4; r++) sc[nt][r] = 0.0f;
            #pragma unroll
            for (int ks = 0; ks < 4; ks++) {
                const int kb = ks * 16;
                uint32_t kf[4][4];
                #pragma unroll
                for (int g = 0; g < 4; g++)
                    ldsm4(kf[g], ksb + (((g * 16 + frow) * KP2) + kb + fcol) * 2);
                #pragma unroll
                for (int nt = 0; nt < 8; nt++)
                    mma_f16(sc[nt], qf[ks],
                            kf[nt >> 1][nt & 1], kf[nt >> 1][(nt & 1) + 2]);
            }

            float mx0 = -1e30f, mx1 = -1e30f;
            #pragma unroll
            for (int nt = 0; nt < 8; nt++) {
                mx0 = fmaxf(mx0, fmaxf(sc[nt][0], sc[nt][1]));
                mx1 = fmaxf(mx1, fmaxf(sc[nt][2], sc[nt][3]));
            }
            mx0 = fmaxf(mx0, __shfl_xor_sync(0xffffffffu, mx0, 1));
            mx0 = fmaxf(mx0, __shfl_xor_sync(0xffffffffu, mx0, 2));
            mx1 = fmaxf(mx1, __shfl_xor_sync(0xffffffffu, mx1, 1));
            mx1 = fmaxf(mx1, __shfl_xor_sync(0xffffffffu, mx1, 2));

            float mn0 = fmaxf(m0, mx0);
            float mn1 = fmaxf(m1, mx1);
            float cr0 = __expf(m0 - mn0);
            float cr1 = __expf(m1 - mn1);
            m0 = mn0; m1 = mn1;

            // exp via ex2.approx.f16x2; results are the fp16 P fed to PV mma
            const float mnl0 = mn0 * L2E;
            const float mnl1 = mn1 * L2E;
            float s0 = 0.0f, s1 = 0.0f;
            #pragma unroll
            for (int nt = 0; nt < 8; nt++) {
                float e0 = fmaf(sc[nt][0], L2E, -mnl0);
                float e1 = fmaf(sc[nt][1], L2E, -mnl0);
                float e2 = fmaf(sc[nt][2], L2E, -mnl1);
                float e3 = fmaf(sc[nt][3], L2E, -mnl1);
                uint32_t p01 = h2ex2(h2pack(e0, e1));
                uint32_t p23 = h2ex2(h2pack(e2, e3));
                *(uint32_t*)((char*)smw + (PSO2 + (wm + grp    ) * KP2 + nt * 8 + 2 * tig) * 2) = p01;
                *(uint32_t*)((char*)smw + (PSO2 + (wm + grp + 8) * KP2 + nt * 8 + 2 * tig) * 2) = p23;
                float2 f01 = __half22float2(*(__half2*)&p01);
                float2 f23 = __half22float2(*(__half2*)&p23);
                s0 += f01.x + f01.y;
                s1 += f23.x + f23.y;
            }
            s0 += __shfl_xor_sync(0xffffffffu, s0, 1);
            s0 += __shfl_xor_sync(0xffffffffu, s0, 2);
            s1 += __shfl_xor_sync(0xffffffffu, s1, 1);
            s1 += __shfl_xor_sync(0xffffffffu, s1, 2);
            l0 = l0 * cr0 + s0;
            l1 = l1 * cr1 + s1;

            #pragma unroll
            for (int dt = 0; dt < 8; dt++) {
                o[dt][0] *= cr0; o[dt][1] *= cr0;
                o[dt][2] *= cr1; o[dt][3] *= cr1;
            }
            __syncwarp();

            #pragma unroll
            for (int ks = 0; ks < 4; ks++) {
                const int kb = ks * 16;
                uint32_t pa[4], vf[4][4];
                ldsm4(pa, psb + (((wm + frow) * KP2) + kb + fcol) * 2);
                #pragma unroll
                for (int db = 0; db < 4; db++)
                    ldsm4t(vf[db], vsb + (((kb + frow) * KP2) + db * 16 + fcol) * 2);
                #pragma unroll
                for (int dt = 0; dt < 8; dt++)
                    mma_f16(o[dt], pa,
                            vf[dt >> 1][(dt & 1) * 2], vf[dt >> 1][(dt & 1) * 2 + 1]);
            }
            __syncwarp();
        }
        __syncthreads();
    }

    float il0 = 1.0f / l0;
    float il1 = 1.0f / l1;
    #pragma unroll
    for (int dt = 0; dt < 8; dt++) {
        size_t i0 = (size_t)(q0 + wm + grp    ) * DIM + h * HD + dt * 8 + 2 * tig;
        size_t i1 = (size_t)(q0 + wm + grp + 8) * DIM + h * HD + dt * 8 + 2 * tig;
        *(uint32_t*)&O[i0] = h2pack(o[dt][0] * il0, o[dt][1] * il0);
        *(uint32_t*)&O[i1] = h2pack(o[dt][2] * il1, o[dt][3] * il1);
    }
}

// ---------------- SwiGLU elementwise (half) -------------------------------------------
__global__ void silu_mul_k(__half* __restrict__ a, const __half* __restrict__ b, int n4) {
    int i = blockIdx.x * blockDim.x + threadIdx.x;
    if (i < n4) {
        uint2 ua = ((uint2*)a)[i];
        uint2 ub = ((const uint2*)b)[i];
        float2 x0 = __half22float2(*(__half2*)&ua.x);
        float2 x1 = __half22float2(*(__half2*)&ua.y);
        float2 y0 = __half22float2(*(__half2*)&ub.x);
        float2 y1 = __half22float2(*(__half2*)&ub.y);
        uint2 o;
        o.x = h2pack(x0.x / (1.0f + __expf(-x0.x)) * y0.x,
                     x0.y / (1.0f + __expf(-x0.y)) * y0.y);
        o.y = h2pack(x1.x / (1.0f + __expf(-x1.x)) * y1.x,
                     x1.y / (1.0f + __expf(-x1.y)) * y1.y);
        ((uint2*)a)[i] = o;
    }
}

// ---------------- launch --------------------------------------------------------------
extern "C" void kernel_launch(void* const* d_in, const int* in_sizes, int n_in,
                              void* d_out, int out_size) {
    const float* x  = (const float*)d_in[0];
    const float* wq = (const float*)d_in[1];
    const float* wk = (const float*)d_in[2];
    const float* wv = (const float*)d_in[3];
    const float* wo = (const float*)d_in[4];
    const float* w1 = (const float*)d_in[5];
    const float* w2 = (const float*)d_in[6];
    const float* w3 = (const float*)d_in[7];
    const float* ga = (const float*)d_in[8];
    const float* gf = (const float*)d_in[9];
    float* out = (float*)d_out;

    __half *xn, *q, *k, *v, *at, *hn, *t1, *t3, *wt;
    float *ct, *st;
    cudaGetSymbolAddress((void**)&xn, g_xn);
    cudaGetSymbolAddress((void**)&q,  g_q);
    cudaGetSymbolAddress((void**)&k,  g_k);
    cudaGetSymbolAddress((void**)&v,  g_v);
    cudaGetSymbolAddress((void**)&at, g_at);
    cudaGetSymbolAddress((void**)&hn, g_hn);
    cudaGetSymbolAddress((void**)&t1, g_t1);
    cudaGetSymbolAddress((void**)&t3, g_t3);
    cudaGetSymbolAddress((void**)&ct, g_cos);
    cudaGetSymbolAddress((void**)&st, g_sin);
    cudaGetSymbolAddress((void**)&wt, g_wt);

    cudaFuncSetAttribute((const void*)gemm_tc<false, true,  true>,  cudaFuncAttributeMaxDynamicSharedMemorySize, GSMEM);
    cudaFuncSetAttribute((const void*)gemm_tc<false, true,  false>, cudaFuncAttributeMaxDynamicSharedMemorySize, GSMEM);
    cudaFuncSetAttribute((const void*)gemm_tc<true,  false, false>, cudaFuncAttributeMaxDynamicSharedMemorySize, GSMEM);
    cudaFuncSetAttribute((const void*)flash_attn_tc, cudaFuncAttributeMaxDynamicSharedMemorySize, ASMEM);

    // all weights -> fp16 (one z-batched launch)
    {
        CvtBatch cb;
        cb.src[0] = wq; cb.off[0] = WQO; cb.n4[0] = DIM * DIM / 4;
        cb.src[1] = wk; cb.off[1] = WKO; cb.n4[1] = DIM * DIM / 4;
        cb.src[2] = wv; cb.off[2] = WVO; cb.n4[2] = DIM * DIM / 4;
        cb.src[3] = wo; cb.off[3] = WOO; cb.n4[3] = DIM * DIM / 4;
        cb.src[4] = w1; cb.off[4] = W1O; cb.n4[4] = HIDDEN * DIM / 4;
        cb.src[5] = w3; cb.off[5] = W3O; cb.n4[5] = HIDDEN * DIM / 4;
        cb.src[6] = w2; cb.off[6] = W2O; cb.n4[6] = DIM * HIDDEN / 4;
        cvt_all_k<<<dim3(256, 1, 7), 256>>>(cb, wt);
    }

    rope_tables_k<<<(SEQ * 32) / 256, 256>>>(ct, st);
    rmsnorm_k<<<SEQ, 256>>>(x, ga, xn);

    // QKV batched (z = 3): RoPE fused for q/k, 0.125 scale folded into q
    {
        Batch3 bt;
        bt.B[0] = wt + WQO; bt.B[1] = wt + WKO; bt.B[2] = wt + WVO;
        bt.C[0] = q; bt.C[1] = k; bt.C[2] = v;
        bt.R[0] = bt.R[1] = bt.R[2] = nullptr;
        gemm_tc<false, true, true><<<dim3(DIM / BN, SEQ / BM, 3), 256, GSMEM>>>(
            xn, bt, SEQ, DIM, DIM, ct, st);
    }

    flash_attn_tc<<<dim3(SEQ / BQ, NH), 512, ASMEM>>>(q, k, v, at);

    // Wo + residual -> out (float)
    {
        Batch3 bt;
        bt.B[0] = wt + WOO; bt.C[0] = out; bt.R[0] = x;
        bt.B[1] = bt.B[2] = nullptr; bt.C[1] = bt.C[2] = nullptr; bt.R[1] = bt.R[2] = nullptr;
        gemm_tc<true, false, false><<<dim3(DIM / BN, SEQ / BM, 1), 256, GSMEM>>>(
            at, bt, SEQ, DIM, DIM, nullptr, nullptr);
    }

    rmsnorm_k<<<SEQ, 256>>>(out, gf, hn);

    // w1 / w3 batched (z = 2), half out
    {
        Batch3 bt;
        bt.B[0] = wt + W1O; bt.B[1] = wt + W3O; bt.B[2] = nullptr;
        bt.C[0] = t1; bt.C[1] = t3; bt.C[2] = nullptr;
        bt.R[0] = bt.R[1] = bt.R[2] = nullptr;
        gemm_tc<false, true, false><<<dim3(HIDDEN / BN, SEQ / BM, 2), 256, GSMEM>>>(
            hn, bt, SEQ, HIDDEN, DIM, nullptr, nullptr);
    }

    silu_mul_k<<<(SEQ * HIDDEN / 4 + 255) / 256, 256>>>(t1, t3, SEQ * HIDDEN / 4);

    // W2 + residual -> out (float, in-place residual)
    {
        Batch3 bt;
        bt.B[0] = wt + W2O; bt.C[0] = out; bt.R[0] = out;
        bt.B[1] = bt.B[2] = nullptr; bt.C[1] = bt.C[2] = nullptr; bt.R[1] = bt.R[2] = nullptr;
        gemm_tc<true, false, false><<<dim3(DIM / BN, SEQ / BM, 1), 256, GSMEM>>>(
            t1, bt, SEQ, DIM, HIDDEN, nullptr, nullptr);
    }
}